// round 1
// baseline (speedup 1.0000x reference)
#include <cuda_runtime.h>
#include <math.h>
#include <float.h>

// Problem constants
#define HIDDEN   2048
#define NH       32
#define NKV      4
#define HD       128
#define BB       2
#define SS       2048
#define BTOK     (BB * SS)          // 4096 tokens
#define QKV_DIM  ((NH + 2 * NKV) * HD)  // 5120
#define ATTN_DIM (NH * HD)              // 4096
#define Q_OFF    0
#define K_OFF    (NH * HD)              // 4096
#define V_OFF    (NH * HD + NKV * HD)   // 4608

// Scratch (no runtime allocation allowed)
__device__ float g_qkv[(size_t)BTOK * QKV_DIM];   // ~84 MB
__device__ float g_attn[(size_t)BTOK * ATTN_DIM]; // ~67 MB

// ============================================================
// SGEMM (NT): C[M,N] = A[M,K] * B[N,K]^T, all row-major, K-contig
// 128x128 block tile, BK=8, 8x8 per thread, 256 threads
// ============================================================
__global__ __launch_bounds__(256) void sgemm_nt(
    const float* __restrict__ A, const float* __restrict__ B,
    float* __restrict__ C, int M, int N, int K)
{
    constexpr int BM = 128, BN = 128, BK = 8, TM = 8, TN = 8;
    __shared__ float As[BK][BM];
    __shared__ float Bs[BK][BN];

    int tid = threadIdx.x;
    int bm = blockIdx.y * BM;
    int bn = blockIdx.x * BN;

    int lrow = tid >> 1;            // 0..127
    int lcol = (tid & 1) << 2;      // 0 or 4
    int tx = tid & 15;              // 0..15
    int ty = tid >> 4;              // 0..15

    const float* Ab = A + (size_t)(bm + lrow) * K + lcol;
    const float* Bb = B + (size_t)(bn + lrow) * K + lcol;

    float acc[TM][TN];
#pragma unroll
    for (int i = 0; i < TM; i++)
#pragma unroll
        for (int j = 0; j < TN; j++) acc[i][j] = 0.f;

    for (int k0 = 0; k0 < K; k0 += BK) {
        float4 a4 = *(const float4*)(Ab + k0);
        float4 b4 = *(const float4*)(Bb + k0);
        As[lcol + 0][lrow] = a4.x;
        As[lcol + 1][lrow] = a4.y;
        As[lcol + 2][lrow] = a4.z;
        As[lcol + 3][lrow] = a4.w;
        Bs[lcol + 0][lrow] = b4.x;
        Bs[lcol + 1][lrow] = b4.y;
        Bs[lcol + 2][lrow] = b4.z;
        Bs[lcol + 3][lrow] = b4.w;
        __syncthreads();

#pragma unroll
        for (int k = 0; k < BK; k++) {
            float ra[TM], rb[TN];
#pragma unroll
            for (int i = 0; i < TM; i += 4) {
                float4 v = *(const float4*)(&As[k][ty * TM + i]);
                ra[i] = v.x; ra[i + 1] = v.y; ra[i + 2] = v.z; ra[i + 3] = v.w;
            }
#pragma unroll
            for (int j = 0; j < TN; j += 4) {
                float4 v = *(const float4*)(&Bs[k][tx * TN + j]);
                rb[j] = v.x; rb[j + 1] = v.y; rb[j + 2] = v.z; rb[j + 3] = v.w;
            }
#pragma unroll
            for (int i = 0; i < TM; i++)
#pragma unroll
                for (int j = 0; j < TN; j++)
                    acc[i][j] += ra[i] * rb[j];
        }
        __syncthreads();
    }

#pragma unroll
    for (int i = 0; i < TM; i++) {
        float* Crow = C + (size_t)(bm + ty * TM + i) * N + bn + tx * TN;
#pragma unroll
        for (int j = 0; j < TN; j += 4) {
            float4 v = make_float4(acc[i][j], acc[i][j + 1], acc[i][j + 2], acc[i][j + 3]);
            *(float4*)(Crow + j) = v;
        }
    }
}

// ============================================================
// Fused RMSNorm + RoPE (in place on q and k heads of g_qkv)
// one warp per (token, head) vector of 128
// ============================================================
__global__ __launch_bounds__(256) void norm_rope(
    const int* __restrict__ positions,
    const float* __restrict__ qw, const float* __restrict__ kw)
{
    const int NHEADS = NH + NKV;  // 36
    int warp = (blockIdx.x * blockDim.x + threadIdx.x) >> 5;
    int lane = threadIdx.x & 31;
    int total = BTOK * NHEADS;
    if (warp >= total) return;

    int g = warp % NHEADS;
    int tok = warp / NHEADS;
    const float* w = (g < NH) ? qw : kw;
    int off = (g < NH) ? g * HD : K_OFF + (g - NH) * HD;
    float* x = g_qkv + (size_t)tok * QKV_DIM + off;

    float xa = x[lane], xb = x[lane + 32], xc = x[lane + 64], xd = x[lane + 96];
    float ss = xa * xa + xb * xb + xc * xc + xd * xd;
#pragma unroll
    for (int o = 16; o; o >>= 1) ss += __shfl_xor_sync(0xffffffffu, ss, o);
    float r = rsqrtf(ss * (1.f / 128.f) + 1e-6f);
    xa *= r * w[lane];
    xb *= r * w[lane + 32];
    xc *= r * w[lane + 64];
    xd *= r * w[lane + 96];

    float pos = (float)positions[tok];
    // half = 64; freq index i: inv_freq = theta^(-i/64)
    float inv1 = powf(1.0e6f, -(float)lane * (1.f / 64.f));
    float inv2 = powf(1.0e6f, -(float)(lane + 32) * (1.f / 64.f));
    float s1, c1, s2, c2;
    sincosf(pos * inv1, &s1, &c1);
    sincosf(pos * inv2, &s2, &c2);

    x[lane]      = xa * c1 - xc * s1;
    x[lane + 64] = xc * c1 + xa * s1;
    x[lane + 32] = xb * c2 - xd * s2;
    x[lane + 96] = xd * c2 + xb * s2;
}

// ============================================================
// Causal flash attention (fp32)
// grid: (S/64, NH, B), 256 threads
// thread: cg = tid&15 (4 cols), rg = tid>>4 (4 rows); 4x4 scores, 4x8 output
// ============================================================
#define AT_BM 64
#define AT_BN 64
#define KP 129          // padded K/V smem row stride
#define PP 65           // padded P smem row stride
#define ATTN_SMEM_FLOATS (AT_BM * HD + 2 * AT_BN * KP + AT_BM * PP)
#define ATTN_SMEM_BYTES (ATTN_SMEM_FLOATS * 4)

__global__ __launch_bounds__(256, 1) void attn_kernel()
{
    extern __shared__ float sm[];
    float* Qs = sm;                         // 64 x 128
    float* Ks = Qs + AT_BM * HD;            // 64 x 129
    float* Vs = Ks + AT_BN * KP;            // 64 x 129
    float* Ps = Vs + AT_BN * KP;            // 64 x 65

    int tile = blockIdx.x;
    int h = blockIdx.y;
    int b = blockIdx.z;
    int kvh = h >> 3;               // 32/4 = 8 q heads per kv head
    int tid = threadIdx.x;
    int cg = tid & 15;
    int rg = tid >> 4;

    const float scale = 0.08838834764831843f;  // 1/sqrt(128)
    int q0 = tile * AT_BM;

    // load scaled Q tile
    for (int idx = tid; idx < AT_BM * HD; idx += 256) {
        int row = idx >> 7, d = idx & 127;
        Qs[row * HD + d] =
            g_qkv[(size_t)(b * SS + q0 + row) * QKV_DIM + h * HD + d] * scale;
    }
    __syncthreads();

    float m[4], l[4], acc[4][8];
#pragma unroll
    for (int i = 0; i < 4; i++) {
        m[i] = -1e30f; l[i] = 0.f;
#pragma unroll
        for (int d = 0; d < 8; d++) acc[i][d] = 0.f;
    }

    int ntiles = tile + 1;
    for (int t = 0; t < ntiles; ++t) {
        // load K and V tiles
        for (int idx = tid; idx < AT_BN * HD; idx += 256) {
            int row = idx >> 7, d = idx & 127;
            size_t tokoff = (size_t)(b * SS + t * AT_BN + row) * QKV_DIM;
            Ks[row * KP + d] = g_qkv[tokoff + K_OFF + kvh * HD + d];
            Vs[row * KP + d] = g_qkv[tokoff + V_OFF + kvh * HD + d];
        }
        __syncthreads();

        // scores: 4 rows x 4 cols per thread
        float s[4][4];
#pragma unroll
        for (int i = 0; i < 4; i++)
#pragma unroll
            for (int j = 0; j < 4; j++) s[i][j] = 0.f;

        const float* qbase = Qs + (rg * 4) * HD;
        const float* kbase = Ks + (cg * 4) * KP;
#pragma unroll 4
        for (int d = 0; d < HD; ++d) {
            float qf[4], kf[4];
#pragma unroll
            for (int i = 0; i < 4; i++) qf[i] = qbase[i * HD + d];
#pragma unroll
            for (int j = 0; j < 4; j++) kf[j] = kbase[j * KP + d];
#pragma unroll
            for (int i = 0; i < 4; i++)
#pragma unroll
                for (int j = 0; j < 4; j++)
                    s[i][j] += qf[i] * kf[j];
        }

        // causal mask (only diagonal tile can violate)
        if (t == tile) {
#pragma unroll
            for (int i = 0; i < 4; i++) {
                int qi = q0 + rg * 4 + i;
#pragma unroll
                for (int j = 0; j < 4; j++) {
                    int kj = t * AT_BN + cg * 4 + j;
                    if (kj > qi) s[i][j] = -1e30f;
                }
            }
        }

        // online softmax per row (reduce across 16 lanes holding this row)
#pragma unroll
        for (int i = 0; i < 4; i++) {
            float mt = fmaxf(fmaxf(s[i][0], s[i][1]), fmaxf(s[i][2], s[i][3]));
            mt = fmaxf(mt, __shfl_xor_sync(0xffffffffu, mt, 1));
            mt = fmaxf(mt, __shfl_xor_sync(0xffffffffu, mt, 2));
            mt = fmaxf(mt, __shfl_xor_sync(0xffffffffu, mt, 4));
            mt = fmaxf(mt, __shfl_xor_sync(0xffffffffu, mt, 8));
            float mnew = fmaxf(m[i], mt);
            float corr = __expf(m[i] - mnew);
            float ps = 0.f;
#pragma unroll
            for (int j = 0; j < 4; j++) {
                float p = __expf(s[i][j] - mnew);
                s[i][j] = p;
                ps += p;
            }
            ps += __shfl_xor_sync(0xffffffffu, ps, 1);
            ps += __shfl_xor_sync(0xffffffffu, ps, 2);
            ps += __shfl_xor_sync(0xffffffffu, ps, 4);
            ps += __shfl_xor_sync(0xffffffffu, ps, 8);
            l[i] = l[i] * corr + ps;
            m[i] = mnew;
#pragma unroll
            for (int d = 0; d < 8; d++) acc[i][d] *= corr;
            // publish probs
#pragma unroll
            for (int j = 0; j < 4; j++)
                Ps[(rg * 4 + i) * PP + cg * 4 + j] = s[i][j];
        }
        __syncwarp();

        // PV: acc[i][dd] += sum_j P[row_i][j] * V[j][cg + 16*dd]
#pragma unroll 2
        for (int j = 0; j < AT_BN; ++j) {
            float pv[4];
#pragma unroll
            for (int i = 0; i < 4; i++) pv[i] = Ps[(rg * 4 + i) * PP + j];
            float vf[8];
            const float* vrow = Vs + j * KP + cg;
#pragma unroll
            for (int d = 0; d < 8; d++) vf[d] = vrow[d * 16];
#pragma unroll
            for (int i = 0; i < 4; i++)
#pragma unroll
                for (int d = 0; d < 8; d++)
                    acc[i][d] += pv[i] * vf[d];
        }
        __syncthreads();
    }

    // epilogue
#pragma unroll
    for (int i = 0; i < 4; i++) {
        float inv = 1.f / l[i];
        size_t row = (size_t)(b * SS + q0 + rg * 4 + i) * ATTN_DIM + h * HD;
#pragma unroll
        for (int d = 0; d < 8; d++)
            g_attn[row + cg + 16 * d] = acc[i][d] * inv;
    }
}

// ============================================================
// launch
// ============================================================
extern "C" void kernel_launch(void* const* d_in, const int* in_sizes, int n_in,
                              void* d_out, int out_size)
{
    const float* hidden    = (const float*)d_in[0];
    const int*   positions = (const int*)d_in[1];
    const float* w_qkv     = (const float*)d_in[2];
    const float* w_o       = (const float*)d_in[3];
    const float* q_norm_w  = (const float*)d_in[4];
    const float* k_norm_w  = (const float*)d_in[5];
    float* out = (float*)d_out;

    float* qkv_buf = nullptr;
    float* attn_buf = nullptr;
    cudaGetSymbolAddress((void**)&qkv_buf, g_qkv);
    cudaGetSymbolAddress((void**)&attn_buf, g_attn);

    cudaFuncSetAttribute(attn_kernel,
                         cudaFuncAttributeMaxDynamicSharedMemorySize,
                         ATTN_SMEM_BYTES);

    // 1) QKV projection: [4096,2048] x [5120,2048]^T -> [4096,5120]
    sgemm_nt<<<dim3(QKV_DIM / 128, BTOK / 128), 256>>>(
        hidden, w_qkv, qkv_buf, BTOK, QKV_DIM, HIDDEN);

    // 2) RMSNorm + RoPE on q and k heads (in place)
    {
        int total_warps = BTOK * (NH + NKV);       // 147456
        int blocks = (total_warps + 7) / 8;        // 8 warps per block
        norm_rope<<<blocks, 256>>>(positions, q_norm_w, k_norm_w);
    }

    // 3) causal GQA flash attention -> g_attn [4096, 4096]
    attn_kernel<<<dim3(SS / AT_BM, NH, BB), 256, ATTN_SMEM_BYTES>>>();

    // 4) O projection: [4096,4096] x [2048,4096]^T -> [4096,2048]
    sgemm_nt<<<dim3(HIDDEN / 128, BTOK / 128), 256>>>(
        attn_buf, w_o, out, BTOK, HIDDEN, ATTN_DIM);
}

// round 3
// speedup vs baseline: 1.8060x; 1.8060x over previous
#include <cuda_runtime.h>
#include <cstdint>
#include <math.h>
#include <float.h>

// Problem constants
#define HIDDEN   2048
#define NH       32
#define NKV      4
#define HD       128
#define BB       2
#define SS       2048
#define BTOK     (BB * SS)              // 4096 tokens
#define QKV_DIM  ((NH + 2 * NKV) * HD)  // 5120
#define ATTN_DIM (NH * HD)              // 4096
#define K_OFF    (NH * HD)              // 4096
#define V_OFF    (NH * HD + NKV * HD)   // 4608

// Scratch (no runtime allocation allowed)
__device__ float g_qkv[(size_t)BTOK * QKV_DIM];   // ~84 MB
__device__ float g_attn[(size_t)BTOK * ATTN_DIM]; // ~67 MB

// ============================================================
// helpers
// ============================================================
__device__ __forceinline__ uint32_t smem_u32(const void* p) {
    uint32_t a;
    asm("{ .reg .u64 t; cvta.to.shared.u64 t, %1; cvt.u32.u64 %0, t; }" : "=r"(a) : "l"(p));
    return a;
}
// split (x,y) into packed bf16x2 high + low parts (lo = x, hi = y)
__device__ __forceinline__ void split2(float x, float y, uint32_t& h, uint32_t& l) {
    asm("cvt.rn.bf16x2.f32 %0, %1, %2;" : "=r"(h) : "f"(y), "f"(x));
    float hx = __uint_as_float(h << 16);
    float hy = __uint_as_float(h & 0xffff0000u);
    float rx = x - hx, ry = y - hy;
    asm("cvt.rn.bf16x2.f32 %0, %1, %2;" : "=r"(l) : "f"(ry), "f"(rx));
}
__device__ __forceinline__ void ldm4(uint32_t addr, uint32_t& r0, uint32_t& r1,
                                     uint32_t& r2, uint32_t& r3) {
    asm volatile("ldmatrix.sync.aligned.m8n8.x4.shared.b16 {%0,%1,%2,%3}, [%4];"
                 : "=r"(r0), "=r"(r1), "=r"(r2), "=r"(r3) : "r"(addr));
}
__device__ __forceinline__ void mma_bf16(float* c, const uint32_t* a, const uint32_t* b) {
    asm volatile(
        "mma.sync.aligned.m16n8k16.row.col.f32.bf16.bf16.f32 "
        "{%0,%1,%2,%3}, {%4,%5,%6,%7}, {%8,%9}, {%0,%1,%2,%3};"
        : "+f"(c[0]), "+f"(c[1]), "+f"(c[2]), "+f"(c[3])
        : "r"(a[0]), "r"(a[1]), "r"(a[2]), "r"(a[3]), "r"(b[0]), "r"(b[1]));
}

// ============================================================
// bf16-split tensor-core GEMM (NT): C[M,N] = A[M,K] * B[N,K]^T
// 128x128x32 block tile, 8 warps (2x4), warp tile 64x32
// 3 passes (AhBh + AhBl + AlBh) for fp32-class accuracy
// ============================================================
#define GBM 128
#define GBN 128
#define GBK 32
#define SROW 80                       // smem row stride in bytes (32 bf16 + 8 pad)
#define TILE_B (128 * SROW)           // 10240 B, one 128x32 bf16 tile
#define STAGE_B (4 * TILE_B)          // Ah, Al, Bh, Bl
#define GEMM_SMEM (2 * STAGE_B)       // 81920 B

__global__ __launch_bounds__(256, 1) void gemm_bf16split(
    const float* __restrict__ A, const float* __restrict__ B,
    float* __restrict__ C, int M, int N, int K)
{
    extern __shared__ char smc[];
    uint32_t smb = smem_u32(smc);
    int tid = threadIdx.x;
    int lane = tid & 31;
    int wid = tid >> 5;
    int warpM = wid >> 2;             // 0..1 -> 64 rows
    int warpN = wid & 3;              // 0..3 -> 32 cols
    int bm = blockIdx.y * GBM;
    int bn = blockIdx.x * GBN;

    // ldmatrix lane-address offsets (bytes), row stride SROW
    int g = lane >> 3, r = lane & 7;
    uint32_t a_off = (uint32_t)(((g & 1) * 8 + r) * SROW + (g >> 1) * 16);
    uint32_t b_off = (uint32_t)(((g >> 1) * 8 + r) * SROW + (g & 1) * 16);

    // gmem loader coords: 4 iterations cover 128 rows x 8 float4
    int lrow[4], lc4[4];
#pragma unroll
    for (int i = 0; i < 4; i++) {
        int idx = tid + i * 256;
        lrow[i] = idx >> 3;
        lc4[i] = idx & 7;
    }

    const float* Ag = A + (size_t)bm * K;
    const float* Bg = B + (size_t)bn * K;

    float c[4][4][4];
#pragma unroll
    for (int mt = 0; mt < 4; mt++)
#pragma unroll
        for (int nt = 0; nt < 4; nt++)
#pragma unroll
            for (int e = 0; e < 4; e++) c[mt][nt][e] = 0.f;

    float4 pa[4], pb[4];

    auto prefetch = [&](int kb) {
        int k0 = kb * GBK;
#pragma unroll
        for (int i = 0; i < 4; i++) {
            pa[i] = *(const float4*)(Ag + (size_t)lrow[i] * K + k0 + lc4[i] * 4);
            pb[i] = *(const float4*)(Bg + (size_t)lrow[i] * K + k0 + lc4[i] * 4);
        }
    };
    auto store_stage = [&](int buf) {
        char* st = smc + buf * STAGE_B;
#pragma unroll
        for (int i = 0; i < 4; i++) {
            uint32_t off = (uint32_t)(lrow[i] * SROW + lc4[i] * 8);
            uint32_t h0, l0, h1, l1;
            split2(pa[i].x, pa[i].y, h0, l0);
            split2(pa[i].z, pa[i].w, h1, l1);
            *(uint2*)(st + off) = make_uint2(h0, h1);
            *(uint2*)(st + TILE_B + off) = make_uint2(l0, l1);
            split2(pb[i].x, pb[i].y, h0, l0);
            split2(pb[i].z, pb[i].w, h1, l1);
            *(uint2*)(st + 2 * TILE_B + off) = make_uint2(h0, h1);
            *(uint2*)(st + 3 * TILE_B + off) = make_uint2(l0, l1);
        }
    };

    prefetch(0);
    store_stage(0);
    __syncthreads();

    int nkb = K / GBK;
    int buf = 0;
    for (int kb = 0; kb < nkb; kb++) {
        bool more = (kb + 1 < nkb);
        if (more) prefetch(kb + 1);

        uint32_t base = smb + buf * STAGE_B;
        uint32_t ah_base = base + (uint32_t)(warpM * 64) * SROW + a_off;
        uint32_t al_base = ah_base + TILE_B;
        uint32_t bh_base = base + 2 * TILE_B + (uint32_t)(warpN * 32) * SROW + b_off;
        uint32_t bl_base = bh_base + TILE_B;

#pragma unroll
        for (int ks = 0; ks < 2; ks++) {
            uint32_t koff = (uint32_t)(ks * 32);   // 16 bf16 = 32 bytes
            uint32_t Bh[4][2], Bl[4][2];
#pragma unroll
            for (int ntp = 0; ntp < 2; ntp++) {
                uint32_t r0, r1, r2, r3;
                ldm4(bh_base + (uint32_t)(ntp * 16 * SROW) + koff, r0, r1, r2, r3);
                Bh[2 * ntp][0] = r0; Bh[2 * ntp][1] = r1;
                Bh[2 * ntp + 1][0] = r2; Bh[2 * ntp + 1][1] = r3;
                ldm4(bl_base + (uint32_t)(ntp * 16 * SROW) + koff, r0, r1, r2, r3);
                Bl[2 * ntp][0] = r0; Bl[2 * ntp][1] = r1;
                Bl[2 * ntp + 1][0] = r2; Bl[2 * ntp + 1][1] = r3;
            }
#pragma unroll
            for (int mt = 0; mt < 4; mt++) {
                uint32_t Ah[4], Al[4];
                ldm4(ah_base + (uint32_t)(mt * 16 * SROW) + koff, Ah[0], Ah[1], Ah[2], Ah[3]);
                ldm4(al_base + (uint32_t)(mt * 16 * SROW) + koff, Al[0], Al[1], Al[2], Al[3]);
#pragma unroll
                for (int nt = 0; nt < 4; nt++) {
                    mma_bf16(c[mt][nt], Ah, Bh[nt]);
                    mma_bf16(c[mt][nt], Ah, Bl[nt]);
                    mma_bf16(c[mt][nt], Al, Bh[nt]);
                }
            }
        }

        if (more) store_stage(buf ^ 1);
        __syncthreads();
        buf ^= 1;
    }

    // epilogue: c frag (row = lane/4 [+8], col = 2*(lane%4))
    int erow = lane >> 2;
    int ecol = (lane & 3) * 2;
#pragma unroll
    for (int mt = 0; mt < 4; mt++) {
#pragma unroll
        for (int nt = 0; nt < 4; nt++) {
            int row0 = bm + warpM * 64 + mt * 16 + erow;
            int col = bn + warpN * 32 + nt * 8 + ecol;
            *(float2*)(C + (size_t)row0 * N + col) = make_float2(c[mt][nt][0], c[mt][nt][1]);
            *(float2*)(C + (size_t)(row0 + 8) * N + col) = make_float2(c[mt][nt][2], c[mt][nt][3]);
        }
    }
}

// ============================================================
// Fused RMSNorm + RoPE (in place on q and k heads of g_qkv)
// ============================================================
__global__ __launch_bounds__(256) void norm_rope(
    const int* __restrict__ positions,
    const float* __restrict__ qw, const float* __restrict__ kw)
{
    const int NHEADS = NH + NKV;  // 36
    int warp = (blockIdx.x * blockDim.x + threadIdx.x) >> 5;
    int lane = threadIdx.x & 31;
    int total = BTOK * NHEADS;
    if (warp >= total) return;

    int gidx = warp % NHEADS;
    int tok = warp / NHEADS;
    const float* w = (gidx < NH) ? qw : kw;
    int off = (gidx < NH) ? gidx * HD : K_OFF + (gidx - NH) * HD;
    float* x = g_qkv + (size_t)tok * QKV_DIM + off;

    float xa = x[lane], xb = x[lane + 32], xc = x[lane + 64], xd = x[lane + 96];
    float ss = xa * xa + xb * xb + xc * xc + xd * xd;
#pragma unroll
    for (int o = 16; o; o >>= 1) ss += __shfl_xor_sync(0xffffffffu, ss, o);
    float rr = rsqrtf(ss * (1.f / 128.f) + 1e-6f);
    xa *= rr * w[lane];
    xb *= rr * w[lane + 32];
    xc *= rr * w[lane + 64];
    xd *= rr * w[lane + 96];

    float pos = (float)positions[tok];
    float inv1 = powf(1.0e6f, -(float)lane * (1.f / 64.f));
    float inv2 = powf(1.0e6f, -(float)(lane + 32) * (1.f / 64.f));
    float s1, c1, s2, c2;
    sincosf(pos * inv1, &s1, &c1);
    sincosf(pos * inv2, &s2, &c2);

    x[lane]      = xa * c1 - xc * s1;
    x[lane + 64] = xc * c1 + xa * s1;
    x[lane + 32] = xb * c2 - xd * s2;
    x[lane + 96] = xd * c2 + xb * s2;
}

// ============================================================
// Causal flash attention (fp32) — unchanged
// ============================================================
#define AT_BM 64
#define AT_BN 64
#define KP 129
#define PP 65
#define ATTN_SMEM_FLOATS (AT_BM * HD + 2 * AT_BN * KP + AT_BM * PP)
#define ATTN_SMEM_BYTES (ATTN_SMEM_FLOATS * 4)

__global__ __launch_bounds__(256, 1) void attn_kernel()
{
    extern __shared__ float smf[];
    float* Qs = smf;
    float* Ks = Qs + AT_BM * HD;
    float* Vs = Ks + AT_BN * KP;
    float* Ps = Vs + AT_BN * KP;

    int tile = blockIdx.x;
    int h = blockIdx.y;
    int b = blockIdx.z;
    int kvh = h >> 3;
    int tid = threadIdx.x;
    int cg = tid & 15;
    int rg = tid >> 4;

    const float scale = 0.08838834764831843f;
    int q0 = tile * AT_BM;

    for (int idx = tid; idx < AT_BM * HD; idx += 256) {
        int row = idx >> 7, d = idx & 127;
        Qs[row * HD + d] =
            g_qkv[(size_t)(b * SS + q0 + row) * QKV_DIM + h * HD + d] * scale;
    }
    __syncthreads();

    float m[4], l[4], acc[4][8];
#pragma unroll
    for (int i = 0; i < 4; i++) {
        m[i] = -1e30f; l[i] = 0.f;
#pragma unroll
        for (int d = 0; d < 8; d++) acc[i][d] = 0.f;
    }

    int ntiles = tile + 1;
    for (int t = 0; t < ntiles; ++t) {
        for (int idx = tid; idx < AT_BN * HD; idx += 256) {
            int row = idx >> 7, d = idx & 127;
            size_t tokoff = (size_t)(b * SS + t * AT_BN + row) * QKV_DIM;
            Ks[row * KP + d] = g_qkv[tokoff + K_OFF + kvh * HD + d];
            Vs[row * KP + d] = g_qkv[tokoff + V_OFF + kvh * HD + d];
        }
        __syncthreads();

        float s[4][4];
#pragma unroll
        for (int i = 0; i < 4; i++)
#pragma unroll
            for (int j = 0; j < 4; j++) s[i][j] = 0.f;

        const float* qbase = Qs + (rg * 4) * HD;
        const float* kbase = Ks + (cg * 4) * KP;
#pragma unroll 4
        for (int d = 0; d < HD; ++d) {
            float qf[4], kf[4];
#pragma unroll
            for (int i = 0; i < 4; i++) qf[i] = qbase[i * HD + d];
#pragma unroll
            for (int j = 0; j < 4; j++) kf[j] = kbase[j * KP + d];
#pragma unroll
            for (int i = 0; i < 4; i++)
#pragma unroll
                for (int j = 0; j < 4; j++)
                    s[i][j] += qf[i] * kf[j];
        }

        if (t == tile) {
#pragma unroll
            for (int i = 0; i < 4; i++) {
                int qi = q0 + rg * 4 + i;
#pragma unroll
                for (int j = 0; j < 4; j++) {
                    int kj = t * AT_BN + cg * 4 + j;
                    if (kj > qi) s[i][j] = -1e30f;
                }
            }
        }

#pragma unroll
        for (int i = 0; i < 4; i++) {
            float mt = fmaxf(fmaxf(s[i][0], s[i][1]), fmaxf(s[i][2], s[i][3]));
            mt = fmaxf(mt, __shfl_xor_sync(0xffffffffu, mt, 1));
            mt = fmaxf(mt, __shfl_xor_sync(0xffffffffu, mt, 2));
            mt = fmaxf(mt, __shfl_xor_sync(0xffffffffu, mt, 4));
            mt = fmaxf(mt, __shfl_xor_sync(0xffffffffu, mt, 8));
            float mnew = fmaxf(m[i], mt);
            float corr = __expf(m[i] - mnew);
            float ps = 0.f;
#pragma unroll
            for (int j = 0; j < 4; j++) {
                float p = __expf(s[i][j] - mnew);
                s[i][j] = p;
                ps += p;
            }
            ps += __shfl_xor_sync(0xffffffffu, ps, 1);
            ps += __shfl_xor_sync(0xffffffffu, ps, 2);
            ps += __shfl_xor_sync(0xffffffffu, ps, 4);
            ps += __shfl_xor_sync(0xffffffffu, ps, 8);
            l[i] = l[i] * corr + ps;
            m[i] = mnew;
#pragma unroll
            for (int d = 0; d < 8; d++) acc[i][d] *= corr;
#pragma unroll
            for (int j = 0; j < 4; j++)
                Ps[(rg * 4 + i) * PP + cg * 4 + j] = s[i][j];
        }
        __syncwarp();

#pragma unroll 2
        for (int j = 0; j < AT_BN; ++j) {
            float pv[4];
#pragma unroll
            for (int i = 0; i < 4; i++) pv[i] = Ps[(rg * 4 + i) * PP + j];
            float vf[8];
            const float* vrow = Vs + j * KP + cg;
#pragma unroll
            for (int d = 0; d < 8; d++) vf[d] = vrow[d * 16];
#pragma unroll
            for (int i = 0; i < 4; i++)
#pragma unroll
                for (int d = 0; d < 8; d++)
                    acc[i][d] += pv[i] * vf[d];
        }
        __syncthreads();
    }

#pragma unroll
    for (int i = 0; i < 4; i++) {
        float inv = 1.f / l[i];
        size_t row = (size_t)(b * SS + q0 + rg * 4 + i) * ATTN_DIM + h * HD;
#pragma unroll
        for (int d = 0; d < 8; d++)
            g_attn[row + cg + 16 * d] = acc[i][d] * inv;
    }
}

// ============================================================
// launch
// ============================================================
extern "C" void kernel_launch(void* const* d_in, const int* in_sizes, int n_in,
                              void* d_out, int out_size)
{
    const float* hidden    = (const float*)d_in[0];
    const int*   positions = (const int*)d_in[1];
    const float* w_qkv     = (const float*)d_in[2];
    const float* w_o       = (const float*)d_in[3];
    const float* q_norm_w  = (const float*)d_in[4];
    const float* k_norm_w  = (const float*)d_in[5];
    float* out = (float*)d_out;

    float* qkv_buf = nullptr;
    float* attn_buf = nullptr;
    cudaGetSymbolAddress((void**)&qkv_buf, g_qkv);
    cudaGetSymbolAddress((void**)&attn_buf, g_attn);

    cudaFuncSetAttribute(attn_kernel,
                         cudaFuncAttributeMaxDynamicSharedMemorySize,
                         ATTN_SMEM_BYTES);
    cudaFuncSetAttribute(gemm_bf16split,
                         cudaFuncAttributeMaxDynamicSharedMemorySize,
                         GEMM_SMEM);

    // 1) QKV projection: [4096,2048] x [5120,2048]^T -> [4096,5120]
    gemm_bf16split<<<dim3(QKV_DIM / GBN, BTOK / GBM), 256, GEMM_SMEM>>>(
        hidden, w_qkv, qkv_buf, BTOK, QKV_DIM, HIDDEN);

    // 2) RMSNorm + RoPE on q and k heads (in place)
    {
        int total_warps = BTOK * (NH + NKV);
        int blocks = (total_warps + 7) / 8;
        norm_rope<<<blocks, 256>>>(positions, q_norm_w, k_norm_w);
    }

    // 3) causal GQA flash attention -> g_attn [4096, 4096]
    attn_kernel<<<dim3(SS / AT_BM, NH, BB), 256, ATTN_SMEM_BYTES>>>();

    // 4) O projection: [4096,4096] x [2048,4096]^T -> [4096,2048]
    gemm_bf16split<<<dim3(HIDDEN / GBN, BTOK / GBM), 256, GEMM_SMEM>>>(
        attn_buf, w_o, out, BTOK, HIDDEN, ATTN_DIM);
}

// round 4
// speedup vs baseline: 3.0828x; 1.7069x over previous
#include <cuda_runtime.h>
#include <cstdint>
#include <math.h>
#include <float.h>

// Problem constants
#define HIDDEN   2048
#define NH       32
#define NKV      4
#define HD       128
#define BB       2
#define SS       2048
#define BTOK     (BB * SS)              // 4096 tokens
#define QKV_DIM  ((NH + 2 * NKV) * HD)  // 5120
#define ATTN_DIM (NH * HD)              // 4096
#define K_OFF    (NH * HD)              // 4096
#define V_OFF    (NH * HD + NKV * HD)   // 4608

// Scratch (no runtime allocation allowed)
__device__ float g_qkv[(size_t)BTOK * QKV_DIM];   // ~84 MB
__device__ float g_attn[(size_t)BTOK * ATTN_DIM]; // ~67 MB

// ============================================================
// helpers
// ============================================================
__device__ __forceinline__ uint32_t smem_u32(const void* p) {
    uint32_t a;
    asm("{ .reg .u64 t; cvta.to.shared.u64 t, %1; cvt.u32.u64 %0, t; }" : "=r"(a) : "l"(p));
    return a;
}
// split (x,y) into packed bf16x2 high + low parts (lo lane = x, hi lane = y)
__device__ __forceinline__ void split2(float x, float y, uint32_t& h, uint32_t& l) {
    asm("cvt.rn.bf16x2.f32 %0, %1, %2;" : "=r"(h) : "f"(y), "f"(x));
    float hx = __uint_as_float(h << 16);
    float hy = __uint_as_float(h & 0xffff0000u);
    float rx = x - hx, ry = y - hy;
    asm("cvt.rn.bf16x2.f32 %0, %1, %2;" : "=r"(l) : "f"(ry), "f"(rx));
}
__device__ __forceinline__ void ldm4(uint32_t addr, uint32_t& r0, uint32_t& r1,
                                     uint32_t& r2, uint32_t& r3) {
    asm volatile("ldmatrix.sync.aligned.m8n8.x4.shared.b16 {%0,%1,%2,%3}, [%4];"
                 : "=r"(r0), "=r"(r1), "=r"(r2), "=r"(r3) : "r"(addr));
}
__device__ __forceinline__ void ldm4t(uint32_t addr, uint32_t& r0, uint32_t& r1,
                                      uint32_t& r2, uint32_t& r3) {
    asm volatile("ldmatrix.sync.aligned.m8n8.x4.trans.shared.b16 {%0,%1,%2,%3}, [%4];"
                 : "=r"(r0), "=r"(r1), "=r"(r2), "=r"(r3) : "r"(addr));
}
__device__ __forceinline__ void mma_bf16(float* c, const uint32_t* a, const uint32_t* b) {
    asm volatile(
        "mma.sync.aligned.m16n8k16.row.col.f32.bf16.bf16.f32 "
        "{%0,%1,%2,%3}, {%4,%5,%6,%7}, {%8,%9}, {%0,%1,%2,%3};"
        : "+f"(c[0]), "+f"(c[1]), "+f"(c[2]), "+f"(c[3])
        : "r"(a[0]), "r"(a[1]), "r"(a[2]), "r"(a[3]), "r"(b[0]), "r"(b[1]));
}

// ============================================================
// bf16-split tensor-core GEMM (NT): C[M,N] = A[M,K] * B[N,K]^T
// 128x128x32 block tile, 8 warps (2x4), warp tile 64x32
// 3 passes (AhBh + AhBl + AlBh) for fp32-class accuracy
// ============================================================
#define GBM 128
#define GBN 128
#define GBK 32
#define SROW 80                       // smem row stride in bytes (32 bf16 + 8 pad)
#define TILE_B (128 * SROW)           // 10240 B, one 128x32 bf16 tile
#define STAGE_B (4 * TILE_B)          // Ah, Al, Bh, Bl
#define GEMM_SMEM (2 * STAGE_B)       // 81920 B

__global__ __launch_bounds__(256, 1) void gemm_bf16split(
    const float* __restrict__ A, const float* __restrict__ B,
    float* __restrict__ C, int M, int N, int K)
{
    extern __shared__ char smc[];
    uint32_t smb = smem_u32(smc);
    int tid = threadIdx.x;
    int lane = tid & 31;
    int wid = tid >> 5;
    int warpM = wid >> 2;             // 0..1 -> 64 rows
    int warpN = wid & 3;              // 0..3 -> 32 cols
    int bm = blockIdx.y * GBM;
    int bn = blockIdx.x * GBN;

    int g = lane >> 3, r = lane & 7;
    uint32_t a_off = (uint32_t)(((g & 1) * 8 + r) * SROW + (g >> 1) * 16);
    uint32_t b_off = (uint32_t)(((g >> 1) * 8 + r) * SROW + (g & 1) * 16);

    int lrow[4], lc4[4];
#pragma unroll
    for (int i = 0; i < 4; i++) {
        int idx = tid + i * 256;
        lrow[i] = idx >> 3;
        lc4[i] = idx & 7;
    }

    const float* Ag = A + (size_t)bm * K;
    const float* Bg = B + (size_t)bn * K;

    float c[4][4][4];
#pragma unroll
    for (int mt = 0; mt < 4; mt++)
#pragma unroll
        for (int nt = 0; nt < 4; nt++)
#pragma unroll
            for (int e = 0; e < 4; e++) c[mt][nt][e] = 0.f;

    float4 pa[4], pb[4];

    auto prefetch = [&](int kb) {
        int k0 = kb * GBK;
#pragma unroll
        for (int i = 0; i < 4; i++) {
            pa[i] = *(const float4*)(Ag + (size_t)lrow[i] * K + k0 + lc4[i] * 4);
            pb[i] = *(const float4*)(Bg + (size_t)lrow[i] * K + k0 + lc4[i] * 4);
        }
    };
    auto store_stage = [&](int buf) {
        char* st = smc + buf * STAGE_B;
#pragma unroll
        for (int i = 0; i < 4; i++) {
            uint32_t off = (uint32_t)(lrow[i] * SROW + lc4[i] * 8);
            uint32_t h0, l0, h1, l1;
            split2(pa[i].x, pa[i].y, h0, l0);
            split2(pa[i].z, pa[i].w, h1, l1);
            *(uint2*)(st + off) = make_uint2(h0, h1);
            *(uint2*)(st + TILE_B + off) = make_uint2(l0, l1);
            split2(pb[i].x, pb[i].y, h0, l0);
            split2(pb[i].z, pb[i].w, h1, l1);
            *(uint2*)(st + 2 * TILE_B + off) = make_uint2(h0, h1);
            *(uint2*)(st + 3 * TILE_B + off) = make_uint2(l0, l1);
        }
    };

    prefetch(0);
    store_stage(0);
    __syncthreads();

    int nkb = K / GBK;
    int buf = 0;
    for (int kb = 0; kb < nkb; kb++) {
        bool more = (kb + 1 < nkb);
        if (more) prefetch(kb + 1);

        uint32_t base = smb + buf * STAGE_B;
        uint32_t ah_base = base + (uint32_t)(warpM * 64) * SROW + a_off;
        uint32_t al_base = ah_base + TILE_B;
        uint32_t bh_base = base + 2 * TILE_B + (uint32_t)(warpN * 32) * SROW + b_off;
        uint32_t bl_base = bh_base + TILE_B;

#pragma unroll
        for (int ks = 0; ks < 2; ks++) {
            uint32_t koff = (uint32_t)(ks * 32);
            uint32_t Bh[4][2], Bl[4][2];
#pragma unroll
            for (int ntp = 0; ntp < 2; ntp++) {
                uint32_t r0, r1, r2, r3;
                ldm4(bh_base + (uint32_t)(ntp * 16 * SROW) + koff, r0, r1, r2, r3);
                Bh[2 * ntp][0] = r0; Bh[2 * ntp][1] = r1;
                Bh[2 * ntp + 1][0] = r2; Bh[2 * ntp + 1][1] = r3;
                ldm4(bl_base + (uint32_t)(ntp * 16 * SROW) + koff, r0, r1, r2, r3);
                Bl[2 * ntp][0] = r0; Bl[2 * ntp][1] = r1;
                Bl[2 * ntp + 1][0] = r2; Bl[2 * ntp + 1][1] = r3;
            }
#pragma unroll
            for (int mt = 0; mt < 4; mt++) {
                uint32_t Ah[4], Al[4];
                ldm4(ah_base + (uint32_t)(mt * 16 * SROW) + koff, Ah[0], Ah[1], Ah[2], Ah[3]);
                ldm4(al_base + (uint32_t)(mt * 16 * SROW) + koff, Al[0], Al[1], Al[2], Al[3]);
#pragma unroll
                for (int nt = 0; nt < 4; nt++) {
                    mma_bf16(c[mt][nt], Ah, Bh[nt]);
                    mma_bf16(c[mt][nt], Ah, Bl[nt]);
                    mma_bf16(c[mt][nt], Al, Bh[nt]);
                }
            }
        }

        if (more) store_stage(buf ^ 1);
        __syncthreads();
        buf ^= 1;
    }

    int erow = lane >> 2;
    int ecol = (lane & 3) * 2;
#pragma unroll
    for (int mt = 0; mt < 4; mt++) {
#pragma unroll
        for (int nt = 0; nt < 4; nt++) {
            int row0 = bm + warpM * 64 + mt * 16 + erow;
            int col = bn + warpN * 32 + nt * 8 + ecol;
            *(float2*)(C + (size_t)row0 * N + col) = make_float2(c[mt][nt][0], c[mt][nt][1]);
            *(float2*)(C + (size_t)(row0 + 8) * N + col) = make_float2(c[mt][nt][2], c[mt][nt][3]);
        }
    }
}

// ============================================================
// Fused RMSNorm + RoPE (in place on q and k heads of g_qkv)
// ============================================================
__global__ __launch_bounds__(256) void norm_rope(
    const int* __restrict__ positions,
    const float* __restrict__ qw, const float* __restrict__ kw)
{
    const int NHEADS = NH + NKV;  // 36
    int warp = (blockIdx.x * blockDim.x + threadIdx.x) >> 5;
    int lane = threadIdx.x & 31;
    int total = BTOK * NHEADS;
    if (warp >= total) return;

    int gidx = warp % NHEADS;
    int tok = warp / NHEADS;
    const float* w = (gidx < NH) ? qw : kw;
    int off = (gidx < NH) ? gidx * HD : K_OFF + (gidx - NH) * HD;
    float* x = g_qkv + (size_t)tok * QKV_DIM + off;

    float xa = x[lane], xb = x[lane + 32], xc = x[lane + 64], xd = x[lane + 96];
    float ss = xa * xa + xb * xb + xc * xc + xd * xd;
#pragma unroll
    for (int o = 16; o; o >>= 1) ss += __shfl_xor_sync(0xffffffffu, ss, o);
    float rr = rsqrtf(ss * (1.f / 128.f) + 1e-6f);
    xa *= rr * w[lane];
    xb *= rr * w[lane + 32];
    xc *= rr * w[lane + 64];
    xd *= rr * w[lane + 96];

    float pos = (float)positions[tok];
    float inv1 = powf(1.0e6f, -(float)lane * (1.f / 64.f));
    float inv2 = powf(1.0e6f, -(float)(lane + 32) * (1.f / 64.f));
    float s1, c1, s2, c2;
    sincosf(pos * inv1, &s1, &c1);
    sincosf(pos * inv2, &s2, &c2);

    x[lane]      = xa * c1 - xc * s1;
    x[lane + 64] = xc * c1 + xa * s1;
    x[lane + 32] = xb * c2 - xd * s2;
    x[lane + 96] = xd * c2 + xb * s2;
}

// ============================================================
// Tensor-core causal flash attention (bf16-split, 3-pass)
// grid (S/64, NH, B), 128 threads (4 warps, warp = 16 q-rows)
// ============================================================
#define FA_BM 64
#define FA_BN 64
#define FROW 272                 // 128 bf16 = 256 B + 16 pad
#define FTILE (64 * FROW)        // 17408 B
#define SQH 0
#define SQL (1 * FTILE)
#define SKH (2 * FTILE)
#define SKL (3 * FTILE)
#define SVH (4 * FTILE)
#define SVL (5 * FTILE)
#define FA_SMEM (6 * FTILE)      // 104448 B

__global__ __launch_bounds__(128, 1) void attn_tc()
{
    extern __shared__ char smc[];
    uint32_t smb = smem_u32(smc);
    int tid = threadIdx.x;
    int lane = tid & 31;
    int wid = tid >> 5;
    int qtile = blockIdx.x;
    int h = blockIdx.y;
    int b = blockIdx.z;
    int kvh = h >> 3;
    int q0 = qtile * FA_BM;

    int g8 = lane >> 3, r8 = lane & 7;
    uint32_t a_off = (uint32_t)(((g8 & 1) * 8 + r8) * FROW + (g8 >> 1) * 16);
    uint32_t b_off = (uint32_t)(((g8 >> 1) * 8 + r8) * FROW + (g8 & 1) * 16);

    const float scale = 0.08838834764831843f;  // 1/sqrt(128)

    // load + scale + split Q tile (64 x 128)
    for (int i = tid; i < FA_BM * 32; i += 128) {
        int row = i >> 5, c4 = i & 31;
        float4 v = *(const float4*)(g_qkv + (size_t)(b * SS + q0 + row) * QKV_DIM + h * HD + c4 * 4);
        v.x *= scale; v.y *= scale; v.z *= scale; v.w *= scale;
        uint32_t h0, l0, h1, l1;
        split2(v.x, v.y, h0, l0);
        split2(v.z, v.w, h1, l1);
        char* dst = smc + row * FROW + c4 * 8;
        *(uint2*)(dst + SQH) = make_uint2(h0, h1);
        *(uint2*)(dst + SQL) = make_uint2(l0, l1);
    }

    float m0 = -1e30f, m1 = -1e30f, lsum0 = 0.f, lsum1 = 0.f;
    float co[16][4];
#pragma unroll
    for (int nf = 0; nf < 16; nf++)
#pragma unroll
        for (int e = 0; e < 4; e++) co[nf][e] = 0.f;

    for (int t = 0; t <= qtile; t++) {
        __syncthreads();   // previous iteration's reads done before overwrite
        int kv0 = t * FA_BN;
        for (int i = tid; i < FA_BN * 32; i += 128) {
            int row = i >> 5, c4 = i & 31;
            size_t tok = (size_t)(b * SS + kv0 + row) * QKV_DIM + kvh * HD + c4 * 4;
            float4 kv4 = *(const float4*)(g_qkv + tok + K_OFF);
            uint32_t h0, l0, h1, l1;
            split2(kv4.x, kv4.y, h0, l0);
            split2(kv4.z, kv4.w, h1, l1);
            char* dst = smc + row * FROW + c4 * 8;
            *(uint2*)(dst + SKH) = make_uint2(h0, h1);
            *(uint2*)(dst + SKL) = make_uint2(l0, l1);
            float4 vv4 = *(const float4*)(g_qkv + tok + V_OFF);
            split2(vv4.x, vv4.y, h0, l0);
            split2(vv4.z, vv4.w, h1, l1);
            *(uint2*)(dst + SVH) = make_uint2(h0, h1);
            *(uint2*)(dst + SVL) = make_uint2(l0, l1);
        }
        __syncthreads();

        // ---- scores S = Q K^T (3-pass split) ----
        float cs[4][2][4];
#pragma unroll
        for (int nb = 0; nb < 4; nb++)
#pragma unroll
            for (int f = 0; f < 2; f++)
#pragma unroll
                for (int e = 0; e < 4; e++) cs[nb][f][e] = 0.f;

        uint32_t qrow = (uint32_t)(wid * 16) * FROW;
#pragma unroll
        for (int ks = 0; ks < 8; ks++) {
            uint32_t koff = (uint32_t)(ks * 32);
            uint32_t ah[4], al[4];
            ldm4(smb + SQH + qrow + koff + a_off, ah[0], ah[1], ah[2], ah[3]);
            ldm4(smb + SQL + qrow + koff + a_off, al[0], al[1], al[2], al[3]);
#pragma unroll
            for (int nb = 0; nb < 4; nb++) {
                uint32_t nboff = (uint32_t)(nb * 16) * FROW + koff;
                uint32_t bh[4], bl[4];
                ldm4(smb + SKH + nboff + b_off, bh[0], bh[1], bh[2], bh[3]);
                ldm4(smb + SKL + nboff + b_off, bl[0], bl[1], bl[2], bl[3]);
                mma_bf16(cs[nb][0], ah, bh);
                mma_bf16(cs[nb][0], ah, bl);
                mma_bf16(cs[nb][0], al, bh);
                mma_bf16(cs[nb][1], ah, bh + 2);
                mma_bf16(cs[nb][1], ah, bl + 2);
                mma_bf16(cs[nb][1], al, bh + 2);
            }
        }

        // ---- causal mask (diagonal tile only) ----
        if (t == qtile) {
            int row0 = q0 + wid * 16 + (lane >> 2);
#pragma unroll
            for (int nb = 0; nb < 4; nb++)
#pragma unroll
                for (int f = 0; f < 2; f++)
#pragma unroll
                    for (int e = 0; e < 4; e++) {
                        int col = kv0 + nb * 16 + f * 8 + 2 * (lane & 3) + (e & 1);
                        int row = row0 + ((e >> 1) ? 8 : 0);
                        if (col > row) cs[nb][f][e] = -1e30f;
                    }
        }

        // ---- online softmax (rows g and g+8) ----
        float mt0 = -1e30f, mt1 = -1e30f;
#pragma unroll
        for (int nb = 0; nb < 4; nb++)
#pragma unroll
            for (int f = 0; f < 2; f++) {
                mt0 = fmaxf(mt0, fmaxf(cs[nb][f][0], cs[nb][f][1]));
                mt1 = fmaxf(mt1, fmaxf(cs[nb][f][2], cs[nb][f][3]));
            }
        mt0 = fmaxf(mt0, __shfl_xor_sync(0xffffffffu, mt0, 1));
        mt0 = fmaxf(mt0, __shfl_xor_sync(0xffffffffu, mt0, 2));
        mt1 = fmaxf(mt1, __shfl_xor_sync(0xffffffffu, mt1, 1));
        mt1 = fmaxf(mt1, __shfl_xor_sync(0xffffffffu, mt1, 2));
        float mn0 = fmaxf(m0, mt0);
        float mn1 = fmaxf(m1, mt1);
        float corr0 = __expf(m0 - mn0);
        float corr1 = __expf(m1 - mn1);
        float ps0 = 0.f, ps1 = 0.f;
#pragma unroll
        for (int nb = 0; nb < 4; nb++)
#pragma unroll
            for (int f = 0; f < 2; f++) {
                cs[nb][f][0] = __expf(cs[nb][f][0] - mn0);
                cs[nb][f][1] = __expf(cs[nb][f][1] - mn0);
                cs[nb][f][2] = __expf(cs[nb][f][2] - mn1);
                cs[nb][f][3] = __expf(cs[nb][f][3] - mn1);
                ps0 += cs[nb][f][0] + cs[nb][f][1];
                ps1 += cs[nb][f][2] + cs[nb][f][3];
            }
        ps0 += __shfl_xor_sync(0xffffffffu, ps0, 1);
        ps0 += __shfl_xor_sync(0xffffffffu, ps0, 2);
        ps1 += __shfl_xor_sync(0xffffffffu, ps1, 1);
        ps1 += __shfl_xor_sync(0xffffffffu, ps1, 2);
        lsum0 = lsum0 * corr0 + ps0;
        lsum1 = lsum1 * corr1 + ps1;
        m0 = mn0; m1 = mn1;
#pragma unroll
        for (int nf = 0; nf < 16; nf++) {
            co[nf][0] *= corr0; co[nf][1] *= corr0;
            co[nf][2] *= corr1; co[nf][3] *= corr1;
        }

        // ---- O += P V (3-pass split), V frags via ldmatrix.trans ----
#pragma unroll
        for (int ks = 0; ks < 4; ks++) {
            uint32_t ph[4], pl[4];
            split2(cs[ks][0][0], cs[ks][0][1], ph[0], pl[0]);
            split2(cs[ks][0][2], cs[ks][0][3], ph[1], pl[1]);
            split2(cs[ks][1][0], cs[ks][1][1], ph[2], pl[2]);
            split2(cs[ks][1][2], cs[ks][1][3], ph[3], pl[3]);
            uint32_t krow = (uint32_t)(ks * 16) * FROW;
#pragma unroll
            for (int db = 0; db < 8; db++) {
                uint32_t doff = krow + (uint32_t)(db * 32) + a_off;
                uint32_t bh[4], bl[4];
                ldm4t(smb + SVH + doff, bh[0], bh[1], bh[2], bh[3]);
                ldm4t(smb + SVL + doff, bl[0], bl[1], bl[2], bl[3]);
                mma_bf16(co[2 * db], ph, bh);
                mma_bf16(co[2 * db], ph, bl);
                mma_bf16(co[2 * db], pl, bh);
                mma_bf16(co[2 * db + 1], ph, bh + 2);
                mma_bf16(co[2 * db + 1], ph, bl + 2);
                mma_bf16(co[2 * db + 1], pl, bh + 2);
            }
        }
    }

    // epilogue
    float inv0 = 1.f / lsum0;
    float inv1 = 1.f / lsum1;
    int row0 = b * SS + q0 + wid * 16 + (lane >> 2);
    int colb = h * HD + 2 * (lane & 3);
#pragma unroll
    for (int nf = 0; nf < 16; nf++) {
        int col = colb + nf * 8;
        *(float2*)(g_attn + (size_t)row0 * ATTN_DIM + col) =
            make_float2(co[nf][0] * inv0, co[nf][1] * inv0);
        *(float2*)(g_attn + (size_t)(row0 + 8) * ATTN_DIM + col) =
            make_float2(co[nf][2] * inv1, co[nf][3] * inv1);
    }
}

// ============================================================
// launch
// ============================================================
extern "C" void kernel_launch(void* const* d_in, const int* in_sizes, int n_in,
                              void* d_out, int out_size)
{
    const float* hidden    = (const float*)d_in[0];
    const int*   positions = (const int*)d_in[1];
    const float* w_qkv     = (const float*)d_in[2];
    const float* w_o       = (const float*)d_in[3];
    const float* q_norm_w  = (const float*)d_in[4];
    const float* k_norm_w  = (const float*)d_in[5];
    float* out = (float*)d_out;

    float* qkv_buf = nullptr;
    float* attn_buf = nullptr;
    cudaGetSymbolAddress((void**)&qkv_buf, g_qkv);
    cudaGetSymbolAddress((void**)&attn_buf, g_attn);

    cudaFuncSetAttribute(gemm_bf16split,
                         cudaFuncAttributeMaxDynamicSharedMemorySize, GEMM_SMEM);
    cudaFuncSetAttribute(attn_tc,
                         cudaFuncAttributeMaxDynamicSharedMemorySize, FA_SMEM);

    // 1) QKV projection
    gemm_bf16split<<<dim3(QKV_DIM / GBN, BTOK / GBM), 256, GEMM_SMEM>>>(
        hidden, w_qkv, qkv_buf, BTOK, QKV_DIM, HIDDEN);

    // 2) RMSNorm + RoPE
    {
        int total_warps = BTOK * (NH + NKV);
        int blocks = (total_warps + 7) / 8;
        norm_rope<<<blocks, 256>>>(positions, q_norm_w, k_norm_w);
    }

    // 3) causal GQA flash attention (tensor cores)
    attn_tc<<<dim3(SS / FA_BM, NH, BB), 128, FA_SMEM>>>();

    // 4) O projection
    gemm_bf16split<<<dim3(HIDDEN / GBN, BTOK / GBM), 256, GEMM_SMEM>>>(
        attn_buf, w_o, out, BTOK, HIDDEN, ATTN_DIM);
}

// round 5
// speedup vs baseline: 3.3130x; 1.0747x over previous
#include <cuda_runtime.h>
#include <cuda_bf16.h>
#include <cstdint>
#include <math.h>

// Problem constants
#define HIDDEN   2048
#define NH       32
#define NKV      4
#define HD       128
#define BB       2
#define SS       2048
#define BTOK     (BB * SS)              // 4096
#define QKV_DIM  ((NH + 2 * NKV) * HD)  // 5120
#define ATTN_DIM (NH * HD)              // 4096
#define K_OFF    (NH * HD)              // 4096
#define V_OFF    (NH * HD + NKV * HD)   // 4608
#define QSCALE   0.08838834764831843f   // 1/sqrt(128)

// ------------------------------------------------------------
// Scratch (device globals; no runtime allocation allowed)
// ------------------------------------------------------------
__device__ float g_qkv[(size_t)BTOK * QKV_DIM];                         // fp32 qkv proj
__device__ __nv_bfloat16 g_hh[(size_t)BTOK * HIDDEN];                   // hidden hi/lo
__device__ __nv_bfloat16 g_hl[(size_t)BTOK * HIDDEN];
__device__ __nv_bfloat16 g_wqh[(size_t)QKV_DIM * HIDDEN];               // w_qkv hi/lo
__device__ __nv_bfloat16 g_wql[(size_t)QKV_DIM * HIDDEN];
__device__ __nv_bfloat16 g_woh[(size_t)HIDDEN * ATTN_DIM];              // w_o hi/lo
__device__ __nv_bfloat16 g_wol[(size_t)HIDDEN * ATTN_DIM];
__device__ __nv_bfloat16 g_qh[(size_t)BTOK * NH * HD];                  // Q (normed+roped+scaled)
__device__ __nv_bfloat16 g_ql[(size_t)BTOK * NH * HD];
__device__ __nv_bfloat16 g_kh[(size_t)BTOK * NKV * HD];                 // K (normed+roped)
__device__ __nv_bfloat16 g_kl[(size_t)BTOK * NKV * HD];
__device__ __nv_bfloat16 g_vh[(size_t)BTOK * NKV * HD];                 // V
__device__ __nv_bfloat16 g_vl[(size_t)BTOK * NKV * HD];
__device__ __nv_bfloat16 g_ah[(size_t)BTOK * ATTN_DIM];                 // attn out hi/lo
__device__ __nv_bfloat16 g_al[(size_t)BTOK * ATTN_DIM];

// ------------------------------------------------------------
// helpers
// ------------------------------------------------------------
__device__ __forceinline__ uint32_t smem_u32(const void* p) {
    uint32_t a;
    asm("{ .reg .u64 t; cvta.to.shared.u64 t, %1; cvt.u32.u64 %0, t; }" : "=r"(a) : "l"(p));
    return a;
}
// split (x,y) into packed bf16x2 high + low parts (lo lane = x, hi lane = y)
__device__ __forceinline__ void split2(float x, float y, uint32_t& h, uint32_t& l) {
    asm("cvt.rn.bf16x2.f32 %0, %1, %2;" : "=r"(h) : "f"(y), "f"(x));
    float hx = __uint_as_float(h << 16);
    float hy = __uint_as_float(h & 0xffff0000u);
    float rx = x - hx, ry = y - hy;
    asm("cvt.rn.bf16x2.f32 %0, %1, %2;" : "=r"(l) : "f"(ry), "f"(rx));
}
__device__ __forceinline__ void ldm4(uint32_t addr, uint32_t& r0, uint32_t& r1,
                                     uint32_t& r2, uint32_t& r3) {
    asm volatile("ldmatrix.sync.aligned.m8n8.x4.shared.b16 {%0,%1,%2,%3}, [%4];"
                 : "=r"(r0), "=r"(r1), "=r"(r2), "=r"(r3) : "r"(addr));
}
__device__ __forceinline__ void ldm4t(uint32_t addr, uint32_t& r0, uint32_t& r1,
                                      uint32_t& r2, uint32_t& r3) {
    asm volatile("ldmatrix.sync.aligned.m8n8.x4.trans.shared.b16 {%0,%1,%2,%3}, [%4];"
                 : "=r"(r0), "=r"(r1), "=r"(r2), "=r"(r3) : "r"(addr));
}
__device__ __forceinline__ void mma_bf16(float* c, const uint32_t* a, const uint32_t* b) {
    asm volatile(
        "mma.sync.aligned.m16n8k16.row.col.f32.bf16.bf16.f32 "
        "{%0,%1,%2,%3}, {%4,%5,%6,%7}, {%8,%9}, {%0,%1,%2,%3};"
        : "+f"(c[0]), "+f"(c[1]), "+f"(c[2]), "+f"(c[3])
        : "r"(a[0]), "r"(a[1]), "r"(a[2]), "r"(a[3]), "r"(b[0]), "r"(b[1]));
}
__device__ __forceinline__ void cp16(uint32_t dst, const void* src) {
    asm volatile("cp.async.cg.shared.global [%0], [%1], 16;" :: "r"(dst), "l"(src));
}
#define CP_COMMIT() asm volatile("cp.async.commit_group;" ::: "memory")
#define CP_WAIT0()  asm volatile("cp.async.wait_group 0;" ::: "memory")
#define CP_WAIT1()  asm volatile("cp.async.wait_group 1;" ::: "memory")

// ------------------------------------------------------------
// fp32 -> bf16 hi/lo split (bandwidth pass)
// ------------------------------------------------------------
__global__ __launch_bounds__(256) void split_f32(
    const float* __restrict__ x, __nv_bfloat16* __restrict__ h,
    __nv_bfloat16* __restrict__ l, int n4)
{
    int i = blockIdx.x * blockDim.x + threadIdx.x;
    if (i >= n4) return;
    float4 v = ((const float4*)x)[i];
    uint32_t h0, l0, h1, l1;
    split2(v.x, v.y, h0, l0);
    split2(v.z, v.w, h1, l1);
    ((uint2*)h)[i] = make_uint2(h0, h1);
    ((uint2*)l)[i] = make_uint2(l0, l1);
}

// ------------------------------------------------------------
// bf16-split tensor-core GEMM (NT): C = A[M,K] * B[N,K]^T, pre-split operands
// 128x128x32 tile, 8 warps, cp.async double-buffered, 2 CTAs/SM
// ------------------------------------------------------------
#define SROW 80                        // 32 bf16 = 64B + 16 pad
#define TILE_B (128 * SROW)            // 10240
#define STAGE_B (4 * TILE_B)           // 40960 (Ah, Al, Bh, Bl)
#define GEMM_SMEM (2 * STAGE_B)        // 81920

__global__ __launch_bounds__(256, 2) void gemm_tc(
    const __nv_bfloat16* __restrict__ Ah, const __nv_bfloat16* __restrict__ Al,
    const __nv_bfloat16* __restrict__ Bh, const __nv_bfloat16* __restrict__ Bl,
    float* __restrict__ C, int M, int N, int K)
{
    extern __shared__ char smc[];
    uint32_t smb = smem_u32(smc);
    int tid = threadIdx.x, lane = tid & 31, wid = tid >> 5;
    int warpM = wid >> 2, warpN = wid & 3;
    int bm = blockIdx.y * 128, bn = blockIdx.x * 128;

    int g8 = lane >> 3, r8 = lane & 7;
    uint32_t a_off = (uint32_t)(((g8 & 1) * 8 + r8) * SROW + (g8 >> 1) * 16);
    uint32_t b_off = (uint32_t)(((g8 >> 1) * 8 + r8) * SROW + (g8 & 1) * 16);

    auto stage_load = [&](int kb, int buf) {
        uint32_t base = smb + buf * STAGE_B;
        int k0 = kb * 32;
#pragma unroll
        for (int i = 0; i < 2; i++) {
            int c = tid + i * 256;             // 512 chunks: 128 rows x 4
            int row = c >> 2, c4 = c & 3;
            uint32_t doff = (uint32_t)(row * SROW + c4 * 16);
            size_t aoff = (size_t)(bm + row) * K + k0 + c4 * 8;
            size_t boff = (size_t)(bn + row) * K + k0 + c4 * 8;
            cp16(base + doff, Ah + aoff);
            cp16(base + TILE_B + doff, Al + aoff);
            cp16(base + 2 * TILE_B + doff, Bh + boff);
            cp16(base + 3 * TILE_B + doff, Bl + boff);
        }
    };

    float acc[4][4][4];
#pragma unroll
    for (int mt = 0; mt < 4; mt++)
#pragma unroll
        for (int nt = 0; nt < 4; nt++)
#pragma unroll
            for (int e = 0; e < 4; e++) acc[mt][nt][e] = 0.f;

    stage_load(0, 0);
    CP_COMMIT();

    int nkb = K / 32, buf = 0;
    for (int kb = 0; kb < nkb; kb++) {
        if (kb + 1 < nkb) {
            stage_load(kb + 1, buf ^ 1);
            CP_COMMIT();
            CP_WAIT1();
        } else {
            CP_WAIT0();
        }
        __syncthreads();

        uint32_t base = smb + buf * STAGE_B;
        uint32_t ah_b = base + (uint32_t)(warpM * 64) * SROW + a_off;
        uint32_t al_b = ah_b + TILE_B;
        uint32_t bh_b = base + 2 * TILE_B + (uint32_t)(warpN * 32) * SROW + b_off;
        uint32_t bl_b = bh_b + TILE_B;

#pragma unroll
        for (int ks = 0; ks < 2; ks++) {
            uint32_t koff = (uint32_t)(ks * 32);
            uint32_t Bh_[4][2], Bl_[4][2];
#pragma unroll
            for (int ntp = 0; ntp < 2; ntp++) {
                uint32_t r0, r1, r2, r3;
                ldm4(bh_b + (uint32_t)(ntp * 16 * SROW) + koff, r0, r1, r2, r3);
                Bh_[2 * ntp][0] = r0; Bh_[2 * ntp][1] = r1;
                Bh_[2 * ntp + 1][0] = r2; Bh_[2 * ntp + 1][1] = r3;
                ldm4(bl_b + (uint32_t)(ntp * 16 * SROW) + koff, r0, r1, r2, r3);
                Bl_[2 * ntp][0] = r0; Bl_[2 * ntp][1] = r1;
                Bl_[2 * ntp + 1][0] = r2; Bl_[2 * ntp + 1][1] = r3;
            }
#pragma unroll
            for (int mt = 0; mt < 4; mt++) {
                uint32_t A_h[4], A_l[4];
                ldm4(ah_b + (uint32_t)(mt * 16 * SROW) + koff, A_h[0], A_h[1], A_h[2], A_h[3]);
                ldm4(al_b + (uint32_t)(mt * 16 * SROW) + koff, A_l[0], A_l[1], A_l[2], A_l[3]);
#pragma unroll
                for (int nt = 0; nt < 4; nt++) {
                    mma_bf16(acc[mt][nt], A_h, Bh_[nt]);
                    mma_bf16(acc[mt][nt], A_h, Bl_[nt]);
                    mma_bf16(acc[mt][nt], A_l, Bh_[nt]);
                }
            }
        }
        __syncthreads();
        buf ^= 1;
    }

    int erow = lane >> 2;
    int ecol = (lane & 3) * 2;
#pragma unroll
    for (int mt = 0; mt < 4; mt++) {
#pragma unroll
        for (int nt = 0; nt < 4; nt++) {
            int row0 = bm + warpM * 64 + mt * 16 + erow;
            int col = bn + warpN * 32 + nt * 8 + ecol;
            *(float2*)(C + (size_t)row0 * N + col) = make_float2(acc[mt][nt][0], acc[mt][nt][1]);
            *(float2*)(C + (size_t)(row0 + 8) * N + col) = make_float2(acc[mt][nt][2], acc[mt][nt][3]);
        }
    }
}

// ------------------------------------------------------------
// Fused RMSNorm + RoPE + bf16 split (Q pre-scaled); V split too
// one warp per (token, group); groups: 32 Q, 4 K, 4 V
// ------------------------------------------------------------
__device__ __forceinline__ void sstore(__nv_bfloat16* dh, __nv_bfloat16* dl, int c, float v) {
    __nv_bfloat16 h = __float2bfloat16(v);
    dh[c] = h;
    dl[c] = __float2bfloat16(v - __bfloat162float(h));
}

__global__ __launch_bounds__(256) void norm_rope_split(
    const int* __restrict__ positions,
    const float* __restrict__ qw, const float* __restrict__ kw)
{
    const int NG = NH + 2 * NKV;  // 40
    int warp = (blockIdx.x * blockDim.x + threadIdx.x) >> 5;
    int lane = threadIdx.x & 31;
    if (warp >= BTOK * NG) return;
    int gidx = warp % NG;
    int tok = warp / NG;

    if (gidx < NH + NKV) {
        bool isQ = gidx < NH;
        const float* w = isQ ? qw : kw;
        int off = isQ ? gidx * HD : K_OFF + (gidx - NH) * HD;
        const float* x = g_qkv + (size_t)tok * QKV_DIM + off;

        float xa = x[lane], xb = x[lane + 32], xc = x[lane + 64], xd = x[lane + 96];
        float ss = xa * xa + xb * xb + xc * xc + xd * xd;
#pragma unroll
        for (int o = 16; o; o >>= 1) ss += __shfl_xor_sync(0xffffffffu, ss, o);
        float rr = rsqrtf(ss * (1.f / 128.f) + 1e-6f);
        xa *= rr * w[lane];
        xb *= rr * w[lane + 32];
        xc *= rr * w[lane + 64];
        xd *= rr * w[lane + 96];

        float pos = (float)positions[tok];
        float inv1 = powf(1.0e6f, -(float)lane * (1.f / 64.f));
        float inv2 = powf(1.0e6f, -(float)(lane + 32) * (1.f / 64.f));
        float s1, c1, s2, c2;
        sincosf(pos * inv1, &s1, &c1);
        sincosf(pos * inv2, &s2, &c2);

        float y0 = xa * c1 - xc * s1;   // col lane
        float y1 = xb * c2 - xd * s2;   // col lane+32
        float y2 = xc * c1 + xa * s1;   // col lane+64
        float y3 = xd * c2 + xb * s2;   // col lane+96
        if (isQ) { y0 *= QSCALE; y1 *= QSCALE; y2 *= QSCALE; y3 *= QSCALE; }

        __nv_bfloat16 *dh, *dl;
        if (isQ) {
            size_t o = ((size_t)tok * NH + gidx) * HD;
            dh = g_qh + o; dl = g_ql + o;
        } else {
            size_t o = ((size_t)tok * NKV + (gidx - NH)) * HD;
            dh = g_kh + o; dl = g_kl + o;
        }
        sstore(dh, dl, lane, y0);
        sstore(dh, dl, lane + 32, y1);
        sstore(dh, dl, lane + 64, y2);
        sstore(dh, dl, lane + 96, y3);
    } else {
        int vh = gidx - NH - NKV;
        const float* x = g_qkv + (size_t)tok * QKV_DIM + V_OFF + vh * HD;
        size_t o = ((size_t)tok * NKV + vh) * HD;
#pragma unroll
        for (int j = 0; j < 4; j++) {
            int c = lane + 32 * j;
            sstore(g_vh + o, g_vl + o, c, x[c]);
        }
    }
}

// ------------------------------------------------------------
// Tensor-core causal flash attention, pre-split bf16 operands
// CTA = 128 q rows x 1 head, 8 warps; KV tiles of 64, cp.async double buffer
// ------------------------------------------------------------
#define FA_BM 128
#define FA_BN 64
#define FROW 272                 // 128 bf16 = 256B + 16 pad
#define QTILE (128 * FROW)       // 34816
#define KVTILE (64 * FROW)       // 17408
#define SQH 0
#define SQL QTILE
#define SKV (2 * QTILE)
#define KVSTAGE (4 * KVTILE)     // Kh, Kl, Vh, Vl
#define FA_SMEM (2 * QTILE + 2 * KVSTAGE)   // 208896

__global__ __launch_bounds__(256, 1) void attn_tc()
{
    extern __shared__ char smc[];
    uint32_t smb = smem_u32(smc);
    int tid = threadIdx.x;
    int lane = tid & 31;
    int wid = tid >> 5;
    int qtile = blockIdx.x;
    int h = blockIdx.y;
    int b = blockIdx.z;
    int kvh = h >> 3;
    int q0 = qtile * FA_BM;

    int g8 = lane >> 3, r8 = lane & 7;
    uint32_t a_off = (uint32_t)(((g8 & 1) * 8 + r8) * FROW + (g8 >> 1) * 16);
    uint32_t b_off = (uint32_t)(((g8 >> 1) * 8 + r8) * FROW + (g8 & 1) * 16);

    // Q tile via cp.async (pre-scaled, pre-split)
#pragma unroll
    for (int i = 0; i < 8; i++) {
        int c = tid + i * 256;            // 2048 chunks: 128 rows x 16
        int row = c >> 4, c4 = c & 15;
        size_t src = ((size_t)(b * SS + q0 + row) * NH + h) * HD + c4 * 8;
        uint32_t doff = (uint32_t)(row * FROW + c4 * 16);
        cp16(smb + SQH + doff, g_qh + src);
        cp16(smb + SQL + doff, g_ql + src);
    }

    auto kvload = [&](int t, int kbuf) {
        uint32_t base = smb + SKV + kbuf * KVSTAGE;
#pragma unroll
        for (int i = 0; i < 4; i++) {
            int c = tid + i * 256;        // 1024 chunks: 64 rows x 16
            int row = c >> 4, c4 = c & 15;
            size_t src = ((size_t)(b * SS + t * FA_BN + row) * NKV + kvh) * HD + c4 * 8;
            uint32_t doff = (uint32_t)(row * FROW + c4 * 16);
            cp16(base + doff, g_kh + src);
            cp16(base + KVTILE + doff, g_kl + src);
            cp16(base + 2 * KVTILE + doff, g_vh + src);
            cp16(base + 3 * KVTILE + doff, g_vl + src);
        }
    };

    kvload(0, 0);
    CP_COMMIT();

    float m0 = -1e30f, m1 = -1e30f, lsum0 = 0.f, lsum1 = 0.f;
    float co[16][4];
#pragma unroll
    for (int nf = 0; nf < 16; nf++)
#pragma unroll
        for (int e = 0; e < 4; e++) co[nf][e] = 0.f;

    int ntiles = 2 * qtile + 2;
    int kbuf = 0;
    for (int t = 0; t < ntiles; t++) {
        if (t + 1 < ntiles) {
            kvload(t + 1, kbuf ^ 1);
            CP_COMMIT();
            CP_WAIT1();
        } else {
            CP_WAIT0();
        }
        __syncthreads();

        int kv0 = t * FA_BN;
        bool skip = (kv0 > q0 + wid * 16 + 15);   // warp tile fully masked
        if (!skip) {
            uint32_t base = smb + SKV + kbuf * KVSTAGE;

            // ---- S = Q K^T (3-pass) ----
            float cs[4][2][4];
#pragma unroll
            for (int nb = 0; nb < 4; nb++)
#pragma unroll
                for (int f = 0; f < 2; f++)
#pragma unroll
                    for (int e = 0; e < 4; e++) cs[nb][f][e] = 0.f;

            uint32_t qrow = (uint32_t)(wid * 16) * FROW;
#pragma unroll
            for (int ks = 0; ks < 8; ks++) {
                uint32_t koff = (uint32_t)(ks * 32);
                uint32_t qh_[4], ql_[4];
                ldm4(smb + SQH + qrow + koff + a_off, qh_[0], qh_[1], qh_[2], qh_[3]);
                ldm4(smb + SQL + qrow + koff + a_off, ql_[0], ql_[1], ql_[2], ql_[3]);
#pragma unroll
                for (int nb = 0; nb < 4; nb++) {
                    uint32_t nboff = (uint32_t)(nb * 16) * FROW + koff;
                    uint32_t kh_[4], kl_[4];
                    ldm4(base + nboff + b_off, kh_[0], kh_[1], kh_[2], kh_[3]);
                    ldm4(base + KVTILE + nboff + b_off, kl_[0], kl_[1], kl_[2], kl_[3]);
                    mma_bf16(cs[nb][0], qh_, kh_);
                    mma_bf16(cs[nb][0], qh_, kl_);
                    mma_bf16(cs[nb][0], ql_, kh_);
                    mma_bf16(cs[nb][1], qh_, kh_ + 2);
                    mma_bf16(cs[nb][1], qh_, kl_ + 2);
                    mma_bf16(cs[nb][1], ql_, kh_ + 2);
                }
            }

            // ---- causal mask (only the top-two kv tiles can clip) ----
            if (t >= 2 * qtile) {
                int row0 = q0 + wid * 16 + (lane >> 2);
#pragma unroll
                for (int nb = 0; nb < 4; nb++)
#pragma unroll
                    for (int f = 0; f < 2; f++)
#pragma unroll
                        for (int e = 0; e < 4; e++) {
                            int col = kv0 + nb * 16 + f * 8 + 2 * (lane & 3) + (e & 1);
                            int row = row0 + ((e >> 1) ? 8 : 0);
                            if (col > row) cs[nb][f][e] = -1e30f;
                        }
            }

            // ---- online softmax ----
            float mt0 = -1e30f, mt1 = -1e30f;
#pragma unroll
            for (int nb = 0; nb < 4; nb++)
#pragma unroll
                for (int f = 0; f < 2; f++) {
                    mt0 = fmaxf(mt0, fmaxf(cs[nb][f][0], cs[nb][f][1]));
                    mt1 = fmaxf(mt1, fmaxf(cs[nb][f][2], cs[nb][f][3]));
                }
            mt0 = fmaxf(mt0, __shfl_xor_sync(0xffffffffu, mt0, 1));
            mt0 = fmaxf(mt0, __shfl_xor_sync(0xffffffffu, mt0, 2));
            mt1 = fmaxf(mt1, __shfl_xor_sync(0xffffffffu, mt1, 1));
            mt1 = fmaxf(mt1, __shfl_xor_sync(0xffffffffu, mt1, 2));
            float mn0 = fmaxf(m0, mt0);
            float mn1 = fmaxf(m1, mt1);
            float corr0 = __expf(m0 - mn0);
            float corr1 = __expf(m1 - mn1);
            float ps0 = 0.f, ps1 = 0.f;
#pragma unroll
            for (int nb = 0; nb < 4; nb++)
#pragma unroll
                for (int f = 0; f < 2; f++) {
                    cs[nb][f][0] = __expf(cs[nb][f][0] - mn0);
                    cs[nb][f][1] = __expf(cs[nb][f][1] - mn0);
                    cs[nb][f][2] = __expf(cs[nb][f][2] - mn1);
                    cs[nb][f][3] = __expf(cs[nb][f][3] - mn1);
                    ps0 += cs[nb][f][0] + cs[nb][f][1];
                    ps1 += cs[nb][f][2] + cs[nb][f][3];
                }
            ps0 += __shfl_xor_sync(0xffffffffu, ps0, 1);
            ps0 += __shfl_xor_sync(0xffffffffu, ps0, 2);
            ps1 += __shfl_xor_sync(0xffffffffu, ps1, 1);
            ps1 += __shfl_xor_sync(0xffffffffu, ps1, 2);
            lsum0 = lsum0 * corr0 + ps0;
            lsum1 = lsum1 * corr1 + ps1;
            m0 = mn0; m1 = mn1;
#pragma unroll
            for (int nf = 0; nf < 16; nf++) {
                co[nf][0] *= corr0; co[nf][1] *= corr0;
                co[nf][2] *= corr1; co[nf][3] *= corr1;
            }

            // ---- O += P V (3-pass), V via ldmatrix.trans ----
#pragma unroll
            for (int ks = 0; ks < 4; ks++) {
                uint32_t ph[4], pl[4];
                split2(cs[ks][0][0], cs[ks][0][1], ph[0], pl[0]);
                split2(cs[ks][0][2], cs[ks][0][3], ph[1], pl[1]);
                split2(cs[ks][1][0], cs[ks][1][1], ph[2], pl[2]);
                split2(cs[ks][1][2], cs[ks][1][3], ph[3], pl[3]);
                uint32_t krow = (uint32_t)(ks * 16) * FROW;
#pragma unroll
                for (int db = 0; db < 8; db++) {
                    uint32_t doff = krow + (uint32_t)(db * 32) + a_off;
                    uint32_t vh_[4], vl_[4];
                    ldm4t(base + 2 * KVTILE + doff, vh_[0], vh_[1], vh_[2], vh_[3]);
                    ldm4t(base + 3 * KVTILE + doff, vl_[0], vl_[1], vl_[2], vl_[3]);
                    mma_bf16(co[2 * db], ph, vh_);
                    mma_bf16(co[2 * db], ph, vl_);
                    mma_bf16(co[2 * db], pl, vh_);
                    mma_bf16(co[2 * db + 1], ph, vh_ + 2);
                    mma_bf16(co[2 * db + 1], ph, vl_ + 2);
                    mma_bf16(co[2 * db + 1], pl, vh_ + 2);
                }
            }
        }
        __syncthreads();
        kbuf ^= 1;
    }

    // epilogue: normalize and write pre-split bf16 for O projection
    float inv0 = 1.f / lsum0;
    float inv1 = 1.f / lsum1;
    int row0 = b * SS + q0 + wid * 16 + (lane >> 2);
    int colb = h * HD + 2 * (lane & 3);
#pragma unroll
    for (int nf = 0; nf < 16; nf++) {
        int col = colb + nf * 8;
        uint32_t hh, ll;
        split2(co[nf][0] * inv0, co[nf][1] * inv0, hh, ll);
        *(uint32_t*)(g_ah + (size_t)row0 * ATTN_DIM + col) = hh;
        *(uint32_t*)(g_al + (size_t)row0 * ATTN_DIM + col) = ll;
        split2(co[nf][2] * inv1, co[nf][3] * inv1, hh, ll);
        *(uint32_t*)(g_ah + (size_t)(row0 + 8) * ATTN_DIM + col) = hh;
        *(uint32_t*)(g_al + (size_t)(row0 + 8) * ATTN_DIM + col) = ll;
    }
}

// ------------------------------------------------------------
// launch
// ------------------------------------------------------------
extern "C" void kernel_launch(void* const* d_in, const int* in_sizes, int n_in,
                              void* d_out, int out_size)
{
    const float* hidden    = (const float*)d_in[0];
    const int*   positions = (const int*)d_in[1];
    const float* w_qkv     = (const float*)d_in[2];
    const float* w_o       = (const float*)d_in[3];
    const float* q_norm_w  = (const float*)d_in[4];
    const float* k_norm_w  = (const float*)d_in[5];
    float* out = (float*)d_out;

    float* qkv_buf;
    __nv_bfloat16 *hh, *hl, *wqh, *wql, *woh, *wol, *ah, *al;
    cudaGetSymbolAddress((void**)&qkv_buf, g_qkv);
    cudaGetSymbolAddress((void**)&hh, g_hh);
    cudaGetSymbolAddress((void**)&hl, g_hl);
    cudaGetSymbolAddress((void**)&wqh, g_wqh);
    cudaGetSymbolAddress((void**)&wql, g_wql);
    cudaGetSymbolAddress((void**)&woh, g_woh);
    cudaGetSymbolAddress((void**)&wol, g_wol);
    cudaGetSymbolAddress((void**)&ah, g_ah);
    cudaGetSymbolAddress((void**)&al, g_al);

    cudaFuncSetAttribute(gemm_tc,
                         cudaFuncAttributeMaxDynamicSharedMemorySize, GEMM_SMEM);
    cudaFuncSetAttribute(attn_tc,
                         cudaFuncAttributeMaxDynamicSharedMemorySize, FA_SMEM);

    // 0) pre-split fp32 operands to bf16 hi/lo
    {
        int n4h = BTOK * HIDDEN / 4;
        split_f32<<<(n4h + 255) / 256, 256>>>(hidden, hh, hl, n4h);
        int n4q = QKV_DIM * HIDDEN / 4;
        split_f32<<<(n4q + 255) / 256, 256>>>(w_qkv, wqh, wql, n4q);
        int n4o = HIDDEN * ATTN_DIM / 4;
        split_f32<<<(n4o + 255) / 256, 256>>>(w_o, woh, wol, n4o);
    }

    // 1) QKV projection -> fp32 g_qkv
    gemm_tc<<<dim3(QKV_DIM / 128, BTOK / 128), 256, GEMM_SMEM>>>(
        hh, hl, wqh, wql, qkv_buf, BTOK, QKV_DIM, HIDDEN);

    // 2) RMSNorm + RoPE + split (Q scaled); V split
    {
        int total_warps = BTOK * (NH + 2 * NKV);
        norm_rope_split<<<(total_warps + 7) / 8, 256>>>(positions, q_norm_w, k_norm_w);
    }

    // 3) causal GQA flash attention -> split bf16 g_ah/g_al
    attn_tc<<<dim3(SS / FA_BM, NH, BB), 256, FA_SMEM>>>();

    // 4) O projection -> fp32 out
    gemm_tc<<<dim3(HIDDEN / 128, BTOK / 128), 256, GEMM_SMEM>>>(
        ah, al, woh, wol, out, BTOK, HIDDEN, ATTN_DIM);
}

// round 6
// speedup vs baseline: 4.4989x; 1.3580x over previous
#include <cuda_runtime.h>
#include <cuda_fp16.h>
#include <cstdint>
#include <math.h>

// Problem constants
#define HIDDEN   2048
#define NH       32
#define NKV      4
#define HD       128
#define BB       2
#define SS       2048
#define BTOK     (BB * SS)              // 4096
#define QKV_DIM  ((NH + 2 * NKV) * HD)  // 5120
#define ATTN_DIM (NH * HD)              // 4096
#define K_OFF    (NH * HD)              // 4096
#define V_OFF    (NH * HD + NKV * HD)   // 4608
#define QSCALE   0.08838834764831843f   // 1/sqrt(128)

// ------------------------------------------------------------
// Scratch (device globals; no runtime allocation allowed)
// ------------------------------------------------------------
__device__ float g_qkv[(size_t)BTOK * QKV_DIM];              // fp32 qkv proj
__device__ __half g_hh[(size_t)BTOK * HIDDEN];               // hidden hi/lo (fp16 split)
__device__ __half g_hl[(size_t)BTOK * HIDDEN];
__device__ __half g_wq[(size_t)QKV_DIM * HIDDEN];            // w_qkv fp16
__device__ __half g_wo[(size_t)HIDDEN * ATTN_DIM];           // w_o fp16
__device__ __half g_qh[(size_t)BTOK * NH * HD];              // Q hi/lo (normed+roped+scaled)
__device__ __half g_ql[(size_t)BTOK * NH * HD];
__device__ __half g_kh[(size_t)BTOK * NKV * HD];             // K fp16 (normed+roped)
__device__ __half g_vh[(size_t)BTOK * NKV * HD];             // V fp16
__device__ __half g_ah[(size_t)BTOK * ATTN_DIM];             // attn out hi/lo
__device__ __half g_al[(size_t)BTOK * ATTN_DIM];

// ------------------------------------------------------------
// helpers
// ------------------------------------------------------------
__device__ __forceinline__ uint32_t smem_u32(const void* p) {
    uint32_t a;
    asm("{ .reg .u64 t; cvta.to.shared.u64 t, %1; cvt.u32.u64 %0, t; }" : "=r"(a) : "l"(p));
    return a;
}
// split (x,y) into packed f16x2 high + low parts (lo lane = x, hi lane = y)
__device__ __forceinline__ void split2h(float x, float y, uint32_t& h, uint32_t& l) {
    asm("cvt.rn.f16x2.f32 %0, %1, %2;" : "=r"(h) : "f"(y), "f"(x));
    float hx = __half2float(__ushort_as_half((unsigned short)(h & 0xffffu)));
    float hy = __half2float(__ushort_as_half((unsigned short)(h >> 16)));
    float rx = x - hx, ry = y - hy;
    asm("cvt.rn.f16x2.f32 %0, %1, %2;" : "=r"(l) : "f"(ry), "f"(rx));
}
// pack (x,y) to f16x2 (round-to-nearest)
__device__ __forceinline__ uint32_t pack2h(float x, float y) {
    uint32_t h;
    asm("cvt.rn.f16x2.f32 %0, %1, %2;" : "=r"(h) : "f"(y), "f"(x));
    return h;
}
__device__ __forceinline__ void ldm4(uint32_t addr, uint32_t& r0, uint32_t& r1,
                                     uint32_t& r2, uint32_t& r3) {
    asm volatile("ldmatrix.sync.aligned.m8n8.x4.shared.b16 {%0,%1,%2,%3}, [%4];"
                 : "=r"(r0), "=r"(r1), "=r"(r2), "=r"(r3) : "r"(addr));
}
__device__ __forceinline__ void ldm4t(uint32_t addr, uint32_t& r0, uint32_t& r1,
                                      uint32_t& r2, uint32_t& r3) {
    asm volatile("ldmatrix.sync.aligned.m8n8.x4.trans.shared.b16 {%0,%1,%2,%3}, [%4];"
                 : "=r"(r0), "=r"(r1), "=r"(r2), "=r"(r3) : "r"(addr));
}
__device__ __forceinline__ void mma_f16(float* c, const uint32_t* a, const uint32_t* b) {
    asm volatile(
        "mma.sync.aligned.m16n8k16.row.col.f32.f16.f16.f32 "
        "{%0,%1,%2,%3}, {%4,%5,%6,%7}, {%8,%9}, {%0,%1,%2,%3};"
        : "+f"(c[0]), "+f"(c[1]), "+f"(c[2]), "+f"(c[3])
        : "r"(a[0]), "r"(a[1]), "r"(a[2]), "r"(a[3]), "r"(b[0]), "r"(b[1]));
}
__device__ __forceinline__ void cp16(uint32_t dst, const void* src) {
    asm volatile("cp.async.cg.shared.global [%0], [%1], 16;" :: "r"(dst), "l"(src));
}
#define CP_COMMIT() asm volatile("cp.async.commit_group;" ::: "memory")
#define CP_WAIT0()  asm volatile("cp.async.wait_group 0;" ::: "memory")
#define CP_WAIT1()  asm volatile("cp.async.wait_group 1;" ::: "memory")

// ------------------------------------------------------------
// conversion passes
// ------------------------------------------------------------
__global__ __launch_bounds__(256) void split_f32(
    const float* __restrict__ x, __half* __restrict__ h,
    __half* __restrict__ l, int n4)
{
    int i = blockIdx.x * blockDim.x + threadIdx.x;
    if (i >= n4) return;
    float4 v = ((const float4*)x)[i];
    uint32_t h0, l0, h1, l1;
    split2h(v.x, v.y, h0, l0);
    split2h(v.z, v.w, h1, l1);
    ((uint2*)h)[i] = make_uint2(h0, h1);
    ((uint2*)l)[i] = make_uint2(l0, l1);
}
__global__ __launch_bounds__(256) void cvt_f32(
    const float* __restrict__ x, __half* __restrict__ h, int n4)
{
    int i = blockIdx.x * blockDim.x + threadIdx.x;
    if (i >= n4) return;
    float4 v = ((const float4*)x)[i];
    ((uint2*)h)[i] = make_uint2(pack2h(v.x, v.y), pack2h(v.z, v.w));
}

// ------------------------------------------------------------
// fp16-split 2-pass tensor-core GEMM (NT): C = A[M,K] * B[N,K]^T
// A split hi/lo, B single fp16. 128x128x32 tile, 8 warps, 2 CTAs/SM
// ------------------------------------------------------------
#define SROW 80                        // 32 f16 = 64B + 16 pad
#define TILE_B (128 * SROW)            // 10240
#define STAGE_B (3 * TILE_B)           // 30720 (Ah, Al, B)
#define GEMM_SMEM (2 * STAGE_B)        // 61440

__global__ __launch_bounds__(256, 2) void gemm_tc(
    const __half* __restrict__ Ah, const __half* __restrict__ Al,
    const __half* __restrict__ B,
    float* __restrict__ C, int M, int N, int K)
{
    extern __shared__ char smc[];
    uint32_t smb = smem_u32(smc);
    int tid = threadIdx.x, lane = tid & 31, wid = tid >> 5;
    int warpM = wid >> 2, warpN = wid & 3;
    int bm = blockIdx.y * 128, bn = blockIdx.x * 128;

    int g8 = lane >> 3, r8 = lane & 7;
    uint32_t a_off = (uint32_t)(((g8 & 1) * 8 + r8) * SROW + (g8 >> 1) * 16);
    uint32_t b_off = (uint32_t)(((g8 >> 1) * 8 + r8) * SROW + (g8 & 1) * 16);

    auto stage_load = [&](int kb, int buf) {
        uint32_t base = smb + buf * STAGE_B;
        int k0 = kb * 32;
#pragma unroll
        for (int i = 0; i < 6; i++) {
            int c = tid + i * 256;             // 1536 chunks = 3 tiles x 512
            int which = c >> 9;                // 0=Ah 1=Al 2=B
            int idx = c & 511;
            int row = idx >> 2, c4 = idx & 3;
            uint32_t doff = (uint32_t)(which * TILE_B + row * SROW + c4 * 16);
            const __half* src;
            if (which == 0)      src = Ah + (size_t)(bm + row) * K + k0 + c4 * 8;
            else if (which == 1) src = Al + (size_t)(bm + row) * K + k0 + c4 * 8;
            else                 src = B + (size_t)(bn + row) * K + k0 + c4 * 8;
            cp16(base + doff, src);
        }
    };

    float acc[4][4][4];
#pragma unroll
    for (int mt = 0; mt < 4; mt++)
#pragma unroll
        for (int nt = 0; nt < 4; nt++)
#pragma unroll
            for (int e = 0; e < 4; e++) acc[mt][nt][e] = 0.f;

    stage_load(0, 0);
    CP_COMMIT();

    int nkb = K / 32, buf = 0;
    for (int kb = 0; kb < nkb; kb++) {
        if (kb + 1 < nkb) {
            stage_load(kb + 1, buf ^ 1);
            CP_COMMIT();
            CP_WAIT1();
        } else {
            CP_WAIT0();
        }
        __syncthreads();

        uint32_t base = smb + buf * STAGE_B;
        uint32_t ah_b = base + (uint32_t)(warpM * 64) * SROW + a_off;
        uint32_t al_b = ah_b + TILE_B;
        uint32_t b_b = base + 2 * TILE_B + (uint32_t)(warpN * 32) * SROW + b_off;

#pragma unroll
        for (int ks = 0; ks < 2; ks++) {
            uint32_t koff = (uint32_t)(ks * 32);
            uint32_t Bf[4][2];
#pragma unroll
            for (int ntp = 0; ntp < 2; ntp++) {
                uint32_t r0, r1, r2, r3;
                ldm4(b_b + (uint32_t)(ntp * 16 * SROW) + koff, r0, r1, r2, r3);
                Bf[2 * ntp][0] = r0; Bf[2 * ntp][1] = r1;
                Bf[2 * ntp + 1][0] = r2; Bf[2 * ntp + 1][1] = r3;
            }
#pragma unroll
            for (int mt = 0; mt < 4; mt++) {
                uint32_t A_h[4], A_l[4];
                ldm4(ah_b + (uint32_t)(mt * 16 * SROW) + koff, A_h[0], A_h[1], A_h[2], A_h[3]);
                ldm4(al_b + (uint32_t)(mt * 16 * SROW) + koff, A_l[0], A_l[1], A_l[2], A_l[3]);
#pragma unroll
                for (int nt = 0; nt < 4; nt++) {
                    mma_f16(acc[mt][nt], A_h, Bf[nt]);
                    mma_f16(acc[mt][nt], A_l, Bf[nt]);
                }
            }
        }
        __syncthreads();
        buf ^= 1;
    }

    int erow = lane >> 2;
    int ecol = (lane & 3) * 2;
#pragma unroll
    for (int mt = 0; mt < 4; mt++) {
#pragma unroll
        for (int nt = 0; nt < 4; nt++) {
            int row0 = bm + warpM * 64 + mt * 16 + erow;
            int col = bn + warpN * 32 + nt * 8 + ecol;
            *(float2*)(C + (size_t)row0 * N + col) = make_float2(acc[mt][nt][0], acc[mt][nt][1]);
            *(float2*)(C + (size_t)(row0 + 8) * N + col) = make_float2(acc[mt][nt][2], acc[mt][nt][3]);
        }
    }
}

// ------------------------------------------------------------
// Fused RMSNorm + RoPE + convert: Q -> fp16 hi/lo (pre-scaled),
// K -> fp16, V -> fp16. One warp per (token, group).
// ------------------------------------------------------------
__global__ __launch_bounds__(256) void norm_rope_split(
    const int* __restrict__ positions,
    const float* __restrict__ qw, const float* __restrict__ kw)
{
    const int NG = NH + 2 * NKV;  // 40
    int warp = (blockIdx.x * blockDim.x + threadIdx.x) >> 5;
    int lane = threadIdx.x & 31;
    if (warp >= BTOK * NG) return;
    int gidx = warp % NG;
    int tok = warp / NG;

    if (gidx < NH + NKV) {
        bool isQ = gidx < NH;
        const float* w = isQ ? qw : kw;
        int off = isQ ? gidx * HD : K_OFF + (gidx - NH) * HD;
        const float* x = g_qkv + (size_t)tok * QKV_DIM + off;

        float xa = x[lane], xb = x[lane + 32], xc = x[lane + 64], xd = x[lane + 96];
        float ss = xa * xa + xb * xb + xc * xc + xd * xd;
#pragma unroll
        for (int o = 16; o; o >>= 1) ss += __shfl_xor_sync(0xffffffffu, ss, o);
        float rr = rsqrtf(ss * (1.f / 128.f) + 1e-6f);
        xa *= rr * w[lane];
        xb *= rr * w[lane + 32];
        xc *= rr * w[lane + 64];
        xd *= rr * w[lane + 96];

        float pos = (float)positions[tok];
        float inv1 = powf(1.0e6f, -(float)lane * (1.f / 64.f));
        float inv2 = powf(1.0e6f, -(float)(lane + 32) * (1.f / 64.f));
        float s1, c1, s2, c2;
        sincosf(pos * inv1, &s1, &c1);
        sincosf(pos * inv2, &s2, &c2);

        float y0 = xa * c1 - xc * s1;   // col lane
        float y1 = xb * c2 - xd * s2;   // col lane+32
        float y2 = xc * c1 + xa * s1;   // col lane+64
        float y3 = xd * c2 + xb * s2;   // col lane+96

        if (isQ) {
            y0 *= QSCALE; y1 *= QSCALE; y2 *= QSCALE; y3 *= QSCALE;
            size_t o = ((size_t)tok * NH + gidx) * HD;
#pragma unroll
            for (int j = 0; j < 4; j++) {
                float v = (j == 0) ? y0 : (j == 1) ? y1 : (j == 2) ? y2 : y3;
                int cc = lane + 32 * j;
                __half hv = __float2half_rn(v);
                g_qh[o + cc] = hv;
                g_ql[o + cc] = __float2half_rn(v - __half2float(hv));
            }
        } else {
            size_t o = ((size_t)tok * NKV + (gidx - NH)) * HD;
            g_kh[o + lane]      = __float2half_rn(y0);
            g_kh[o + lane + 32] = __float2half_rn(y1);
            g_kh[o + lane + 64] = __float2half_rn(y2);
            g_kh[o + lane + 96] = __float2half_rn(y3);
        }
    } else {
        int vh = gidx - NH - NKV;
        const float* x = g_qkv + (size_t)tok * QKV_DIM + V_OFF + vh * HD;
        size_t o = ((size_t)tok * NKV + vh) * HD;
#pragma unroll
        for (int j = 0; j < 4; j++) {
            int c = lane + 32 * j;
            g_vh[o + c] = __float2half_rn(x[c]);
        }
    }
}

// ------------------------------------------------------------
// Tensor-core causal flash attention, fp16 2-pass
// CTA = 128 q rows x 1 head, 8 warps; KV tiles of 64, cp.async double buffer
// ------------------------------------------------------------
#define FA_BM 128
#define FA_BN 64
#define FROW 272                 // 128 f16 = 256B + 16 pad
#define QTILE (128 * FROW)       // 34816
#define KVTILE (64 * FROW)       // 17408
#define SQH 0
#define SQL QTILE
#define SKV (2 * QTILE)
#define KVSTAGE (2 * KVTILE)     // Kh, Vh
#define FA_SMEM (2 * QTILE + 2 * KVSTAGE)   // 139264

__global__ __launch_bounds__(256, 1) void attn_tc()
{
    extern __shared__ char smc[];
    uint32_t smb = smem_u32(smc);
    int tid = threadIdx.x;
    int lane = tid & 31;
    int wid = tid >> 5;
    int qtile = blockIdx.x;
    int h = blockIdx.y;
    int b = blockIdx.z;
    int kvh = h >> 3;
    int q0 = qtile * FA_BM;

    int g8 = lane >> 3, r8 = lane & 7;
    uint32_t a_off = (uint32_t)(((g8 & 1) * 8 + r8) * FROW + (g8 >> 1) * 16);
    uint32_t b_off = (uint32_t)(((g8 >> 1) * 8 + r8) * FROW + (g8 & 1) * 16);

    // Q tile via cp.async (pre-scaled, pre-split)
#pragma unroll
    for (int i = 0; i < 8; i++) {
        int c = tid + i * 256;            // 2048 chunks: 128 rows x 16
        int row = c >> 4, c4 = c & 15;
        size_t src = ((size_t)(b * SS + q0 + row) * NH + h) * HD + c4 * 8;
        uint32_t doff = (uint32_t)(row * FROW + c4 * 16);
        cp16(smb + SQH + doff, g_qh + src);
        cp16(smb + SQL + doff, g_ql + src);
    }

    auto kvload = [&](int t, int kbuf) {
        uint32_t base = smb + SKV + kbuf * KVSTAGE;
#pragma unroll
        for (int i = 0; i < 4; i++) {
            int c = tid + i * 256;        // 1024 chunks: 64 rows x 16
            int row = c >> 4, c4 = c & 15;
            size_t src = ((size_t)(b * SS + t * FA_BN + row) * NKV + kvh) * HD + c4 * 8;
            uint32_t doff = (uint32_t)(row * FROW + c4 * 16);
            cp16(base + doff, g_kh + src);
            cp16(base + KVTILE + doff, g_vh + src);
        }
    };

    kvload(0, 0);
    CP_COMMIT();

    float m0 = -1e30f, m1 = -1e30f, lsum0 = 0.f, lsum1 = 0.f;
    float co[16][4];
#pragma unroll
    for (int nf = 0; nf < 16; nf++)
#pragma unroll
        for (int e = 0; e < 4; e++) co[nf][e] = 0.f;

    int ntiles = 2 * qtile + 2;
    int kbuf = 0;
    for (int t = 0; t < ntiles; t++) {
        if (t + 1 < ntiles) {
            kvload(t + 1, kbuf ^ 1);
            CP_COMMIT();
            CP_WAIT1();
        } else {
            CP_WAIT0();
        }
        __syncthreads();

        int kv0 = t * FA_BN;
        bool skip = (kv0 > q0 + wid * 16 + 15);   // warp tile fully masked
        if (!skip) {
            uint32_t base = smb + SKV + kbuf * KVSTAGE;

            // ---- S = Q K^T (2-pass: Qh + Ql vs fp16 K) ----
            float cs[4][2][4];
#pragma unroll
            for (int nb = 0; nb < 4; nb++)
#pragma unroll
                for (int f = 0; f < 2; f++)
#pragma unroll
                    for (int e = 0; e < 4; e++) cs[nb][f][e] = 0.f;

            uint32_t qrow = (uint32_t)(wid * 16) * FROW;
#pragma unroll
            for (int ks = 0; ks < 8; ks++) {
                uint32_t koff = (uint32_t)(ks * 32);
                uint32_t qh_[4], ql_[4];
                ldm4(smb + SQH + qrow + koff + a_off, qh_[0], qh_[1], qh_[2], qh_[3]);
                ldm4(smb + SQL + qrow + koff + a_off, ql_[0], ql_[1], ql_[2], ql_[3]);
#pragma unroll
                for (int nb = 0; nb < 4; nb++) {
                    uint32_t nboff = (uint32_t)(nb * 16) * FROW + koff;
                    uint32_t kf[4];
                    ldm4(base + nboff + b_off, kf[0], kf[1], kf[2], kf[3]);
                    mma_f16(cs[nb][0], qh_, kf);
                    mma_f16(cs[nb][0], ql_, kf);
                    mma_f16(cs[nb][1], qh_, kf + 2);
                    mma_f16(cs[nb][1], ql_, kf + 2);
                }
            }

            // ---- causal mask (only top-two kv tiles can clip) ----
            if (t >= 2 * qtile) {
                int row0 = q0 + wid * 16 + (lane >> 2);
#pragma unroll
                for (int nb = 0; nb < 4; nb++)
#pragma unroll
                    for (int f = 0; f < 2; f++)
#pragma unroll
                        for (int e = 0; e < 4; e++) {
                            int col = kv0 + nb * 16 + f * 8 + 2 * (lane & 3) + (e & 1);
                            int row = row0 + ((e >> 1) ? 8 : 0);
                            if (col > row) cs[nb][f][e] = -1e30f;
                        }
            }

            // ---- online softmax ----
            float mt0 = -1e30f, mt1 = -1e30f;
#pragma unroll
            for (int nb = 0; nb < 4; nb++)
#pragma unroll
                for (int f = 0; f < 2; f++) {
                    mt0 = fmaxf(mt0, fmaxf(cs[nb][f][0], cs[nb][f][1]));
                    mt1 = fmaxf(mt1, fmaxf(cs[nb][f][2], cs[nb][f][3]));
                }
            mt0 = fmaxf(mt0, __shfl_xor_sync(0xffffffffu, mt0, 1));
            mt0 = fmaxf(mt0, __shfl_xor_sync(0xffffffffu, mt0, 2));
            mt1 = fmaxf(mt1, __shfl_xor_sync(0xffffffffu, mt1, 1));
            mt1 = fmaxf(mt1, __shfl_xor_sync(0xffffffffu, mt1, 2));
            float mn0 = fmaxf(m0, mt0);
            float mn1 = fmaxf(m1, mt1);
            float corr0 = __expf(m0 - mn0);
            float corr1 = __expf(m1 - mn1);
            float ps0 = 0.f, ps1 = 0.f;
#pragma unroll
            for (int nb = 0; nb < 4; nb++)
#pragma unroll
                for (int f = 0; f < 2; f++) {
                    cs[nb][f][0] = __expf(cs[nb][f][0] - mn0);
                    cs[nb][f][1] = __expf(cs[nb][f][1] - mn0);
                    cs[nb][f][2] = __expf(cs[nb][f][2] - mn1);
                    cs[nb][f][3] = __expf(cs[nb][f][3] - mn1);
                    ps0 += cs[nb][f][0] + cs[nb][f][1];
                    ps1 += cs[nb][f][2] + cs[nb][f][3];
                }
            ps0 += __shfl_xor_sync(0xffffffffu, ps0, 1);
            ps0 += __shfl_xor_sync(0xffffffffu, ps0, 2);
            ps1 += __shfl_xor_sync(0xffffffffu, ps1, 1);
            ps1 += __shfl_xor_sync(0xffffffffu, ps1, 2);
            lsum0 = lsum0 * corr0 + ps0;
            lsum1 = lsum1 * corr1 + ps1;
            m0 = mn0; m1 = mn1;
#pragma unroll
            for (int nf = 0; nf < 16; nf++) {
                co[nf][0] *= corr0; co[nf][1] *= corr0;
                co[nf][2] *= corr1; co[nf][3] *= corr1;
            }

            // ---- O += P V (2-pass: P split hi/lo vs fp16 V) ----
#pragma unroll
            for (int ks = 0; ks < 4; ks++) {
                uint32_t ph[4], pl[4];
                split2h(cs[ks][0][0], cs[ks][0][1], ph[0], pl[0]);
                split2h(cs[ks][0][2], cs[ks][0][3], ph[1], pl[1]);
                split2h(cs[ks][1][0], cs[ks][1][1], ph[2], pl[2]);
                split2h(cs[ks][1][2], cs[ks][1][3], ph[3], pl[3]);
                uint32_t krow = (uint32_t)(ks * 16) * FROW;
#pragma unroll
                for (int db = 0; db < 8; db++) {
                    uint32_t doff = krow + (uint32_t)(db * 32) + a_off;
                    uint32_t vf[4];
                    ldm4t(base + KVTILE + doff, vf[0], vf[1], vf[2], vf[3]);
                    mma_f16(co[2 * db], ph, vf);
                    mma_f16(co[2 * db], pl, vf);
                    mma_f16(co[2 * db + 1], ph, vf + 2);
                    mma_f16(co[2 * db + 1], pl, vf + 2);
                }
            }
        }
        __syncthreads();
        kbuf ^= 1;
    }

    // epilogue: normalize, write pre-split fp16 for O projection
    float inv0 = 1.f / lsum0;
    float inv1 = 1.f / lsum1;
    int row0 = b * SS + q0 + wid * 16 + (lane >> 2);
    int colb = h * HD + 2 * (lane & 3);
#pragma unroll
    for (int nf = 0; nf < 16; nf++) {
        int col = colb + nf * 8;
        uint32_t hh, ll;
        split2h(co[nf][0] * inv0, co[nf][1] * inv0, hh, ll);
        *(uint32_t*)(g_ah + (size_t)row0 * ATTN_DIM + col) = hh;
        *(uint32_t*)(g_al + (size_t)row0 * ATTN_DIM + col) = ll;
        split2h(co[nf][2] * inv1, co[nf][3] * inv1, hh, ll);
        *(uint32_t*)(g_ah + (size_t)(row0 + 8) * ATTN_DIM + col) = hh;
        *(uint32_t*)(g_al + (size_t)(row0 + 8) * ATTN_DIM + col) = ll;
    }
}

// ------------------------------------------------------------
// launch
// ------------------------------------------------------------
extern "C" void kernel_launch(void* const* d_in, const int* in_sizes, int n_in,
                              void* d_out, int out_size)
{
    const float* hidden    = (const float*)d_in[0];
    const int*   positions = (const int*)d_in[1];
    const float* w_qkv     = (const float*)d_in[2];
    const float* w_o       = (const float*)d_in[3];
    const float* q_norm_w  = (const float*)d_in[4];
    const float* k_norm_w  = (const float*)d_in[5];
    float* out = (float*)d_out;

    float* qkv_buf;
    __half *hh, *hl, *wq, *wo, *ah, *al;
    cudaGetSymbolAddress((void**)&qkv_buf, g_qkv);
    cudaGetSymbolAddress((void**)&hh, g_hh);
    cudaGetSymbolAddress((void**)&hl, g_hl);
    cudaGetSymbolAddress((void**)&wq, g_wq);
    cudaGetSymbolAddress((void**)&wo, g_wo);
    cudaGetSymbolAddress((void**)&ah, g_ah);
    cudaGetSymbolAddress((void**)&al, g_al);

    cudaFuncSetAttribute(gemm_tc,
                         cudaFuncAttributeMaxDynamicSharedMemorySize, GEMM_SMEM);
    cudaFuncSetAttribute(attn_tc,
                         cudaFuncAttributeMaxDynamicSharedMemorySize, FA_SMEM);

    // 0) convert inputs
    {
        int n4h = BTOK * HIDDEN / 4;
        split_f32<<<(n4h + 255) / 256, 256>>>(hidden, hh, hl, n4h);
        int n4q = QKV_DIM * HIDDEN / 4;
        cvt_f32<<<(n4q + 255) / 256, 256>>>(w_qkv, wq, n4q);
        int n4o = HIDDEN * ATTN_DIM / 4;
        cvt_f32<<<(n4o + 255) / 256, 256>>>(w_o, wo, n4o);
    }

    // 1) QKV projection -> fp32 g_qkv
    gemm_tc<<<dim3(QKV_DIM / 128, BTOK / 128), 256, GEMM_SMEM>>>(
        hh, hl, wq, qkv_buf, BTOK, QKV_DIM, HIDDEN);

    // 2) RMSNorm + RoPE + convert
    {
        int total_warps = BTOK * (NH + 2 * NKV);
        norm_rope_split<<<(total_warps + 7) / 8, 256>>>(positions, q_norm_w, k_norm_w);
    }

    // 3) causal GQA flash attention
    attn_tc<<<dim3(SS / FA_BM, NH, BB), 256, FA_SMEM>>>();

    // 4) O projection -> fp32 out
    gemm_tc<<<dim3(HIDDEN / 128, BTOK / 128), 256, GEMM_SMEM>>>(
        ah, al, wo, out, BTOK, HIDDEN, ATTN_DIM);
}

// round 7
// speedup vs baseline: 4.7127x; 1.0475x over previous
#include <cuda_runtime.h>
#include <cuda_fp16.h>
#include <cstdint>
#include <math.h>

// Problem constants
#define HIDDEN   2048
#define NH       32
#define NKV      4
#define HD       128
#define BB       2
#define SS       2048
#define BTOK     (BB * SS)              // 4096
#define QKV_DIM  ((NH + 2 * NKV) * HD)  // 5120
#define ATTN_DIM (NH * HD)              // 4096
#define K_OFF    (NH * HD)              // 4096
#define V_OFF    (NH * HD + NKV * HD)   // 4608
#define QSCALE   0.08838834764831843f   // 1/sqrt(128)

// ------------------------------------------------------------
// Scratch (device globals; no runtime allocation allowed)
// ------------------------------------------------------------
__device__ float g_qkv[(size_t)BTOK * QKV_DIM];              // fp32 qkv proj
__device__ __half g_hh[(size_t)BTOK * HIDDEN];               // hidden hi/lo (fp16 split)
__device__ __half g_hl[(size_t)BTOK * HIDDEN];
__device__ __half g_wq[(size_t)QKV_DIM * HIDDEN];            // w_qkv fp16
__device__ __half g_wo[(size_t)HIDDEN * ATTN_DIM];           // w_o fp16
__device__ __half g_qh[(size_t)BTOK * NH * HD];              // Q hi/lo (normed+roped+scaled)
__device__ __half g_ql[(size_t)BTOK * NH * HD];
__device__ __half g_kh[(size_t)BTOK * NKV * HD];             // K fp16 (normed+roped)
__device__ __half g_vh[(size_t)BTOK * NKV * HD];             // V fp16
__device__ __half g_ah[(size_t)BTOK * ATTN_DIM];             // attn out hi/lo
__device__ __half g_al[(size_t)BTOK * ATTN_DIM];

// ------------------------------------------------------------
// helpers
// ------------------------------------------------------------
__device__ __forceinline__ uint32_t smem_u32(const void* p) {
    uint32_t a;
    asm("{ .reg .u64 t; cvta.to.shared.u64 t, %1; cvt.u32.u64 %0, t; }" : "=r"(a) : "l"(p));
    return a;
}
// split (x,y) into packed f16x2 high + low parts (lo lane = x, hi lane = y)
__device__ __forceinline__ void split2h(float x, float y, uint32_t& h, uint32_t& l) {
    asm("cvt.rn.f16x2.f32 %0, %1, %2;" : "=r"(h) : "f"(y), "f"(x));
    float hx = __half2float(__ushort_as_half((unsigned short)(h & 0xffffu)));
    float hy = __half2float(__ushort_as_half((unsigned short)(h >> 16)));
    float rx = x - hx, ry = y - hy;
    asm("cvt.rn.f16x2.f32 %0, %1, %2;" : "=r"(l) : "f"(ry), "f"(rx));
}
// pack (x,y) to f16x2 (round-to-nearest)
__device__ __forceinline__ uint32_t pack2h(float x, float y) {
    uint32_t h;
    asm("cvt.rn.f16x2.f32 %0, %1, %2;" : "=r"(h) : "f"(y), "f"(x));
    return h;
}
__device__ __forceinline__ void ldm4(uint32_t addr, uint32_t& r0, uint32_t& r1,
                                     uint32_t& r2, uint32_t& r3) {
    asm volatile("ldmatrix.sync.aligned.m8n8.x4.shared.b16 {%0,%1,%2,%3}, [%4];"
                 : "=r"(r0), "=r"(r1), "=r"(r2), "=r"(r3) : "r"(addr));
}
__device__ __forceinline__ void ldm4t(uint32_t addr, uint32_t& r0, uint32_t& r1,
                                      uint32_t& r2, uint32_t& r3) {
    asm volatile("ldmatrix.sync.aligned.m8n8.x4.trans.shared.b16 {%0,%1,%2,%3}, [%4];"
                 : "=r"(r0), "=r"(r1), "=r"(r2), "=r"(r3) : "r"(addr));
}
__device__ __forceinline__ void mma_f16(float* c, const uint32_t* a, const uint32_t* b) {
    asm volatile(
        "mma.sync.aligned.m16n8k16.row.col.f32.f16.f16.f32 "
        "{%0,%1,%2,%3}, {%4,%5,%6,%7}, {%8,%9}, {%0,%1,%2,%3};"
        : "+f"(c[0]), "+f"(c[1]), "+f"(c[2]), "+f"(c[3])
        : "r"(a[0]), "r"(a[1]), "r"(a[2]), "r"(a[3]), "r"(b[0]), "r"(b[1]));
}
__device__ __forceinline__ void cp16(uint32_t dst, const void* src) {
    asm volatile("cp.async.cg.shared.global [%0], [%1], 16;" :: "r"(dst), "l"(src));
}
#define CP_COMMIT() asm volatile("cp.async.commit_group;" ::: "memory")
#define CP_WAIT0()  asm volatile("cp.async.wait_group 0;" ::: "memory")
#define CP_WAIT1()  asm volatile("cp.async.wait_group 1;" ::: "memory")

// ------------------------------------------------------------
// conversion passes
// ------------------------------------------------------------
__global__ __launch_bounds__(256) void split_f32(
    const float* __restrict__ x, __half* __restrict__ h,
    __half* __restrict__ l, int n4)
{
    int i = blockIdx.x * blockDim.x + threadIdx.x;
    if (i >= n4) return;
    float4 v = ((const float4*)x)[i];
    uint32_t h0, l0, h1, l1;
    split2h(v.x, v.y, h0, l0);
    split2h(v.z, v.w, h1, l1);
    ((uint2*)h)[i] = make_uint2(h0, h1);
    ((uint2*)l)[i] = make_uint2(l0, l1);
}
__global__ __launch_bounds__(256) void cvt_f32(
    const float* __restrict__ x, __half* __restrict__ h, int n4)
{
    int i = blockIdx.x * blockDim.x + threadIdx.x;
    if (i >= n4) return;
    float4 v = ((const float4*)x)[i];
    ((uint2*)h)[i] = make_uint2(pack2h(v.x, v.y), pack2h(v.z, v.w));
}

// ------------------------------------------------------------
// fp16-split 2-pass tensor-core GEMM (NT): C = A[M,K] * B[N,K]^T
// A split hi/lo, B single fp16. 128x128x32 tile, 4 warps (2x2),
// warp tile 64x64 -> 64 MMA / 12 ldmatrix per k-step. 2 CTAs/SM.
// ------------------------------------------------------------
#define SROW 80                        // 32 f16 = 64B + 16 pad
#define TILE_B (128 * SROW)            // 10240
#define STAGE_B (3 * TILE_B)           // 30720 (Ah, Al, B)
#define GEMM_SMEM (2 * STAGE_B)        // 61440

__global__ __launch_bounds__(128, 2) void gemm_tc(
    const __half* __restrict__ Ah, const __half* __restrict__ Al,
    const __half* __restrict__ B,
    float* __restrict__ C, int M, int N, int K)
{
    extern __shared__ char smc[];
    uint32_t smb = smem_u32(smc);
    int tid = threadIdx.x, lane = tid & 31, wid = tid >> 5;
    int warpM = wid >> 1, warpN = wid & 1;     // 2x2 warps, 64x64 each
    int bm = blockIdx.y * 128, bn = blockIdx.x * 128;

    int g8 = lane >> 3, r8 = lane & 7;
    uint32_t a_off = (uint32_t)(((g8 & 1) * 8 + r8) * SROW + (g8 >> 1) * 16);
    uint32_t b_off = (uint32_t)(((g8 >> 1) * 8 + r8) * SROW + (g8 & 1) * 16);

    auto stage_load = [&](int kb, int buf) {
        uint32_t base = smb + buf * STAGE_B;
        int k0 = kb * 32;
        // Ah tile: 512 chunks of 16B
#pragma unroll
        for (int i = 0; i < 4; i++) {
            int idx = i * 128 + tid;
            int row = idx >> 2, c4 = idx & 3;
            cp16(base + (uint32_t)(row * SROW + c4 * 16),
                 Ah + (size_t)(bm + row) * K + k0 + c4 * 8);
        }
        // Al tile
#pragma unroll
        for (int i = 0; i < 4; i++) {
            int idx = i * 128 + tid;
            int row = idx >> 2, c4 = idx & 3;
            cp16(base + TILE_B + (uint32_t)(row * SROW + c4 * 16),
                 Al + (size_t)(bm + row) * K + k0 + c4 * 8);
        }
        // B tile
#pragma unroll
        for (int i = 0; i < 4; i++) {
            int idx = i * 128 + tid;
            int row = idx >> 2, c4 = idx & 3;
            cp16(base + 2 * TILE_B + (uint32_t)(row * SROW + c4 * 16),
                 B + (size_t)(bn + row) * K + k0 + c4 * 8);
        }
    };

    float acc[4][8][4];
#pragma unroll
    for (int mt = 0; mt < 4; mt++)
#pragma unroll
        for (int nt = 0; nt < 8; nt++)
#pragma unroll
            for (int e = 0; e < 4; e++) acc[mt][nt][e] = 0.f;

    stage_load(0, 0);
    CP_COMMIT();

    int nkb = K / 32, buf = 0;
    for (int kb = 0; kb < nkb; kb++) {
        if (kb + 1 < nkb) {
            stage_load(kb + 1, buf ^ 1);
            CP_COMMIT();
            CP_WAIT1();
        } else {
            CP_WAIT0();
        }
        __syncthreads();

        uint32_t base = smb + buf * STAGE_B;
        uint32_t ah_b = base + (uint32_t)(warpM * 64) * SROW + a_off;
        uint32_t al_b = ah_b + TILE_B;
        uint32_t b_b = base + 2 * TILE_B + (uint32_t)(warpN * 64) * SROW + b_off;

#pragma unroll
        for (int ks = 0; ks < 2; ks++) {
            uint32_t koff = (uint32_t)(ks * 32);
            uint32_t Bf[8][2];
#pragma unroll
            for (int ntp = 0; ntp < 4; ntp++) {
                uint32_t r0, r1, r2, r3;
                ldm4(b_b + (uint32_t)(ntp * 16 * SROW) + koff, r0, r1, r2, r3);
                Bf[2 * ntp][0] = r0; Bf[2 * ntp][1] = r1;
                Bf[2 * ntp + 1][0] = r2; Bf[2 * ntp + 1][1] = r3;
            }
#pragma unroll
            for (int mt = 0; mt < 4; mt++) {
                uint32_t A_h[4], A_l[4];
                ldm4(ah_b + (uint32_t)(mt * 16 * SROW) + koff, A_h[0], A_h[1], A_h[2], A_h[3]);
                ldm4(al_b + (uint32_t)(mt * 16 * SROW) + koff, A_l[0], A_l[1], A_l[2], A_l[3]);
#pragma unroll
                for (int nt = 0; nt < 8; nt++) {
                    mma_f16(acc[mt][nt], A_h, Bf[nt]);
                    mma_f16(acc[mt][nt], A_l, Bf[nt]);
                }
            }
        }
        __syncthreads();
        buf ^= 1;
    }

    int erow = lane >> 2;
    int ecol = (lane & 3) * 2;
#pragma unroll
    for (int mt = 0; mt < 4; mt++) {
#pragma unroll
        for (int nt = 0; nt < 8; nt++) {
            int row0 = bm + warpM * 64 + mt * 16 + erow;
            int col = bn + warpN * 64 + nt * 8 + ecol;
            *(float2*)(C + (size_t)row0 * N + col) = make_float2(acc[mt][nt][0], acc[mt][nt][1]);
            *(float2*)(C + (size_t)(row0 + 8) * N + col) = make_float2(acc[mt][nt][2], acc[mt][nt][3]);
        }
    }
}

// ------------------------------------------------------------
// Fused RMSNorm + RoPE + convert: Q -> fp16 hi/lo (pre-scaled),
// K -> fp16, V -> fp16. One warp per (token, group).
// ------------------------------------------------------------
__global__ __launch_bounds__(256) void norm_rope_split(
    const int* __restrict__ positions,
    const float* __restrict__ qw, const float* __restrict__ kw)
{
    const int NG = NH + 2 * NKV;  // 40
    int warp = (blockIdx.x * blockDim.x + threadIdx.x) >> 5;
    int lane = threadIdx.x & 31;
    if (warp >= BTOK * NG) return;
    int gidx = warp % NG;
    int tok = warp / NG;

    if (gidx < NH + NKV) {
        bool isQ = gidx < NH;
        const float* w = isQ ? qw : kw;
        int off = isQ ? gidx * HD : K_OFF + (gidx - NH) * HD;
        const float* x = g_qkv + (size_t)tok * QKV_DIM + off;

        float xa = x[lane], xb = x[lane + 32], xc = x[lane + 64], xd = x[lane + 96];
        float ss = xa * xa + xb * xb + xc * xc + xd * xd;
#pragma unroll
        for (int o = 16; o; o >>= 1) ss += __shfl_xor_sync(0xffffffffu, ss, o);
        float rr = rsqrtf(ss * (1.f / 128.f) + 1e-6f);
        xa *= rr * w[lane];
        xb *= rr * w[lane + 32];
        xc *= rr * w[lane + 64];
        xd *= rr * w[lane + 96];

        float pos = (float)positions[tok];
        float inv1 = powf(1.0e6f, -(float)lane * (1.f / 64.f));
        float inv2 = powf(1.0e6f, -(float)(lane + 32) * (1.f / 64.f));
        float s1, c1, s2, c2;
        sincosf(pos * inv1, &s1, &c1);
        sincosf(pos * inv2, &s2, &c2);

        float y0 = xa * c1 - xc * s1;   // col lane
        float y1 = xb * c2 - xd * s2;   // col lane+32
        float y2 = xc * c1 + xa * s1;   // col lane+64
        float y3 = xd * c2 + xb * s2;   // col lane+96

        if (isQ) {
            y0 *= QSCALE; y1 *= QSCALE; y2 *= QSCALE; y3 *= QSCALE;
            size_t o = ((size_t)tok * NH + gidx) * HD;
#pragma unroll
            for (int j = 0; j < 4; j++) {
                float v = (j == 0) ? y0 : (j == 1) ? y1 : (j == 2) ? y2 : y3;
                int cc = lane + 32 * j;
                __half hv = __float2half_rn(v);
                g_qh[o + cc] = hv;
                g_ql[o + cc] = __float2half_rn(v - __half2float(hv));
            }
        } else {
            size_t o = ((size_t)tok * NKV + (gidx - NH)) * HD;
            g_kh[o + lane]      = __float2half_rn(y0);
            g_kh[o + lane + 32] = __float2half_rn(y1);
            g_kh[o + lane + 64] = __float2half_rn(y2);
            g_kh[o + lane + 96] = __float2half_rn(y3);
        }
    } else {
        int vh = gidx - NH - NKV;
        const float* x = g_qkv + (size_t)tok * QKV_DIM + V_OFF + vh * HD;
        size_t o = ((size_t)tok * NKV + vh) * HD;
#pragma unroll
        for (int j = 0; j < 4; j++) {
            int c = lane + 32 * j;
            g_vh[o + c] = __float2half_rn(x[c]);
        }
    }
}

// ------------------------------------------------------------
// Tensor-core causal flash attention, fp16 2-pass (unchanged)
// CTA = 128 q rows x 1 head, 8 warps; KV tiles of 64, cp.async double buffer
// ------------------------------------------------------------
#define FA_BM 128
#define FA_BN 64
#define FROW 272                 // 128 f16 = 256B + 16 pad
#define QTILE (128 * FROW)       // 34816
#define KVTILE (64 * FROW)       // 17408
#define SQH 0
#define SQL QTILE
#define SKV (2 * QTILE)
#define KVSTAGE (2 * KVTILE)     // Kh, Vh
#define FA_SMEM (2 * QTILE + 2 * KVSTAGE)   // 139264

__global__ __launch_bounds__(256, 1) void attn_tc()
{
    extern __shared__ char smc[];
    uint32_t smb = smem_u32(smc);
    int tid = threadIdx.x;
    int lane = tid & 31;
    int wid = tid >> 5;
    int qtile = blockIdx.x;
    int h = blockIdx.y;
    int b = blockIdx.z;
    int kvh = h >> 3;
    int q0 = qtile * FA_BM;

    int g8 = lane >> 3, r8 = lane & 7;
    uint32_t a_off = (uint32_t)(((g8 & 1) * 8 + r8) * FROW + (g8 >> 1) * 16);
    uint32_t b_off = (uint32_t)(((g8 >> 1) * 8 + r8) * FROW + (g8 & 1) * 16);

    // Q tile via cp.async (pre-scaled, pre-split)
#pragma unroll
    for (int i = 0; i < 8; i++) {
        int c = tid + i * 256;            // 2048 chunks: 128 rows x 16
        int row = c >> 4, c4 = c & 15;
        size_t src = ((size_t)(b * SS + q0 + row) * NH + h) * HD + c4 * 8;
        uint32_t doff = (uint32_t)(row * FROW + c4 * 16);
        cp16(smb + SQH + doff, g_qh + src);
        cp16(smb + SQL + doff, g_ql + src);
    }

    auto kvload = [&](int t, int kbuf) {
        uint32_t base = smb + SKV + kbuf * KVSTAGE;
#pragma unroll
        for (int i = 0; i < 4; i++) {
            int c = tid + i * 256;        // 1024 chunks: 64 rows x 16
            int row = c >> 4, c4 = c & 15;
            size_t src = ((size_t)(b * SS + t * FA_BN + row) * NKV + kvh) * HD + c4 * 8;
            uint32_t doff = (uint32_t)(row * FROW + c4 * 16);
            cp16(base + doff, g_kh + src);
            cp16(base + KVTILE + doff, g_vh + src);
        }
    };

    kvload(0, 0);
    CP_COMMIT();

    float m0 = -1e30f, m1 = -1e30f, lsum0 = 0.f, lsum1 = 0.f;
    float co[16][4];
#pragma unroll
    for (int nf = 0; nf < 16; nf++)
#pragma unroll
        for (int e = 0; e < 4; e++) co[nf][e] = 0.f;

    int ntiles = 2 * qtile + 2;
    int kbuf = 0;
    for (int t = 0; t < ntiles; t++) {
        if (t + 1 < ntiles) {
            kvload(t + 1, kbuf ^ 1);
            CP_COMMIT();
            CP_WAIT1();
        } else {
            CP_WAIT0();
        }
        __syncthreads();

        int kv0 = t * FA_BN;
        bool skip = (kv0 > q0 + wid * 16 + 15);   // warp tile fully masked
        if (!skip) {
            uint32_t base = smb + SKV + kbuf * KVSTAGE;

            // ---- S = Q K^T (2-pass: Qh + Ql vs fp16 K) ----
            float cs[4][2][4];
#pragma unroll
            for (int nb = 0; nb < 4; nb++)
#pragma unroll
                for (int f = 0; f < 2; f++)
#pragma unroll
                    for (int e = 0; e < 4; e++) cs[nb][f][e] = 0.f;

            uint32_t qrow = (uint32_t)(wid * 16) * FROW;
#pragma unroll
            for (int ks = 0; ks < 8; ks++) {
                uint32_t koff = (uint32_t)(ks * 32);
                uint32_t qh_[4], ql_[4];
                ldm4(smb + SQH + qrow + koff + a_off, qh_[0], qh_[1], qh_[2], qh_[3]);
                ldm4(smb + SQL + qrow + koff + a_off, ql_[0], ql_[1], ql_[2], ql_[3]);
#pragma unroll
                for (int nb = 0; nb < 4; nb++) {
                    uint32_t nboff = (uint32_t)(nb * 16) * FROW + koff;
                    uint32_t kf[4];
                    ldm4(base + nboff + b_off, kf[0], kf[1], kf[2], kf[3]);
                    mma_f16(cs[nb][0], qh_, kf);
                    mma_f16(cs[nb][0], ql_, kf);
                    mma_f16(cs[nb][1], qh_, kf + 2);
                    mma_f16(cs[nb][1], ql_, kf + 2);
                }
            }

            // ---- causal mask (only top-two kv tiles can clip) ----
            if (t >= 2 * qtile) {
                int row0 = q0 + wid * 16 + (lane >> 2);
#pragma unroll
                for (int nb = 0; nb < 4; nb++)
#pragma unroll
                    for (int f = 0; f < 2; f++)
#pragma unroll
                        for (int e = 0; e < 4; e++) {
                            int col = kv0 + nb * 16 + f * 8 + 2 * (lane & 3) + (e & 1);
                            int row = row0 + ((e >> 1) ? 8 : 0);
                            if (col > row) cs[nb][f][e] = -1e30f;
                        }
            }

            // ---- online softmax ----
            float mt0 = -1e30f, mt1 = -1e30f;
#pragma unroll
            for (int nb = 0; nb < 4; nb++)
#pragma unroll
                for (int f = 0; f < 2; f++) {
                    mt0 = fmaxf(mt0, fmaxf(cs[nb][f][0], cs[nb][f][1]));
                    mt1 = fmaxf(mt1, fmaxf(cs[nb][f][2], cs[nb][f][3]));
                }
            mt0 = fmaxf(mt0, __shfl_xor_sync(0xffffffffu, mt0, 1));
            mt0 = fmaxf(mt0, __shfl_xor_sync(0xffffffffu, mt0, 2));
            mt1 = fmaxf(mt1, __shfl_xor_sync(0xffffffffu, mt1, 1));
            mt1 = fmaxf(mt1, __shfl_xor_sync(0xffffffffu, mt1, 2));
            float mn0 = fmaxf(m0, mt0);
            float mn1 = fmaxf(m1, mt1);
            float corr0 = __expf(m0 - mn0);
            float corr1 = __expf(m1 - mn1);
            float ps0 = 0.f, ps1 = 0.f;
#pragma unroll
            for (int nb = 0; nb < 4; nb++)
#pragma unroll
                for (int f = 0; f < 2; f++) {
                    cs[nb][f][0] = __expf(cs[nb][f][0] - mn0);
                    cs[nb][f][1] = __expf(cs[nb][f][1] - mn0);
                    cs[nb][f][2] = __expf(cs[nb][f][2] - mn1);
                    cs[nb][f][3] = __expf(cs[nb][f][3] - mn1);
                    ps0 += cs[nb][f][0] + cs[nb][f][1];
                    ps1 += cs[nb][f][2] + cs[nb][f][3];
                }
            ps0 += __shfl_xor_sync(0xffffffffu, ps0, 1);
            ps0 += __shfl_xor_sync(0xffffffffu, ps0, 2);
            ps1 += __shfl_xor_sync(0xffffffffu, ps1, 1);
            ps1 += __shfl_xor_sync(0xffffffffu, ps1, 2);
            lsum0 = lsum0 * corr0 + ps0;
            lsum1 = lsum1 * corr1 + ps1;
            m0 = mn0; m1 = mn1;
#pragma unroll
            for (int nf = 0; nf < 16; nf++) {
                co[nf][0] *= corr0; co[nf][1] *= corr0;
                co[nf][2] *= corr1; co[nf][3] *= corr1;
            }

            // ---- O += P V (2-pass: P split hi/lo vs fp16 V) ----
#pragma unroll
            for (int ks = 0; ks < 4; ks++) {
                uint32_t ph[4], pl[4];
                split2h(cs[ks][0][0], cs[ks][0][1], ph[0], pl[0]);
                split2h(cs[ks][0][2], cs[ks][0][3], ph[1], pl[1]);
                split2h(cs[ks][1][0], cs[ks][1][1], ph[2], pl[2]);
                split2h(cs[ks][1][2], cs[ks][1][3], ph[3], pl[3]);
                uint32_t krow = (uint32_t)(ks * 16) * FROW;
#pragma unroll
                for (int db = 0; db < 8; db++) {
                    uint32_t doff = krow + (uint32_t)(db * 32) + a_off;
                    uint32_t vf[4];
                    ldm4t(base + KVTILE + doff, vf[0], vf[1], vf[2], vf[3]);
                    mma_f16(co[2 * db], ph, vf);
                    mma_f16(co[2 * db], pl, vf);
                    mma_f16(co[2 * db + 1], ph, vf + 2);
                    mma_f16(co[2 * db + 1], pl, vf + 2);
                }
            }
        }
        __syncthreads();
        kbuf ^= 1;
    }

    // epilogue: normalize, write pre-split fp16 for O projection
    float inv0 = 1.f / lsum0;
    float inv1 = 1.f / lsum1;
    int row0 = b * SS + q0 + wid * 16 + (lane >> 2);
    int colb = h * HD + 2 * (lane & 3);
#pragma unroll
    for (int nf = 0; nf < 16; nf++) {
        int col = colb + nf * 8;
        uint32_t hh, ll;
        split2h(co[nf][0] * inv0, co[nf][1] * inv0, hh, ll);
        *(uint32_t*)(g_ah + (size_t)row0 * ATTN_DIM + col) = hh;
        *(uint32_t*)(g_al + (size_t)row0 * ATTN_DIM + col) = ll;
        split2h(co[nf][2] * inv1, co[nf][3] * inv1, hh, ll);
        *(uint32_t*)(g_ah + (size_t)(row0 + 8) * ATTN_DIM + col) = hh;
        *(uint32_t*)(g_al + (size_t)(row0 + 8) * ATTN_DIM + col) = ll;
    }
}

// ------------------------------------------------------------
// launch
// ------------------------------------------------------------
extern "C" void kernel_launch(void* const* d_in, const int* in_sizes, int n_in,
                              void* d_out, int out_size)
{
    const float* hidden    = (const float*)d_in[0];
    const int*   positions = (const int*)d_in[1];
    const float* w_qkv     = (const float*)d_in[2];
    const float* w_o       = (const float*)d_in[3];
    const float* q_norm_w  = (const float*)d_in[4];
    const float* k_norm_w  = (const float*)d_in[5];
    float* out = (float*)d_out;

    float* qkv_buf;
    __half *hh, *hl, *wq, *wo, *ah, *al;
    cudaGetSymbolAddress((void**)&qkv_buf, g_qkv);
    cudaGetSymbolAddress((void**)&hh, g_hh);
    cudaGetSymbolAddress((void**)&hl, g_hl);
    cudaGetSymbolAddress((void**)&wq, g_wq);
    cudaGetSymbolAddress((void**)&wo, g_wo);
    cudaGetSymbolAddress((void**)&ah, g_ah);
    cudaGetSymbolAddress((void**)&al, g_al);

    cudaFuncSetAttribute(gemm_tc,
                         cudaFuncAttributeMaxDynamicSharedMemorySize, GEMM_SMEM);
    cudaFuncSetAttribute(attn_tc,
                         cudaFuncAttributeMaxDynamicSharedMemorySize, FA_SMEM);

    // 0) convert inputs
    {
        int n4h = BTOK * HIDDEN / 4;
        split_f32<<<(n4h + 255) / 256, 256>>>(hidden, hh, hl, n4h);
        int n4q = QKV_DIM * HIDDEN / 4;
        cvt_f32<<<(n4q + 255) / 256, 256>>>(w_qkv, wq, n4q);
        int n4o = HIDDEN * ATTN_DIM / 4;
        cvt_f32<<<(n4o + 255) / 256, 256>>>(w_o, wo, n4o);
    }

    // 1) QKV projection -> fp32 g_qkv
    gemm_tc<<<dim3(QKV_DIM / 128, BTOK / 128), 128, GEMM_SMEM>>>(
        hh, hl, wq, qkv_buf, BTOK, QKV_DIM, HIDDEN);

    // 2) RMSNorm + RoPE + convert
    {
        int total_warps = BTOK * (NH + 2 * NKV);
        norm_rope_split<<<(total_warps + 7) / 8, 256>>>(positions, q_norm_w, k_norm_w);
    }

    // 3) causal GQA flash attention
    attn_tc<<<dim3(SS / FA_BM, NH, BB), 256, FA_SMEM>>>();

    // 4) O projection -> fp32 out
    gemm_tc<<<dim3(HIDDEN / 128, BTOK / 128), 128, GEMM_SMEM>>>(
        ah, al, wo, out, BTOK, HIDDEN, ATTN_DIM);
}

// round 8
// speedup vs baseline: 5.0253x; 1.0663x over previous
#include <cuda_runtime.h>
#include <cuda_fp16.h>
#include <cstdint>
#include <math.h>

// Problem constants
#define HIDDEN   2048
#define NH       32
#define NKV      4
#define HD       128
#define BB       2
#define SS       2048
#define BTOK     (BB * SS)              // 4096
#define QKV_DIM  ((NH + 2 * NKV) * HD)  // 5120
#define ATTN_DIM (NH * HD)              // 4096
#define K_OFF    (NH * HD)              // 4096
#define V_OFF    (NH * HD + NKV * HD)   // 4608
#define QSCALE   0.08838834764831843f   // 1/sqrt(128)

// ------------------------------------------------------------
// Scratch (device globals; no runtime allocation allowed)
// ------------------------------------------------------------
__device__ float g_qkv[(size_t)BTOK * QKV_DIM];              // fp32 qkv proj
__device__ __half g_hh[(size_t)BTOK * HIDDEN];               // hidden hi/lo (fp16 split)
__device__ __half g_hl[(size_t)BTOK * HIDDEN];
__device__ __half g_wq[(size_t)QKV_DIM * HIDDEN];            // w_qkv fp16
__device__ __half g_wo[(size_t)HIDDEN * ATTN_DIM];           // w_o fp16
__device__ __half g_qh[(size_t)BTOK * NH * HD];              // Q hi/lo (normed+roped+scaled)
__device__ __half g_ql[(size_t)BTOK * NH * HD];
__device__ __half g_kh[(size_t)BTOK * NKV * HD];             // K fp16 (normed+roped)
__device__ __half g_vh[(size_t)BTOK * NKV * HD];             // V fp16
__device__ __half g_ah[(size_t)BTOK * ATTN_DIM];             // attn out hi/lo
__device__ __half g_al[(size_t)BTOK * ATTN_DIM];

// ------------------------------------------------------------
// helpers
// ------------------------------------------------------------
__device__ __forceinline__ uint32_t smem_u32(const void* p) {
    uint32_t a;
    asm("{ .reg .u64 t; cvta.to.shared.u64 t, %1; cvt.u32.u64 %0, t; }" : "=r"(a) : "l"(p));
    return a;
}
// split (x,y) into packed f16x2 high + low parts (lo lane = x, hi lane = y)
__device__ __forceinline__ void split2h(float x, float y, uint32_t& h, uint32_t& l) {
    asm("cvt.rn.f16x2.f32 %0, %1, %2;" : "=r"(h) : "f"(y), "f"(x));
    float hx = __half2float(__ushort_as_half((unsigned short)(h & 0xffffu)));
    float hy = __half2float(__ushort_as_half((unsigned short)(h >> 16)));
    float rx = x - hx, ry = y - hy;
    asm("cvt.rn.f16x2.f32 %0, %1, %2;" : "=r"(l) : "f"(ry), "f"(rx));
}
// pack (x,y) to f16x2 (round-to-nearest)
__device__ __forceinline__ uint32_t pack2h(float x, float y) {
    uint32_t h;
    asm("cvt.rn.f16x2.f32 %0, %1, %2;" : "=r"(h) : "f"(y), "f"(x));
    return h;
}
__device__ __forceinline__ void ldm4(uint32_t addr, uint32_t& r0, uint32_t& r1,
                                     uint32_t& r2, uint32_t& r3) {
    asm volatile("ldmatrix.sync.aligned.m8n8.x4.shared.b16 {%0,%1,%2,%3}, [%4];"
                 : "=r"(r0), "=r"(r1), "=r"(r2), "=r"(r3) : "r"(addr));
}
__device__ __forceinline__ void ldm4t(uint32_t addr, uint32_t& r0, uint32_t& r1,
                                      uint32_t& r2, uint32_t& r3) {
    asm volatile("ldmatrix.sync.aligned.m8n8.x4.trans.shared.b16 {%0,%1,%2,%3}, [%4];"
                 : "=r"(r0), "=r"(r1), "=r"(r2), "=r"(r3) : "r"(addr));
}
__device__ __forceinline__ void mma_f16(float* c, const uint32_t* a, const uint32_t* b) {
    asm volatile(
        "mma.sync.aligned.m16n8k16.row.col.f32.f16.f16.f32 "
        "{%0,%1,%2,%3}, {%4,%5,%6,%7}, {%8,%9}, {%0,%1,%2,%3};"
        : "+f"(c[0]), "+f"(c[1]), "+f"(c[2]), "+f"(c[3])
        : "r"(a[0]), "r"(a[1]), "r"(a[2]), "r"(a[3]), "r"(b[0]), "r"(b[1]));
}
__device__ __forceinline__ void cp16(uint32_t dst, const void* src) {
    asm volatile("cp.async.cg.shared.global [%0], [%1], 16;" :: "r"(dst), "l"(src));
}
#define CP_COMMIT() asm volatile("cp.async.commit_group;" ::: "memory")
#define CP_WAIT0()  asm volatile("cp.async.wait_group 0;" ::: "memory")
#define CP_WAIT1()  asm volatile("cp.async.wait_group 1;" ::: "memory")

// ------------------------------------------------------------
// conversion passes
// ------------------------------------------------------------
__global__ __launch_bounds__(256) void split_f32(
    const float* __restrict__ x, __half* __restrict__ h,
    __half* __restrict__ l, int n4)
{
    int i = blockIdx.x * blockDim.x + threadIdx.x;
    if (i >= n4) return;
    float4 v = ((const float4*)x)[i];
    uint32_t h0, l0, h1, l1;
    split2h(v.x, v.y, h0, l0);
    split2h(v.z, v.w, h1, l1);
    ((uint2*)h)[i] = make_uint2(h0, h1);
    ((uint2*)l)[i] = make_uint2(l0, l1);
}
__global__ __launch_bounds__(256) void cvt_f32(
    const float* __restrict__ x, __half* __restrict__ h, int n4)
{
    int i = blockIdx.x * blockDim.x + threadIdx.x;
    if (i >= n4) return;
    float4 v = ((const float4*)x)[i];
    ((uint2*)h)[i] = make_uint2(pack2h(v.x, v.y), pack2h(v.z, v.w));
}

// ------------------------------------------------------------
// fp16-split 2-pass tensor-core GEMM (NT): C = A[M,K] * B[N,K]^T
// A split hi/lo, B single fp16. 64x128x32 block tile, 4 warps (2x2),
// warp tile 32x64. 4 CTAs/SM -> 16 warps/SM, halved tail-wave waste.
// ------------------------------------------------------------
#define SROW 80                        // 32 f16 = 64B + 16 pad
#define ATILE_B (64 * SROW)            // 5120 (one 64x32 f16 tile)
#define BTILE_B (128 * SROW)           // 10240
#define STAGE_B (2 * ATILE_B + BTILE_B)   // 20480 (Ah, Al, B)
#define GEMM_SMEM (2 * STAGE_B)        // 40960

__global__ __launch_bounds__(128, 4) void gemm_tc(
    const __half* __restrict__ Ah, const __half* __restrict__ Al,
    const __half* __restrict__ B,
    float* __restrict__ C, int M, int N, int K)
{
    extern __shared__ char smc[];
    uint32_t smb = smem_u32(smc);
    int tid = threadIdx.x, lane = tid & 31, wid = tid >> 5;
    int warpM = wid >> 1, warpN = wid & 1;     // 2x2 warps; warp tile 32x64
    int bm = blockIdx.y * 64, bn = blockIdx.x * 128;

    int g8 = lane >> 3, r8 = lane & 7;
    uint32_t a_off = (uint32_t)(((g8 & 1) * 8 + r8) * SROW + (g8 >> 1) * 16);
    uint32_t b_off = (uint32_t)(((g8 >> 1) * 8 + r8) * SROW + (g8 & 1) * 16);

    auto stage_load = [&](int kb, int buf) {
        uint32_t base = smb + buf * STAGE_B;
        int k0 = kb * 32;
        // Ah: 256 chunks (64 rows x 4)
#pragma unroll
        for (int i = 0; i < 2; i++) {
            int idx = i * 128 + tid;
            int row = idx >> 2, c4 = idx & 3;
            cp16(base + (uint32_t)(row * SROW + c4 * 16),
                 Ah + (size_t)(bm + row) * K + k0 + c4 * 8);
        }
        // Al: 256 chunks
#pragma unroll
        for (int i = 0; i < 2; i++) {
            int idx = i * 128 + tid;
            int row = idx >> 2, c4 = idx & 3;
            cp16(base + ATILE_B + (uint32_t)(row * SROW + c4 * 16),
                 Al + (size_t)(bm + row) * K + k0 + c4 * 8);
        }
        // B: 512 chunks (128 rows x 4)
#pragma unroll
        for (int i = 0; i < 4; i++) {
            int idx = i * 128 + tid;
            int row = idx >> 2, c4 = idx & 3;
            cp16(base + 2 * ATILE_B + (uint32_t)(row * SROW + c4 * 16),
                 B + (size_t)(bn + row) * K + k0 + c4 * 8);
        }
    };

    float acc[2][8][4];
#pragma unroll
    for (int mt = 0; mt < 2; mt++)
#pragma unroll
        for (int nt = 0; nt < 8; nt++)
#pragma unroll
            for (int e = 0; e < 4; e++) acc[mt][nt][e] = 0.f;

    stage_load(0, 0);
    CP_COMMIT();

    int nkb = K / 32, buf = 0;
    for (int kb = 0; kb < nkb; kb++) {
        if (kb + 1 < nkb) {
            stage_load(kb + 1, buf ^ 1);
            CP_COMMIT();
            CP_WAIT1();
        } else {
            CP_WAIT0();
        }
        __syncthreads();

        uint32_t base = smb + buf * STAGE_B;
        uint32_t ah_b = base + (uint32_t)(warpM * 32) * SROW + a_off;
        uint32_t al_b = ah_b + ATILE_B;
        uint32_t b_b = base + 2 * ATILE_B + (uint32_t)(warpN * 64) * SROW + b_off;

#pragma unroll
        for (int ks = 0; ks < 2; ks++) {
            uint32_t koff = (uint32_t)(ks * 32);
            uint32_t Bf[8][2];
#pragma unroll
            for (int ntp = 0; ntp < 4; ntp++) {
                uint32_t r0, r1, r2, r3;
                ldm4(b_b + (uint32_t)(ntp * 16 * SROW) + koff, r0, r1, r2, r3);
                Bf[2 * ntp][0] = r0; Bf[2 * ntp][1] = r1;
                Bf[2 * ntp + 1][0] = r2; Bf[2 * ntp + 1][1] = r3;
            }
#pragma unroll
            for (int mt = 0; mt < 2; mt++) {
                uint32_t A_h[4], A_l[4];
                ldm4(ah_b + (uint32_t)(mt * 16 * SROW) + koff, A_h[0], A_h[1], A_h[2], A_h[3]);
                ldm4(al_b + (uint32_t)(mt * 16 * SROW) + koff, A_l[0], A_l[1], A_l[2], A_l[3]);
#pragma unroll
                for (int nt = 0; nt < 8; nt++) {
                    mma_f16(acc[mt][nt], A_h, Bf[nt]);
                    mma_f16(acc[mt][nt], A_l, Bf[nt]);
                }
            }
        }
        __syncthreads();
        buf ^= 1;
    }

    int erow = lane >> 2;
    int ecol = (lane & 3) * 2;
#pragma unroll
    for (int mt = 0; mt < 2; mt++) {
#pragma unroll
        for (int nt = 0; nt < 8; nt++) {
            int row0 = bm + warpM * 32 + mt * 16 + erow;
            int col = bn + warpN * 64 + nt * 8 + ecol;
            *(float2*)(C + (size_t)row0 * N + col) = make_float2(acc[mt][nt][0], acc[mt][nt][1]);
            *(float2*)(C + (size_t)(row0 + 8) * N + col) = make_float2(acc[mt][nt][2], acc[mt][nt][3]);
        }
    }
}

// ------------------------------------------------------------
// Fused RMSNorm + RoPE + convert: Q -> fp16 hi/lo (pre-scaled),
// K -> fp16, V -> fp16. One warp per (token, group).
// ------------------------------------------------------------
__global__ __launch_bounds__(256) void norm_rope_split(
    const int* __restrict__ positions,
    const float* __restrict__ qw, const float* __restrict__ kw)
{
    const int NG = NH + 2 * NKV;  // 40
    int warp = (blockIdx.x * blockDim.x + threadIdx.x) >> 5;
    int lane = threadIdx.x & 31;
    if (warp >= BTOK * NG) return;
    int gidx = warp % NG;
    int tok = warp / NG;

    if (gidx < NH + NKV) {
        bool isQ = gidx < NH;
        const float* w = isQ ? qw : kw;
        int off = isQ ? gidx * HD : K_OFF + (gidx - NH) * HD;
        const float* x = g_qkv + (size_t)tok * QKV_DIM + off;

        float xa = x[lane], xb = x[lane + 32], xc = x[lane + 64], xd = x[lane + 96];
        float ss = xa * xa + xb * xb + xc * xc + xd * xd;
#pragma unroll
        for (int o = 16; o; o >>= 1) ss += __shfl_xor_sync(0xffffffffu, ss, o);
        float rr = rsqrtf(ss * (1.f / 128.f) + 1e-6f);
        xa *= rr * w[lane];
        xb *= rr * w[lane + 32];
        xc *= rr * w[lane + 64];
        xd *= rr * w[lane + 96];

        float pos = (float)positions[tok];
        float inv1 = powf(1.0e6f, -(float)lane * (1.f / 64.f));
        float inv2 = powf(1.0e6f, -(float)(lane + 32) * (1.f / 64.f));
        float s1, c1, s2, c2;
        sincosf(pos * inv1, &s1, &c1);
        sincosf(pos * inv2, &s2, &c2);

        float y0 = xa * c1 - xc * s1;   // col lane
        float y1 = xb * c2 - xd * s2;   // col lane+32
        float y2 = xc * c1 + xa * s1;   // col lane+64
        float y3 = xd * c2 + xb * s2;   // col lane+96

        if (isQ) {
            y0 *= QSCALE; y1 *= QSCALE; y2 *= QSCALE; y3 *= QSCALE;
            size_t o = ((size_t)tok * NH + gidx) * HD;
#pragma unroll
            for (int j = 0; j < 4; j++) {
                float v = (j == 0) ? y0 : (j == 1) ? y1 : (j == 2) ? y2 : y3;
                int cc = lane + 32 * j;
                __half hv = __float2half_rn(v);
                g_qh[o + cc] = hv;
                g_ql[o + cc] = __float2half_rn(v - __half2float(hv));
            }
        } else {
            size_t o = ((size_t)tok * NKV + (gidx - NH)) * HD;
            g_kh[o + lane]      = __float2half_rn(y0);
            g_kh[o + lane + 32] = __float2half_rn(y1);
            g_kh[o + lane + 64] = __float2half_rn(y2);
            g_kh[o + lane + 96] = __float2half_rn(y3);
        }
    } else {
        int vh = gidx - NH - NKV;
        const float* x = g_qkv + (size_t)tok * QKV_DIM + V_OFF + vh * HD;
        size_t o = ((size_t)tok * NKV + vh) * HD;
#pragma unroll
        for (int j = 0; j < 4; j++) {
            int c = lane + 32 * j;
            g_vh[o + c] = __float2half_rn(x[c]);
        }
    }
}

// ------------------------------------------------------------
// Tensor-core causal flash attention, fp16 2-pass
// CTA = 128 q rows x 1 head, 8 warps; KV tiles of 64, cp.async double buffer
// Q fragments hoisted to registers (invariant across kv tiles)
// ------------------------------------------------------------
#define FA_BM 128
#define FA_BN 64
#define FROW 272                 // 128 f16 = 256B + 16 pad
#define QTILE (128 * FROW)       // 34816
#define KVTILE (64 * FROW)       // 17408
#define SQH 0
#define SQL QTILE
#define SKV (2 * QTILE)
#define KVSTAGE (2 * KVTILE)     // Kh, Vh
#define FA_SMEM (2 * QTILE + 2 * KVSTAGE)   // 139264

__global__ __launch_bounds__(256, 1) void attn_tc()
{
    extern __shared__ char smc[];
    uint32_t smb = smem_u32(smc);
    int tid = threadIdx.x;
    int lane = tid & 31;
    int wid = tid >> 5;
    int qtile = blockIdx.x;
    int h = blockIdx.y;
    int b = blockIdx.z;
    int kvh = h >> 3;
    int q0 = qtile * FA_BM;

    int g8 = lane >> 3, r8 = lane & 7;
    uint32_t a_off = (uint32_t)(((g8 & 1) * 8 + r8) * FROW + (g8 >> 1) * 16);
    uint32_t b_off = (uint32_t)(((g8 >> 1) * 8 + r8) * FROW + (g8 & 1) * 16);

    // Q tile via cp.async (pre-scaled, pre-split)
#pragma unroll
    for (int i = 0; i < 8; i++) {
        int c = tid + i * 256;            // 2048 chunks: 128 rows x 16
        int row = c >> 4, c4 = c & 15;
        size_t src = ((size_t)(b * SS + q0 + row) * NH + h) * HD + c4 * 8;
        uint32_t doff = (uint32_t)(row * FROW + c4 * 16);
        cp16(smb + SQH + doff, g_qh + src);
        cp16(smb + SQL + doff, g_ql + src);
    }
    CP_COMMIT();

    auto kvload = [&](int t, int kbuf) {
        uint32_t base = smb + SKV + kbuf * KVSTAGE;
#pragma unroll
        for (int i = 0; i < 4; i++) {
            int c = tid + i * 256;        // 1024 chunks: 64 rows x 16
            int row = c >> 4, c4 = c & 15;
            size_t src = ((size_t)(b * SS + t * FA_BN + row) * NKV + kvh) * HD + c4 * 8;
            uint32_t doff = (uint32_t)(row * FROW + c4 * 16);
            cp16(base + doff, g_kh + src);
            cp16(base + KVTILE + doff, g_vh + src);
        }
    };

    kvload(0, 0);
    CP_COMMIT();

    // wait for Q group (all but the kv group), then hoist Q frags to regs
    CP_WAIT1();
    __syncthreads();
    uint32_t qfh[8][4], qfl[8][4];
    {
        uint32_t qrow = (uint32_t)(wid * 16) * FROW;
#pragma unroll
        for (int ks = 0; ks < 8; ks++) {
            uint32_t koff = (uint32_t)(ks * 32);
            ldm4(smb + SQH + qrow + koff + a_off, qfh[ks][0], qfh[ks][1], qfh[ks][2], qfh[ks][3]);
            ldm4(smb + SQL + qrow + koff + a_off, qfl[ks][0], qfl[ks][1], qfl[ks][2], qfl[ks][3]);
        }
    }

    float m0 = -1e30f, m1 = -1e30f, lsum0 = 0.f, lsum1 = 0.f;
    float co[16][4];
#pragma unroll
    for (int nf = 0; nf < 16; nf++)
#pragma unroll
        for (int e = 0; e < 4; e++) co[nf][e] = 0.f;

    int ntiles = 2 * qtile + 2;
    int kbuf = 0;
    for (int t = 0; t < ntiles; t++) {
        if (t + 1 < ntiles) {
            kvload(t + 1, kbuf ^ 1);
            CP_COMMIT();
            CP_WAIT1();
        } else {
            CP_WAIT0();
        }
        __syncthreads();

        int kv0 = t * FA_BN;
        bool skip = (kv0 > q0 + wid * 16 + 15);   // warp tile fully masked
        if (!skip) {
            uint32_t base = smb + SKV + kbuf * KVSTAGE;

            // ---- S = Q K^T (2-pass: Qh + Ql vs fp16 K) ----
            float cs[4][2][4];
#pragma unroll
            for (int nb = 0; nb < 4; nb++)
#pragma unroll
                for (int f = 0; f < 2; f++)
#pragma unroll
                    for (int e = 0; e < 4; e++) cs[nb][f][e] = 0.f;

#pragma unroll
            for (int ks = 0; ks < 8; ks++) {
                uint32_t koff = (uint32_t)(ks * 32);
#pragma unroll
                for (int nb = 0; nb < 4; nb++) {
                    uint32_t nboff = (uint32_t)(nb * 16) * FROW + koff;
                    uint32_t kf[4];
                    ldm4(base + nboff + b_off, kf[0], kf[1], kf[2], kf[3]);
                    mma_f16(cs[nb][0], qfh[ks], kf);
                    mma_f16(cs[nb][0], qfl[ks], kf);
                    mma_f16(cs[nb][1], qfh[ks], kf + 2);
                    mma_f16(cs[nb][1], qfl[ks], kf + 2);
                }
            }

            // ---- causal mask (only top-two kv tiles can clip) ----
            if (t >= 2 * qtile) {
                int row0 = q0 + wid * 16 + (lane >> 2);
#pragma unroll
                for (int nb = 0; nb < 4; nb++)
#pragma unroll
                    for (int f = 0; f < 2; f++)
#pragma unroll
                        for (int e = 0; e < 4; e++) {
                            int col = kv0 + nb * 16 + f * 8 + 2 * (lane & 3) + (e & 1);
                            int row = row0 + ((e >> 1) ? 8 : 0);
                            if (col > row) cs[nb][f][e] = -1e30f;
                        }
            }

            // ---- online softmax ----
            float mt0 = -1e30f, mt1 = -1e30f;
#pragma unroll
            for (int nb = 0; nb < 4; nb++)
#pragma unroll
                for (int f = 0; f < 2; f++) {
                    mt0 = fmaxf(mt0, fmaxf(cs[nb][f][0], cs[nb][f][1]));
                    mt1 = fmaxf(mt1, fmaxf(cs[nb][f][2], cs[nb][f][3]));
                }
            mt0 = fmaxf(mt0, __shfl_xor_sync(0xffffffffu, mt0, 1));
            mt0 = fmaxf(mt0, __shfl_xor_sync(0xffffffffu, mt0, 2));
            mt1 = fmaxf(mt1, __shfl_xor_sync(0xffffffffu, mt1, 1));
            mt1 = fmaxf(mt1, __shfl_xor_sync(0xffffffffu, mt1, 2));
            float mn0 = fmaxf(m0, mt0);
            float mn1 = fmaxf(m1, mt1);
            float corr0 = __expf(m0 - mn0);
            float corr1 = __expf(m1 - mn1);
            float ps0 = 0.f, ps1 = 0.f;
#pragma unroll
            for (int nb = 0; nb < 4; nb++)
#pragma unroll
                for (int f = 0; f < 2; f++) {
                    cs[nb][f][0] = __expf(cs[nb][f][0] - mn0);
                    cs[nb][f][1] = __expf(cs[nb][f][1] - mn0);
                    cs[nb][f][2] = __expf(cs[nb][f][2] - mn1);
                    cs[nb][f][3] = __expf(cs[nb][f][3] - mn1);
                    ps0 += cs[nb][f][0] + cs[nb][f][1];
                    ps1 += cs[nb][f][2] + cs[nb][f][3];
                }
            ps0 += __shfl_xor_sync(0xffffffffu, ps0, 1);
            ps0 += __shfl_xor_sync(0xffffffffu, ps0, 2);
            ps1 += __shfl_xor_sync(0xffffffffu, ps1, 1);
            ps1 += __shfl_xor_sync(0xffffffffu, ps1, 2);
            lsum0 = lsum0 * corr0 + ps0;
            lsum1 = lsum1 * corr1 + ps1;
            m0 = mn0; m1 = mn1;
#pragma unroll
            for (int nf = 0; nf < 16; nf++) {
                co[nf][0] *= corr0; co[nf][1] *= corr0;
                co[nf][2] *= corr1; co[nf][3] *= corr1;
            }

            // ---- O += P V (2-pass: P split hi/lo vs fp16 V) ----
#pragma unroll
            for (int ks = 0; ks < 4; ks++) {
                uint32_t ph[4], pl[4];
                split2h(cs[ks][0][0], cs[ks][0][1], ph[0], pl[0]);
                split2h(cs[ks][0][2], cs[ks][0][3], ph[1], pl[1]);
                split2h(cs[ks][1][0], cs[ks][1][1], ph[2], pl[2]);
                split2h(cs[ks][1][2], cs[ks][1][3], ph[3], pl[3]);
                uint32_t krow = (uint32_t)(ks * 16) * FROW;
#pragma unroll
                for (int db = 0; db < 8; db++) {
                    uint32_t doff = krow + (uint32_t)(db * 32) + a_off;
                    uint32_t vf[4];
                    ldm4t(base + KVTILE + doff, vf[0], vf[1], vf[2], vf[3]);
                    mma_f16(co[2 * db], ph, vf);
                    mma_f16(co[2 * db], pl, vf);
                    mma_f16(co[2 * db + 1], ph, vf + 2);
                    mma_f16(co[2 * db + 1], pl, vf + 2);
                }
            }
        }
        __syncthreads();
        kbuf ^= 1;
    }

    // epilogue: normalize, write pre-split fp16 for O projection
    float inv0 = 1.f / lsum0;
    float inv1 = 1.f / lsum1;
    int row0 = b * SS + q0 + wid * 16 + (lane >> 2);
    int colb = h * HD + 2 * (lane & 3);
#pragma unroll
    for (int nf = 0; nf < 16; nf++) {
        int col = colb + nf * 8;
        uint32_t hh, ll;
        split2h(co[nf][0] * inv0, co[nf][1] * inv0, hh, ll);
        *(uint32_t*)(g_ah + (size_t)row0 * ATTN_DIM + col) = hh;
        *(uint32_t*)(g_al + (size_t)row0 * ATTN_DIM + col) = ll;
        split2h(co[nf][2] * inv1, co[nf][3] * inv1, hh, ll);
        *(uint32_t*)(g_ah + (size_t)(row0 + 8) * ATTN_DIM + col) = hh;
        *(uint32_t*)(g_al + (size_t)(row0 + 8) * ATTN_DIM + col) = ll;
    }
}

// ------------------------------------------------------------
// launch
// ------------------------------------------------------------
extern "C" void kernel_launch(void* const* d_in, const int* in_sizes, int n_in,
                              void* d_out, int out_size)
{
    const float* hidden    = (const float*)d_in[0];
    const int*   positions = (const int*)d_in[1];
    const float* w_qkv     = (const float*)d_in[2];
    const float* w_o       = (const float*)d_in[3];
    const float* q_norm_w  = (const float*)d_in[4];
    const float* k_norm_w  = (const float*)d_in[5];
    float* out = (float*)d_out;

    float* qkv_buf;
    __half *hh, *hl, *wq, *wo, *ah, *al;
    cudaGetSymbolAddress((void**)&qkv_buf, g_qkv);
    cudaGetSymbolAddress((void**)&hh, g_hh);
    cudaGetSymbolAddress((void**)&hl, g_hl);
    cudaGetSymbolAddress((void**)&wq, g_wq);
    cudaGetSymbolAddress((void**)&wo, g_wo);
    cudaGetSymbolAddress((void**)&ah, g_ah);
    cudaGetSymbolAddress((void**)&al, g_al);

    cudaFuncSetAttribute(gemm_tc,
                         cudaFuncAttributeMaxDynamicSharedMemorySize, GEMM_SMEM);
    cudaFuncSetAttribute(attn_tc,
                         cudaFuncAttributeMaxDynamicSharedMemorySize, FA_SMEM);

    // 0) convert inputs
    {
        int n4h = BTOK * HIDDEN / 4;
        split_f32<<<(n4h + 255) / 256, 256>>>(hidden, hh, hl, n4h);
        int n4q = QKV_DIM * HIDDEN / 4;
        cvt_f32<<<(n4q + 255) / 256, 256>>>(w_qkv, wq, n4q);
        int n4o = HIDDEN * ATTN_DIM / 4;
        cvt_f32<<<(n4o + 255) / 256, 256>>>(w_o, wo, n4o);
    }

    // 1) QKV projection -> fp32 g_qkv
    gemm_tc<<<dim3(QKV_DIM / 128, BTOK / 64), 128, GEMM_SMEM>>>(
        hh, hl, wq, qkv_buf, BTOK, QKV_DIM, HIDDEN);

    // 2) RMSNorm + RoPE + convert
    {
        int total_warps = BTOK * (NH + 2 * NKV);
        norm_rope_split<<<(total_warps + 7) / 8, 256>>>(positions, q_norm_w, k_norm_w);
    }

    // 3) causal GQA flash attention
    attn_tc<<<dim3(SS / FA_BM, NH, BB), 256, FA_SMEM>>>();

    // 4) O projection -> fp32 out
    gemm_tc<<<dim3(HIDDEN / 128, BTOK / 64), 128, GEMM_SMEM>>>(
        ah, al, wo, out, BTOK, HIDDEN, ATTN_DIM);
}

// round 9
// speedup vs baseline: 6.4009x; 1.2737x over previous
#include <cuda_runtime.h>
#include <cuda_fp16.h>
#include <cstdint>
#include <math.h>

// Problem constants
#define HIDDEN   2048
#define NH       32
#define NKV      4
#define HD       128
#define BB       2
#define SS       2048
#define BTOK     (BB * SS)              // 4096
#define QKV_DIM  ((NH + 2 * NKV) * HD)  // 5120
#define ATTN_DIM (NH * HD)              // 4096
#define K_OFF    (NH * HD)              // 4096
#define V_OFF    (NH * HD + NKV * HD)   // 4608
#define QSCALE   0.08838834764831843f   // 1/sqrt(128)

// ------------------------------------------------------------
// Scratch (device globals; no runtime allocation allowed)
// ------------------------------------------------------------
__device__ float g_qkv[(size_t)BTOK * QKV_DIM];              // fp32 qkv proj
__device__ __half g_hh[(size_t)BTOK * HIDDEN];               // hidden hi/lo (fp16 split)
__device__ __half g_hl[(size_t)BTOK * HIDDEN];
__device__ __half g_wq[(size_t)QKV_DIM * HIDDEN];            // w_qkv fp16
__device__ __half g_wo[(size_t)HIDDEN * ATTN_DIM];           // w_o fp16
__device__ __half g_qh[(size_t)BTOK * NH * HD];              // Q fp16 (normed+roped+scaled)
__device__ __half g_kh[(size_t)BTOK * NKV * HD];             // K fp16 (normed+roped)
__device__ __half g_vh[(size_t)BTOK * NKV * HD];             // V fp16
__device__ __half g_ah[(size_t)BTOK * ATTN_DIM];             // attn out fp16

// ------------------------------------------------------------
// helpers
// ------------------------------------------------------------
__device__ __forceinline__ uint32_t smem_u32(const void* p) {
    uint32_t a;
    asm("{ .reg .u64 t; cvta.to.shared.u64 t, %1; cvt.u32.u64 %0, t; }" : "=r"(a) : "l"(p));
    return a;
}
// split (x,y) into packed f16x2 high + low parts (lo lane = x, hi lane = y)
__device__ __forceinline__ void split2h(float x, float y, uint32_t& h, uint32_t& l) {
    asm("cvt.rn.f16x2.f32 %0, %1, %2;" : "=r"(h) : "f"(y), "f"(x));
    float hx = __half2float(__ushort_as_half((unsigned short)(h & 0xffffu)));
    float hy = __half2float(__ushort_as_half((unsigned short)(h >> 16)));
    float rx = x - hx, ry = y - hy;
    asm("cvt.rn.f16x2.f32 %0, %1, %2;" : "=r"(l) : "f"(ry), "f"(rx));
}
// pack (x,y) to f16x2 (round-to-nearest)
__device__ __forceinline__ uint32_t pack2h(float x, float y) {
    uint32_t h;
    asm("cvt.rn.f16x2.f32 %0, %1, %2;" : "=r"(h) : "f"(y), "f"(x));
    return h;
}
__device__ __forceinline__ void ldm4(uint32_t addr, uint32_t& r0, uint32_t& r1,
                                     uint32_t& r2, uint32_t& r3) {
    asm volatile("ldmatrix.sync.aligned.m8n8.x4.shared.b16 {%0,%1,%2,%3}, [%4];"
                 : "=r"(r0), "=r"(r1), "=r"(r2), "=r"(r3) : "r"(addr));
}
__device__ __forceinline__ void ldm4t(uint32_t addr, uint32_t& r0, uint32_t& r1,
                                      uint32_t& r2, uint32_t& r3) {
    asm volatile("ldmatrix.sync.aligned.m8n8.x4.trans.shared.b16 {%0,%1,%2,%3}, [%4];"
                 : "=r"(r0), "=r"(r1), "=r"(r2), "=r"(r3) : "r"(addr));
}
__device__ __forceinline__ void mma_f16(float* c, const uint32_t* a, const uint32_t* b) {
    asm volatile(
        "mma.sync.aligned.m16n8k16.row.col.f32.f16.f16.f32 "
        "{%0,%1,%2,%3}, {%4,%5,%6,%7}, {%8,%9}, {%0,%1,%2,%3};"
        : "+f"(c[0]), "+f"(c[1]), "+f"(c[2]), "+f"(c[3])
        : "r"(a[0]), "r"(a[1]), "r"(a[2]), "r"(a[3]), "r"(b[0]), "r"(b[1]));
}
__device__ __forceinline__ void cp16(uint32_t dst, const void* src) {
    asm volatile("cp.async.cg.shared.global [%0], [%1], 16;" :: "r"(dst), "l"(src));
}
#define CP_COMMIT() asm volatile("cp.async.commit_group;" ::: "memory")
#define CP_WAIT0()  asm volatile("cp.async.wait_group 0;" ::: "memory")
#define CP_WAIT1()  asm volatile("cp.async.wait_group 1;" ::: "memory")

// ------------------------------------------------------------
// conversion passes
// ------------------------------------------------------------
__global__ __launch_bounds__(256) void split_f32(
    const float* __restrict__ x, __half* __restrict__ h,
    __half* __restrict__ l, int n4)
{
    int i = blockIdx.x * blockDim.x + threadIdx.x;
    if (i >= n4) return;
    float4 v = ((const float4*)x)[i];
    uint32_t h0, l0, h1, l1;
    split2h(v.x, v.y, h0, l0);
    split2h(v.z, v.w, h1, l1);
    ((uint2*)h)[i] = make_uint2(h0, h1);
    ((uint2*)l)[i] = make_uint2(l0, l1);
}
__global__ __launch_bounds__(256) void cvt_f32(
    const float* __restrict__ x, __half* __restrict__ h, int n4)
{
    int i = blockIdx.x * blockDim.x + threadIdx.x;
    if (i >= n4) return;
    float4 v = ((const float4*)x)[i];
    ((uint2*)h)[i] = make_uint2(pack2h(v.x, v.y), pack2h(v.z, v.w));
}

// ------------------------------------------------------------
// fp16-split 2-pass GEMM (NT): C = A[M,K]*B[N,K]^T, A split hi/lo
// 64x128x32 block tile, 4 warps (2x2), warp 32x64, 4 CTAs/SM
// ------------------------------------------------------------
#define SROW 80                        // 32 f16 = 64B + 16 pad
#define ATILE_B (64 * SROW)            // 5120
#define BTILE_B (128 * SROW)           // 10240
#define STAGE_B (2 * ATILE_B + BTILE_B)   // 20480
#define GEMM_SMEM (2 * STAGE_B)        // 40960

__global__ __launch_bounds__(128, 4) void gemm_tc(
    const __half* __restrict__ Ah, const __half* __restrict__ Al,
    const __half* __restrict__ B,
    float* __restrict__ C, int M, int N, int K)
{
    extern __shared__ char smc[];
    uint32_t smb = smem_u32(smc);
    int tid = threadIdx.x, lane = tid & 31, wid = tid >> 5;
    int warpM = wid >> 1, warpN = wid & 1;
    int bm = blockIdx.y * 64, bn = blockIdx.x * 128;

    int g8 = lane >> 3, r8 = lane & 7;
    uint32_t a_off = (uint32_t)(((g8 & 1) * 8 + r8) * SROW + (g8 >> 1) * 16);
    uint32_t b_off = (uint32_t)(((g8 >> 1) * 8 + r8) * SROW + (g8 & 1) * 16);

    auto stage_load = [&](int kb, int buf) {
        uint32_t base = smb + buf * STAGE_B;
        int k0 = kb * 32;
#pragma unroll
        for (int i = 0; i < 2; i++) {
            int idx = i * 128 + tid;
            int row = idx >> 2, c4 = idx & 3;
            cp16(base + (uint32_t)(row * SROW + c4 * 16),
                 Ah + (size_t)(bm + row) * K + k0 + c4 * 8);
        }
#pragma unroll
        for (int i = 0; i < 2; i++) {
            int idx = i * 128 + tid;
            int row = idx >> 2, c4 = idx & 3;
            cp16(base + ATILE_B + (uint32_t)(row * SROW + c4 * 16),
                 Al + (size_t)(bm + row) * K + k0 + c4 * 8);
        }
#pragma unroll
        for (int i = 0; i < 4; i++) {
            int idx = i * 128 + tid;
            int row = idx >> 2, c4 = idx & 3;
            cp16(base + 2 * ATILE_B + (uint32_t)(row * SROW + c4 * 16),
                 B + (size_t)(bn + row) * K + k0 + c4 * 8);
        }
    };

    float acc[2][8][4];
#pragma unroll
    for (int mt = 0; mt < 2; mt++)
#pragma unroll
        for (int nt = 0; nt < 8; nt++)
#pragma unroll
            for (int e = 0; e < 4; e++) acc[mt][nt][e] = 0.f;

    stage_load(0, 0);
    CP_COMMIT();

    int nkb = K / 32, buf = 0;
    for (int kb = 0; kb < nkb; kb++) {
        if (kb + 1 < nkb) {
            stage_load(kb + 1, buf ^ 1);
            CP_COMMIT();
            CP_WAIT1();
        } else {
            CP_WAIT0();
        }
        __syncthreads();

        uint32_t base = smb + buf * STAGE_B;
        uint32_t ah_b = base + (uint32_t)(warpM * 32) * SROW + a_off;
        uint32_t al_b = ah_b + ATILE_B;
        uint32_t b_b = base + 2 * ATILE_B + (uint32_t)(warpN * 64) * SROW + b_off;

#pragma unroll
        for (int ks = 0; ks < 2; ks++) {
            uint32_t koff = (uint32_t)(ks * 32);
            uint32_t Bf[8][2];
#pragma unroll
            for (int ntp = 0; ntp < 4; ntp++) {
                uint32_t r0, r1, r2, r3;
                ldm4(b_b + (uint32_t)(ntp * 16 * SROW) + koff, r0, r1, r2, r3);
                Bf[2 * ntp][0] = r0; Bf[2 * ntp][1] = r1;
                Bf[2 * ntp + 1][0] = r2; Bf[2 * ntp + 1][1] = r3;
            }
#pragma unroll
            for (int mt = 0; mt < 2; mt++) {
                uint32_t A_h[4], A_l[4];
                ldm4(ah_b + (uint32_t)(mt * 16 * SROW) + koff, A_h[0], A_h[1], A_h[2], A_h[3]);
                ldm4(al_b + (uint32_t)(mt * 16 * SROW) + koff, A_l[0], A_l[1], A_l[2], A_l[3]);
#pragma unroll
                for (int nt = 0; nt < 8; nt++) {
                    mma_f16(acc[mt][nt], A_h, Bf[nt]);
                    mma_f16(acc[mt][nt], A_l, Bf[nt]);
                }
            }
        }
        __syncthreads();
        buf ^= 1;
    }

    int erow = lane >> 2;
    int ecol = (lane & 3) * 2;
#pragma unroll
    for (int mt = 0; mt < 2; mt++) {
#pragma unroll
        for (int nt = 0; nt < 8; nt++) {
            int row0 = bm + warpM * 32 + mt * 16 + erow;
            int col = bn + warpN * 64 + nt * 8 + ecol;
            *(float2*)(C + (size_t)row0 * N + col) = make_float2(acc[mt][nt][0], acc[mt][nt][1]);
            *(float2*)(C + (size_t)(row0 + 8) * N + col) = make_float2(acc[mt][nt][2], acc[mt][nt][3]);
        }
    }
}

// ------------------------------------------------------------
// single-pass fp16 GEMM (NT), same tiling (for O projection)
// ------------------------------------------------------------
#define STAGE1_B (ATILE_B + BTILE_B)      // 15360
#define GEMM1_SMEM (2 * STAGE1_B)         // 30720

__global__ __launch_bounds__(128, 4) void gemm_tc1(
    const __half* __restrict__ A, const __half* __restrict__ B,
    float* __restrict__ C, int M, int N, int K)
{
    extern __shared__ char smc[];
    uint32_t smb = smem_u32(smc);
    int tid = threadIdx.x, lane = tid & 31, wid = tid >> 5;
    int warpM = wid >> 1, warpN = wid & 1;
    int bm = blockIdx.y * 64, bn = blockIdx.x * 128;

    int g8 = lane >> 3, r8 = lane & 7;
    uint32_t a_off = (uint32_t)(((g8 & 1) * 8 + r8) * SROW + (g8 >> 1) * 16);
    uint32_t b_off = (uint32_t)(((g8 >> 1) * 8 + r8) * SROW + (g8 & 1) * 16);

    auto stage_load = [&](int kb, int buf) {
        uint32_t base = smb + buf * STAGE1_B;
        int k0 = kb * 32;
#pragma unroll
        for (int i = 0; i < 2; i++) {
            int idx = i * 128 + tid;
            int row = idx >> 2, c4 = idx & 3;
            cp16(base + (uint32_t)(row * SROW + c4 * 16),
                 A + (size_t)(bm + row) * K + k0 + c4 * 8);
        }
#pragma unroll
        for (int i = 0; i < 4; i++) {
            int idx = i * 128 + tid;
            int row = idx >> 2, c4 = idx & 3;
            cp16(base + ATILE_B + (uint32_t)(row * SROW + c4 * 16),
                 B + (size_t)(bn + row) * K + k0 + c4 * 8);
        }
    };

    float acc[2][8][4];
#pragma unroll
    for (int mt = 0; mt < 2; mt++)
#pragma unroll
        for (int nt = 0; nt < 8; nt++)
#pragma unroll
            for (int e = 0; e < 4; e++) acc[mt][nt][e] = 0.f;

    stage_load(0, 0);
    CP_COMMIT();

    int nkb = K / 32, buf = 0;
    for (int kb = 0; kb < nkb; kb++) {
        if (kb + 1 < nkb) {
            stage_load(kb + 1, buf ^ 1);
            CP_COMMIT();
            CP_WAIT1();
        } else {
            CP_WAIT0();
        }
        __syncthreads();

        uint32_t base = smb + buf * STAGE1_B;
        uint32_t a_b = base + (uint32_t)(warpM * 32) * SROW + a_off;
        uint32_t b_b = base + ATILE_B + (uint32_t)(warpN * 64) * SROW + b_off;

#pragma unroll
        for (int ks = 0; ks < 2; ks++) {
            uint32_t koff = (uint32_t)(ks * 32);
            uint32_t Bf[8][2];
#pragma unroll
            for (int ntp = 0; ntp < 4; ntp++) {
                uint32_t r0, r1, r2, r3;
                ldm4(b_b + (uint32_t)(ntp * 16 * SROW) + koff, r0, r1, r2, r3);
                Bf[2 * ntp][0] = r0; Bf[2 * ntp][1] = r1;
                Bf[2 * ntp + 1][0] = r2; Bf[2 * ntp + 1][1] = r3;
            }
#pragma unroll
            for (int mt = 0; mt < 2; mt++) {
                uint32_t Af[4];
                ldm4(a_b + (uint32_t)(mt * 16 * SROW) + koff, Af[0], Af[1], Af[2], Af[3]);
#pragma unroll
                for (int nt = 0; nt < 8; nt++)
                    mma_f16(acc[mt][nt], Af, Bf[nt]);
            }
        }
        __syncthreads();
        buf ^= 1;
    }

    int erow = lane >> 2;
    int ecol = (lane & 3) * 2;
#pragma unroll
    for (int mt = 0; mt < 2; mt++) {
#pragma unroll
        for (int nt = 0; nt < 8; nt++) {
            int row0 = bm + warpM * 32 + mt * 16 + erow;
            int col = bn + warpN * 64 + nt * 8 + ecol;
            *(float2*)(C + (size_t)row0 * N + col) = make_float2(acc[mt][nt][0], acc[mt][nt][1]);
            *(float2*)(C + (size_t)(row0 + 8) * N + col) = make_float2(acc[mt][nt][2], acc[mt][nt][3]);
        }
    }
}

// ------------------------------------------------------------
// Fused RMSNorm + RoPE + convert: Q/K/V -> single fp16 (Q pre-scaled)
// ------------------------------------------------------------
__global__ __launch_bounds__(256) void norm_rope_split(
    const int* __restrict__ positions,
    const float* __restrict__ qw, const float* __restrict__ kw)
{
    const int NG = NH + 2 * NKV;  // 40
    int warp = (blockIdx.x * blockDim.x + threadIdx.x) >> 5;
    int lane = threadIdx.x & 31;
    if (warp >= BTOK * NG) return;
    int gidx = warp % NG;
    int tok = warp / NG;

    if (gidx < NH + NKV) {
        bool isQ = gidx < NH;
        const float* w = isQ ? qw : kw;
        int off = isQ ? gidx * HD : K_OFF + (gidx - NH) * HD;
        const float* x = g_qkv + (size_t)tok * QKV_DIM + off;

        float xa = x[lane], xb = x[lane + 32], xc = x[lane + 64], xd = x[lane + 96];
        float ss = xa * xa + xb * xb + xc * xc + xd * xd;
#pragma unroll
        for (int o = 16; o; o >>= 1) ss += __shfl_xor_sync(0xffffffffu, ss, o);
        float rr = rsqrtf(ss * (1.f / 128.f) + 1e-6f);
        xa *= rr * w[lane];
        xb *= rr * w[lane + 32];
        xc *= rr * w[lane + 64];
        xd *= rr * w[lane + 96];

        float pos = (float)positions[tok];
        float inv1 = powf(1.0e6f, -(float)lane * (1.f / 64.f));
        float inv2 = powf(1.0e6f, -(float)(lane + 32) * (1.f / 64.f));
        float s1, c1, s2, c2;
        sincosf(pos * inv1, &s1, &c1);
        sincosf(pos * inv2, &s2, &c2);

        float y0 = xa * c1 - xc * s1;   // col lane
        float y1 = xb * c2 - xd * s2;   // col lane+32
        float y2 = xc * c1 + xa * s1;   // col lane+64
        float y3 = xd * c2 + xb * s2;   // col lane+96

        if (isQ) {
            size_t o = ((size_t)tok * NH + gidx) * HD;
            g_qh[o + lane]      = __float2half_rn(y0 * QSCALE);
            g_qh[o + lane + 32] = __float2half_rn(y1 * QSCALE);
            g_qh[o + lane + 64] = __float2half_rn(y2 * QSCALE);
            g_qh[o + lane + 96] = __float2half_rn(y3 * QSCALE);
        } else {
            size_t o = ((size_t)tok * NKV + (gidx - NH)) * HD;
            g_kh[o + lane]      = __float2half_rn(y0);
            g_kh[o + lane + 32] = __float2half_rn(y1);
            g_kh[o + lane + 64] = __float2half_rn(y2);
            g_kh[o + lane + 96] = __float2half_rn(y3);
        }
    } else {
        int vh = gidx - NH - NKV;
        const float* x = g_qkv + (size_t)tok * QKV_DIM + V_OFF + vh * HD;
        size_t o = ((size_t)tok * NKV + vh) * HD;
#pragma unroll
        for (int j = 0; j < 4; j++) {
            int c = lane + 32 * j;
            g_vh[o + c] = __float2half_rn(x[c]);
        }
    }
}

// ------------------------------------------------------------
// Tensor-core causal flash attention, single-pass fp16
// CTA = 128 q rows x 1 head, 8 warps; KV tiles of 128, double buffer
// Q fragments hoisted to registers; Q smem not needed after hoist
// ------------------------------------------------------------
#define FA_BM 128
#define FA_BN 128
#define FROW 272                 // 128 f16 = 256B + 16 pad
#define QTILE (128 * FROW)       // 34816
#define KVTILE (128 * FROW)      // 34816
#define SQ 0
#define SKV QTILE
#define KVSTAGE (2 * KVTILE)     // 69632 (K, V)
#define FA_SMEM (QTILE + 2 * KVSTAGE)   // 174080

__global__ __launch_bounds__(256, 1) void attn_tc()
{
    extern __shared__ char smc[];
    uint32_t smb = smem_u32(smc);
    int tid = threadIdx.x;
    int lane = tid & 31;
    int wid = tid >> 5;
    int qtile = blockIdx.x;
    int h = blockIdx.y;
    int b = blockIdx.z;
    int kvh = h >> 3;
    int q0 = qtile * FA_BM;

    int g8 = lane >> 3, r8 = lane & 7;
    uint32_t a_off = (uint32_t)(((g8 & 1) * 8 + r8) * FROW + (g8 >> 1) * 16);
    uint32_t b_off = (uint32_t)(((g8 >> 1) * 8 + r8) * FROW + (g8 & 1) * 16);

    // Q tile via cp.async (pre-scaled fp16)
#pragma unroll
    for (int i = 0; i < 8; i++) {
        int c = tid + i * 256;            // 2048 chunks: 128 rows x 16
        int row = c >> 4, c4 = c & 15;
        size_t src = ((size_t)(b * SS + q0 + row) * NH + h) * HD + c4 * 8;
        cp16(smb + SQ + (uint32_t)(row * FROW + c4 * 16), g_qh + src);
    }
    CP_COMMIT();

    auto kvload = [&](int t, int kbuf) {
        uint32_t base = smb + SKV + kbuf * KVSTAGE;
#pragma unroll
        for (int i = 0; i < 8; i++) {
            int c = tid + i * 256;        // 2048 chunks: 128 rows x 16
            int row = c >> 4, c4 = c & 15;
            size_t src = ((size_t)(b * SS + t * FA_BN + row) * NKV + kvh) * HD + c4 * 8;
            uint32_t doff = (uint32_t)(row * FROW + c4 * 16);
            cp16(base + doff, g_kh + src);
            cp16(base + KVTILE + doff, g_vh + src);
        }
    };

    kvload(0, 0);
    CP_COMMIT();

    // wait for Q (kv group still in flight), hoist Q frags to registers
    CP_WAIT1();
    __syncthreads();
    uint32_t qf[8][4];
    {
        uint32_t qrow = (uint32_t)(wid * 16) * FROW;
#pragma unroll
        for (int ks = 0; ks < 8; ks++)
            ldm4(smb + SQ + qrow + (uint32_t)(ks * 32) + a_off,
                 qf[ks][0], qf[ks][1], qf[ks][2], qf[ks][3]);
    }

    float m0 = -1e30f, m1 = -1e30f, lsum0 = 0.f, lsum1 = 0.f;
    float co[16][4];
#pragma unroll
    for (int nf = 0; nf < 16; nf++)
#pragma unroll
        for (int e = 0; e < 4; e++) co[nf][e] = 0.f;

    int ntiles = qtile + 1;
    int kbuf = 0;
    for (int t = 0; t < ntiles; t++) {
        if (t + 1 < ntiles) {
            kvload(t + 1, kbuf ^ 1);
            CP_COMMIT();
            CP_WAIT1();
        } else {
            CP_WAIT0();
        }
        __syncthreads();

        int kv0 = t * FA_BN;
        uint32_t base = smb + SKV + kbuf * KVSTAGE;

        // ---- S = Q K^T (single pass) ----
        float cs[8][2][4];
#pragma unroll
        for (int nb = 0; nb < 8; nb++)
#pragma unroll
            for (int f = 0; f < 2; f++)
#pragma unroll
                for (int e = 0; e < 4; e++) cs[nb][f][e] = 0.f;

#pragma unroll
        for (int ks = 0; ks < 8; ks++) {
            uint32_t koff = (uint32_t)(ks * 32);
#pragma unroll
            for (int nb = 0; nb < 8; nb++) {
                uint32_t nboff = (uint32_t)(nb * 16) * FROW + koff;
                uint32_t kf[4];
                ldm4(base + nboff + b_off, kf[0], kf[1], kf[2], kf[3]);
                mma_f16(cs[nb][0], qf[ks], kf);
                mma_f16(cs[nb][1], qf[ks], kf + 2);
            }
        }

        // ---- causal mask (diagonal tile only) ----
        if (t == qtile) {
            int row0 = q0 + wid * 16 + (lane >> 2);
#pragma unroll
            for (int nb = 0; nb < 8; nb++)
#pragma unroll
                for (int f = 0; f < 2; f++)
#pragma unroll
                    for (int e = 0; e < 4; e++) {
                        int col = kv0 + nb * 16 + f * 8 + 2 * (lane & 3) + (e & 1);
                        int row = row0 + ((e >> 1) ? 8 : 0);
                        if (col > row) cs[nb][f][e] = -1e30f;
                    }
        }

        // ---- online softmax ----
        float mt0 = -1e30f, mt1 = -1e30f;
#pragma unroll
        for (int nb = 0; nb < 8; nb++)
#pragma unroll
            for (int f = 0; f < 2; f++) {
                mt0 = fmaxf(mt0, fmaxf(cs[nb][f][0], cs[nb][f][1]));
                mt1 = fmaxf(mt1, fmaxf(cs[nb][f][2], cs[nb][f][3]));
            }
        mt0 = fmaxf(mt0, __shfl_xor_sync(0xffffffffu, mt0, 1));
        mt0 = fmaxf(mt0, __shfl_xor_sync(0xffffffffu, mt0, 2));
        mt1 = fmaxf(mt1, __shfl_xor_sync(0xffffffffu, mt1, 1));
        mt1 = fmaxf(mt1, __shfl_xor_sync(0xffffffffu, mt1, 2));
        float mn0 = fmaxf(m0, mt0);
        float mn1 = fmaxf(m1, mt1);
        float corr0 = __expf(m0 - mn0);
        float corr1 = __expf(m1 - mn1);
        float ps0 = 0.f, ps1 = 0.f;
#pragma unroll
        for (int nb = 0; nb < 8; nb++)
#pragma unroll
            for (int f = 0; f < 2; f++) {
                cs[nb][f][0] = __expf(cs[nb][f][0] - mn0);
                cs[nb][f][1] = __expf(cs[nb][f][1] - mn0);
                cs[nb][f][2] = __expf(cs[nb][f][2] - mn1);
                cs[nb][f][3] = __expf(cs[nb][f][3] - mn1);
                ps0 += cs[nb][f][0] + cs[nb][f][1];
                ps1 += cs[nb][f][2] + cs[nb][f][3];
            }
        ps0 += __shfl_xor_sync(0xffffffffu, ps0, 1);
        ps0 += __shfl_xor_sync(0xffffffffu, ps0, 2);
        ps1 += __shfl_xor_sync(0xffffffffu, ps1, 1);
        ps1 += __shfl_xor_sync(0xffffffffu, ps1, 2);
        lsum0 = lsum0 * corr0 + ps0;
        lsum1 = lsum1 * corr1 + ps1;
        m0 = mn0; m1 = mn1;
#pragma unroll
        for (int nf = 0; nf < 16; nf++) {
            co[nf][0] *= corr0; co[nf][1] *= corr0;
            co[nf][2] *= corr1; co[nf][3] *= corr1;
        }

        // ---- O += P V (single pass, P packed to fp16) ----
#pragma unroll
        for (int ks = 0; ks < 8; ks++) {
            uint32_t ph[4];
            ph[0] = pack2h(cs[ks][0][0], cs[ks][0][1]);
            ph[1] = pack2h(cs[ks][0][2], cs[ks][0][3]);
            ph[2] = pack2h(cs[ks][1][0], cs[ks][1][1]);
            ph[3] = pack2h(cs[ks][1][2], cs[ks][1][3]);
            uint32_t krow = (uint32_t)(ks * 16) * FROW;
#pragma unroll
            for (int db = 0; db < 8; db++) {
                uint32_t doff = krow + (uint32_t)(db * 32) + a_off;
                uint32_t vf[4];
                ldm4t(base + KVTILE + doff, vf[0], vf[1], vf[2], vf[3]);
                mma_f16(co[2 * db], ph, vf);
                mma_f16(co[2 * db + 1], ph, vf + 2);
            }
        }
        __syncthreads();
        kbuf ^= 1;
    }

    // epilogue: normalize, write fp16 for O projection
    float inv0 = 1.f / lsum0;
    float inv1 = 1.f / lsum1;
    int row0 = b * SS + q0 + wid * 16 + (lane >> 2);
    int colb = h * HD + 2 * (lane & 3);
#pragma unroll
    for (int nf = 0; nf < 16; nf++) {
        int col = colb + nf * 8;
        *(uint32_t*)(g_ah + (size_t)row0 * ATTN_DIM + col) =
            pack2h(co[nf][0] * inv0, co[nf][1] * inv0);
        *(uint32_t*)(g_ah + (size_t)(row0 + 8) * ATTN_DIM + col) =
            pack2h(co[nf][2] * inv1, co[nf][3] * inv1);
    }
}

// ------------------------------------------------------------
// launch
// ------------------------------------------------------------
extern "C" void kernel_launch(void* const* d_in, const int* in_sizes, int n_in,
                              void* d_out, int out_size)
{
    const float* hidden    = (const float*)d_in[0];
    const int*   positions = (const int*)d_in[1];
    const float* w_qkv     = (const float*)d_in[2];
    const float* w_o       = (const float*)d_in[3];
    const float* q_norm_w  = (const float*)d_in[4];
    const float* k_norm_w  = (const float*)d_in[5];
    float* out = (float*)d_out;

    float* qkv_buf;
    __half *hh, *hl, *wq, *wo, *ah;
    cudaGetSymbolAddress((void**)&qkv_buf, g_qkv);
    cudaGetSymbolAddress((void**)&hh, g_hh);
    cudaGetSymbolAddress((void**)&hl, g_hl);
    cudaGetSymbolAddress((void**)&wq, g_wq);
    cudaGetSymbolAddress((void**)&wo, g_wo);
    cudaGetSymbolAddress((void**)&ah, g_ah);

    cudaFuncSetAttribute(gemm_tc,
                         cudaFuncAttributeMaxDynamicSharedMemorySize, GEMM_SMEM);
    cudaFuncSetAttribute(gemm_tc1,
                         cudaFuncAttributeMaxDynamicSharedMemorySize, GEMM1_SMEM);
    cudaFuncSetAttribute(attn_tc,
                         cudaFuncAttributeMaxDynamicSharedMemorySize, FA_SMEM);

    // 0) convert inputs
    {
        int n4h = BTOK * HIDDEN / 4;
        split_f32<<<(n4h + 255) / 256, 256>>>(hidden, hh, hl, n4h);
        int n4q = QKV_DIM * HIDDEN / 4;
        cvt_f32<<<(n4q + 255) / 256, 256>>>(w_qkv, wq, n4q);
        int n4o = HIDDEN * ATTN_DIM / 4;
        cvt_f32<<<(n4o + 255) / 256, 256>>>(w_o, wo, n4o);
    }

    // 1) QKV projection (2-pass, fp32-class) -> g_qkv
    gemm_tc<<<dim3(QKV_DIM / 128, BTOK / 64), 128, GEMM_SMEM>>>(
        hh, hl, wq, qkv_buf, BTOK, QKV_DIM, HIDDEN);

    // 2) RMSNorm + RoPE + fp16 convert
    {
        int total_warps = BTOK * (NH + 2 * NKV);
        norm_rope_split<<<(total_warps + 7) / 8, 256>>>(positions, q_norm_w, k_norm_w);
    }

    // 3) causal GQA flash attention (single-pass fp16)
    attn_tc<<<dim3(SS / FA_BM, NH, BB), 256, FA_SMEM>>>();

    // 4) O projection (single-pass fp16) -> fp32 out
    gemm_tc1<<<dim3(HIDDEN / 128, BTOK / 64), 128, GEMM1_SMEM>>>(
        ah, wo, out, BTOK, HIDDEN, ATTN_DIM);
}

// round 10
// speedup vs baseline: 7.4073x; 1.1572x over previous
#include <cuda_runtime.h>
#include <cuda_fp16.h>
#include <cstdint>
#include <math.h>

// Problem constants
#define HIDDEN   2048
#define NH       32
#define NKV      4
#define HD       128
#define BB       2
#define SS       2048
#define BTOK     (BB * SS)              // 4096
#define QKV_DIM  ((NH + 2 * NKV) * HD)  // 5120
#define ATTN_DIM (NH * HD)              // 4096
#define K_OFF    (NH * HD)              // 4096
#define V_OFF    (NH * HD + NKV * HD)   // 4608
#define QSCALE   0.08838834764831843f   // 1/sqrt(128)

// ------------------------------------------------------------
// Scratch (device globals; no runtime allocation allowed)
// ------------------------------------------------------------
__device__ float g_qkv[(size_t)BTOK * QKV_DIM];              // fp32 qkv proj
__device__ __half g_hh[(size_t)BTOK * HIDDEN];               // hidden fp16
__device__ __half g_wq[(size_t)QKV_DIM * HIDDEN];            // w_qkv fp16
__device__ __half g_wo[(size_t)HIDDEN * ATTN_DIM];           // w_o fp16
__device__ __half g_qh[(size_t)BTOK * NH * HD];              // Q fp16 (normed+roped+scaled)
__device__ __half g_kh[(size_t)BTOK * NKV * HD];             // K fp16 (normed+roped)
__device__ __half g_vh[(size_t)BTOK * NKV * HD];             // V fp16
__device__ __half g_ah[(size_t)BTOK * ATTN_DIM];             // attn out fp16

// ------------------------------------------------------------
// helpers
// ------------------------------------------------------------
__device__ __forceinline__ uint32_t smem_u32(const void* p) {
    uint32_t a;
    asm("{ .reg .u64 t; cvta.to.shared.u64 t, %1; cvt.u32.u64 %0, t; }" : "=r"(a) : "l"(p));
    return a;
}
// pack (x,y) to f16x2 (round-to-nearest)
__device__ __forceinline__ uint32_t pack2h(float x, float y) {
    uint32_t h;
    asm("cvt.rn.f16x2.f32 %0, %1, %2;" : "=r"(h) : "f"(y), "f"(x));
    return h;
}
__device__ __forceinline__ void ldm4(uint32_t addr, uint32_t& r0, uint32_t& r1,
                                     uint32_t& r2, uint32_t& r3) {
    asm volatile("ldmatrix.sync.aligned.m8n8.x4.shared.b16 {%0,%1,%2,%3}, [%4];"
                 : "=r"(r0), "=r"(r1), "=r"(r2), "=r"(r3) : "r"(addr));
}
__device__ __forceinline__ void ldm4t(uint32_t addr, uint32_t& r0, uint32_t& r1,
                                      uint32_t& r2, uint32_t& r3) {
    asm volatile("ldmatrix.sync.aligned.m8n8.x4.trans.shared.b16 {%0,%1,%2,%3}, [%4];"
                 : "=r"(r0), "=r"(r1), "=r"(r2), "=r"(r3) : "r"(addr));
}
__device__ __forceinline__ void mma_f16(float* c, const uint32_t* a, const uint32_t* b) {
    asm volatile(
        "mma.sync.aligned.m16n8k16.row.col.f32.f16.f16.f32 "
        "{%0,%1,%2,%3}, {%4,%5,%6,%7}, {%8,%9}, {%0,%1,%2,%3};"
        : "+f"(c[0]), "+f"(c[1]), "+f"(c[2]), "+f"(c[3])
        : "r"(a[0]), "r"(a[1]), "r"(a[2]), "r"(a[3]), "r"(b[0]), "r"(b[1]));
}
__device__ __forceinline__ void cp16(uint32_t dst, const void* src) {
    asm volatile("cp.async.cg.shared.global [%0], [%1], 16;" :: "r"(dst), "l"(src));
}
#define CP_COMMIT() asm volatile("cp.async.commit_group;" ::: "memory")
#define CP_WAIT0()  asm volatile("cp.async.wait_group 0;" ::: "memory")
#define CP_WAIT1()  asm volatile("cp.async.wait_group 1;" ::: "memory")

// ------------------------------------------------------------
// conversion pass (fp32 -> fp16)
// ------------------------------------------------------------
__global__ __launch_bounds__(256) void cvt_f32(
    const float* __restrict__ x, __half* __restrict__ h, int n4)
{
    int i = blockIdx.x * blockDim.x + threadIdx.x;
    if (i >= n4) return;
    float4 v = ((const float4*)x)[i];
    ((uint2*)h)[i] = make_uint2(pack2h(v.x, v.y), pack2h(v.z, v.w));
}

// ------------------------------------------------------------
// single-pass fp16 tensor-core GEMM (NT): C = A[M,K]*B[N,K]^T
// 64x128x32 block tile, 4 warps (2x2), warp 32x64, 4 CTAs/SM
// ------------------------------------------------------------
#define SROW 80                        // 32 f16 = 64B + 16 pad
#define ATILE_B (64 * SROW)            // 5120
#define BTILE_B (128 * SROW)           // 10240
#define STAGE1_B (ATILE_B + BTILE_B)   // 15360
#define GEMM1_SMEM (2 * STAGE1_B)      // 30720

__global__ __launch_bounds__(128, 4) void gemm_tc1(
    const __half* __restrict__ A, const __half* __restrict__ B,
    float* __restrict__ C, int M, int N, int K)
{
    extern __shared__ char smc[];
    uint32_t smb = smem_u32(smc);
    int tid = threadIdx.x, lane = tid & 31, wid = tid >> 5;
    int warpM = wid >> 1, warpN = wid & 1;
    int bm = blockIdx.y * 64, bn = blockIdx.x * 128;

    int g8 = lane >> 3, r8 = lane & 7;
    uint32_t a_off = (uint32_t)(((g8 & 1) * 8 + r8) * SROW + (g8 >> 1) * 16);
    uint32_t b_off = (uint32_t)(((g8 >> 1) * 8 + r8) * SROW + (g8 & 1) * 16);

    auto stage_load = [&](int kb, int buf) {
        uint32_t base = smb + buf * STAGE1_B;
        int k0 = kb * 32;
#pragma unroll
        for (int i = 0; i < 2; i++) {
            int idx = i * 128 + tid;
            int row = idx >> 2, c4 = idx & 3;
            cp16(base + (uint32_t)(row * SROW + c4 * 16),
                 A + (size_t)(bm + row) * K + k0 + c4 * 8);
        }
#pragma unroll
        for (int i = 0; i < 4; i++) {
            int idx = i * 128 + tid;
            int row = idx >> 2, c4 = idx & 3;
            cp16(base + ATILE_B + (uint32_t)(row * SROW + c4 * 16),
                 B + (size_t)(bn + row) * K + k0 + c4 * 8);
        }
    };

    float acc[2][8][4];
#pragma unroll
    for (int mt = 0; mt < 2; mt++)
#pragma unroll
        for (int nt = 0; nt < 8; nt++)
#pragma unroll
            for (int e = 0; e < 4; e++) acc[mt][nt][e] = 0.f;

    stage_load(0, 0);
    CP_COMMIT();

    int nkb = K / 32, buf = 0;
    for (int kb = 0; kb < nkb; kb++) {
        if (kb + 1 < nkb) {
            stage_load(kb + 1, buf ^ 1);
            CP_COMMIT();
            CP_WAIT1();
        } else {
            CP_WAIT0();
        }
        __syncthreads();

        uint32_t base = smb + buf * STAGE1_B;
        uint32_t a_b = base + (uint32_t)(warpM * 32) * SROW + a_off;
        uint32_t b_b = base + ATILE_B + (uint32_t)(warpN * 64) * SROW + b_off;

#pragma unroll
        for (int ks = 0; ks < 2; ks++) {
            uint32_t koff = (uint32_t)(ks * 32);
            uint32_t Bf[8][2];
#pragma unroll
            for (int ntp = 0; ntp < 4; ntp++) {
                uint32_t r0, r1, r2, r3;
                ldm4(b_b + (uint32_t)(ntp * 16 * SROW) + koff, r0, r1, r2, r3);
                Bf[2 * ntp][0] = r0; Bf[2 * ntp][1] = r1;
                Bf[2 * ntp + 1][0] = r2; Bf[2 * ntp + 1][1] = r3;
            }
#pragma unroll
            for (int mt = 0; mt < 2; mt++) {
                uint32_t Af[4];
                ldm4(a_b + (uint32_t)(mt * 16 * SROW) + koff, Af[0], Af[1], Af[2], Af[3]);
#pragma unroll
                for (int nt = 0; nt < 8; nt++)
                    mma_f16(acc[mt][nt], Af, Bf[nt]);
            }
        }
        __syncthreads();
        buf ^= 1;
    }

    int erow = lane >> 2;
    int ecol = (lane & 3) * 2;
#pragma unroll
    for (int mt = 0; mt < 2; mt++) {
#pragma unroll
        for (int nt = 0; nt < 8; nt++) {
            int row0 = bm + warpM * 32 + mt * 16 + erow;
            int col = bn + warpN * 64 + nt * 8 + ecol;
            *(float2*)(C + (size_t)row0 * N + col) = make_float2(acc[mt][nt][0], acc[mt][nt][1]);
            *(float2*)(C + (size_t)(row0 + 8) * N + col) = make_float2(acc[mt][nt][2], acc[mt][nt][3]);
        }
    }
}

// ------------------------------------------------------------
// Fused RMSNorm + RoPE + convert: Q/K/V -> single fp16 (Q pre-scaled)
// ------------------------------------------------------------
__global__ __launch_bounds__(256) void norm_rope_split(
    const int* __restrict__ positions,
    const float* __restrict__ qw, const float* __restrict__ kw)
{
    const int NG = NH + 2 * NKV;  // 40
    int warp = (blockIdx.x * blockDim.x + threadIdx.x) >> 5;
    int lane = threadIdx.x & 31;
    if (warp >= BTOK * NG) return;
    int gidx = warp % NG;
    int tok = warp / NG;

    if (gidx < NH + NKV) {
        bool isQ = gidx < NH;
        const float* w = isQ ? qw : kw;
        int off = isQ ? gidx * HD : K_OFF + (gidx - NH) * HD;
        const float* x = g_qkv + (size_t)tok * QKV_DIM + off;

        float xa = x[lane], xb = x[lane + 32], xc = x[lane + 64], xd = x[lane + 96];
        float ss = xa * xa + xb * xb + xc * xc + xd * xd;
#pragma unroll
        for (int o = 16; o; o >>= 1) ss += __shfl_xor_sync(0xffffffffu, ss, o);
        float rr = rsqrtf(ss * (1.f / 128.f) + 1e-6f);
        xa *= rr * w[lane];
        xb *= rr * w[lane + 32];
        xc *= rr * w[lane + 64];
        xd *= rr * w[lane + 96];

        float pos = (float)positions[tok];
        float inv1 = powf(1.0e6f, -(float)lane * (1.f / 64.f));
        float inv2 = powf(1.0e6f, -(float)(lane + 32) * (1.f / 64.f));
        float s1, c1, s2, c2;
        sincosf(pos * inv1, &s1, &c1);
        sincosf(pos * inv2, &s2, &c2);

        float y0 = xa * c1 - xc * s1;   // col lane
        float y1 = xb * c2 - xd * s2;   // col lane+32
        float y2 = xc * c1 + xa * s1;   // col lane+64
        float y3 = xd * c2 + xb * s2;   // col lane+96

        if (isQ) {
            size_t o = ((size_t)tok * NH + gidx) * HD;
            g_qh[o + lane]      = __float2half_rn(y0 * QSCALE);
            g_qh[o + lane + 32] = __float2half_rn(y1 * QSCALE);
            g_qh[o + lane + 64] = __float2half_rn(y2 * QSCALE);
            g_qh[o + lane + 96] = __float2half_rn(y3 * QSCALE);
        } else {
            size_t o = ((size_t)tok * NKV + (gidx - NH)) * HD;
            g_kh[o + lane]      = __float2half_rn(y0);
            g_kh[o + lane + 32] = __float2half_rn(y1);
            g_kh[o + lane + 64] = __float2half_rn(y2);
            g_kh[o + lane + 96] = __float2half_rn(y3);
        }
    } else {
        int vh = gidx - NH - NKV;
        const float* x = g_qkv + (size_t)tok * QKV_DIM + V_OFF + vh * HD;
        size_t o = ((size_t)tok * NKV + vh) * HD;
#pragma unroll
        for (int j = 0; j < 4; j++) {
            int c = lane + 32 * j;
            g_vh[o + c] = __float2half_rn(x[c]);
        }
    }
}

// ------------------------------------------------------------
// Tensor-core causal flash attention, single-pass fp16
// CTA = 128 q rows x 1 head, 8 warps; KV tiles of 128, double buffer
// Q fragments hoisted to registers
// ------------------------------------------------------------
#define FA_BM 128
#define FA_BN 128
#define FROW 272                 // 128 f16 = 256B + 16 pad
#define QTILE (128 * FROW)       // 34816
#define KVTILE (128 * FROW)      // 34816
#define SQ 0
#define SKV QTILE
#define KVSTAGE (2 * KVTILE)     // 69632 (K, V)
#define FA_SMEM (QTILE + 2 * KVSTAGE)   // 174080

__global__ __launch_bounds__(256, 1) void attn_tc()
{
    extern __shared__ char smc[];
    uint32_t smb = smem_u32(smc);
    int tid = threadIdx.x;
    int lane = tid & 31;
    int wid = tid >> 5;
    int qtile = blockIdx.x;
    int h = blockIdx.y;
    int b = blockIdx.z;
    int kvh = h >> 3;
    int q0 = qtile * FA_BM;

    int g8 = lane >> 3, r8 = lane & 7;
    uint32_t a_off = (uint32_t)(((g8 & 1) * 8 + r8) * FROW + (g8 >> 1) * 16);
    uint32_t b_off = (uint32_t)(((g8 >> 1) * 8 + r8) * FROW + (g8 & 1) * 16);

    // Q tile via cp.async (pre-scaled fp16)
#pragma unroll
    for (int i = 0; i < 8; i++) {
        int c = tid + i * 256;            // 2048 chunks: 128 rows x 16
        int row = c >> 4, c4 = c & 15;
        size_t src = ((size_t)(b * SS + q0 + row) * NH + h) * HD + c4 * 8;
        cp16(smb + SQ + (uint32_t)(row * FROW + c4 * 16), g_qh + src);
    }
    CP_COMMIT();

    auto kvload = [&](int t, int kbuf) {
        uint32_t base = smb + SKV + kbuf * KVSTAGE;
#pragma unroll
        for (int i = 0; i < 8; i++) {
            int c = tid + i * 256;        // 2048 chunks: 128 rows x 16
            int row = c >> 4, c4 = c & 15;
            size_t src = ((size_t)(b * SS + t * FA_BN + row) * NKV + kvh) * HD + c4 * 8;
            uint32_t doff = (uint32_t)(row * FROW + c4 * 16);
            cp16(base + doff, g_kh + src);
            cp16(base + KVTILE + doff, g_vh + src);
        }
    };

    kvload(0, 0);
    CP_COMMIT();

    // wait for Q (kv group still in flight), hoist Q frags to registers
    CP_WAIT1();
    __syncthreads();
    uint32_t qf[8][4];
    {
        uint32_t qrow = (uint32_t)(wid * 16) * FROW;
#pragma unroll
        for (int ks = 0; ks < 8; ks++)
            ldm4(smb + SQ + qrow + (uint32_t)(ks * 32) + a_off,
                 qf[ks][0], qf[ks][1], qf[ks][2], qf[ks][3]);
    }

    float m0 = -1e30f, m1 = -1e30f, lsum0 = 0.f, lsum1 = 0.f;
    float co[16][4];
#pragma unroll
    for (int nf = 0; nf < 16; nf++)
#pragma unroll
        for (int e = 0; e < 4; e++) co[nf][e] = 0.f;

    int ntiles = qtile + 1;
    int kbuf = 0;
    for (int t = 0; t < ntiles; t++) {
        if (t + 1 < ntiles) {
            kvload(t + 1, kbuf ^ 1);
            CP_COMMIT();
            CP_WAIT1();
        } else {
            CP_WAIT0();
        }
        __syncthreads();

        int kv0 = t * FA_BN;
        uint32_t base = smb + SKV + kbuf * KVSTAGE;

        // ---- S = Q K^T (single pass) ----
        float cs[8][2][4];
#pragma unroll
        for (int nb = 0; nb < 8; nb++)
#pragma unroll
            for (int f = 0; f < 2; f++)
#pragma unroll
                for (int e = 0; e < 4; e++) cs[nb][f][e] = 0.f;

#pragma unroll
        for (int ks = 0; ks < 8; ks++) {
            uint32_t koff = (uint32_t)(ks * 32);
#pragma unroll
            for (int nb = 0; nb < 8; nb++) {
                uint32_t nboff = (uint32_t)(nb * 16) * FROW + koff;
                uint32_t kf[4];
                ldm4(base + nboff + b_off, kf[0], kf[1], kf[2], kf[3]);
                mma_f16(cs[nb][0], qf[ks], kf);
                mma_f16(cs[nb][1], qf[ks], kf + 2);
            }
        }

        // ---- causal mask (diagonal tile only) ----
        if (t == qtile) {
            int row0 = q0 + wid * 16 + (lane >> 2);
#pragma unroll
            for (int nb = 0; nb < 8; nb++)
#pragma unroll
                for (int f = 0; f < 2; f++)
#pragma unroll
                    for (int e = 0; e < 4; e++) {
                        int col = kv0 + nb * 16 + f * 8 + 2 * (lane & 3) + (e & 1);
                        int row = row0 + ((e >> 1) ? 8 : 0);
                        if (col > row) cs[nb][f][e] = -1e30f;
                    }
        }

        // ---- online softmax ----
        float mt0 = -1e30f, mt1 = -1e30f;
#pragma unroll
        for (int nb = 0; nb < 8; nb++)
#pragma unroll
            for (int f = 0; f < 2; f++) {
                mt0 = fmaxf(mt0, fmaxf(cs[nb][f][0], cs[nb][f][1]));
                mt1 = fmaxf(mt1, fmaxf(cs[nb][f][2], cs[nb][f][3]));
            }
        mt0 = fmaxf(mt0, __shfl_xor_sync(0xffffffffu, mt0, 1));
        mt0 = fmaxf(mt0, __shfl_xor_sync(0xffffffffu, mt0, 2));
        mt1 = fmaxf(mt1, __shfl_xor_sync(0xffffffffu, mt1, 1));
        mt1 = fmaxf(mt1, __shfl_xor_sync(0xffffffffu, mt1, 2));
        float mn0 = fmaxf(m0, mt0);
        float mn1 = fmaxf(m1, mt1);
        float corr0 = __expf(m0 - mn0);
        float corr1 = __expf(m1 - mn1);
        float ps0 = 0.f, ps1 = 0.f;
#pragma unroll
        for (int nb = 0; nb < 8; nb++)
#pragma unroll
            for (int f = 0; f < 2; f++) {
                cs[nb][f][0] = __expf(cs[nb][f][0] - mn0);
                cs[nb][f][1] = __expf(cs[nb][f][1] - mn0);
                cs[nb][f][2] = __expf(cs[nb][f][2] - mn1);
                cs[nb][f][3] = __expf(cs[nb][f][3] - mn1);
                ps0 += cs[nb][f][0] + cs[nb][f][1];
                ps1 += cs[nb][f][2] + cs[nb][f][3];
            }
        ps0 += __shfl_xor_sync(0xffffffffu, ps0, 1);
        ps0 += __shfl_xor_sync(0xffffffffu, ps0, 2);
        ps1 += __shfl_xor_sync(0xffffffffu, ps1, 1);
        ps1 += __shfl_xor_sync(0xffffffffu, ps1, 2);
        lsum0 = lsum0 * corr0 + ps0;
        lsum1 = lsum1 * corr1 + ps1;
        m0 = mn0; m1 = mn1;
#pragma unroll
        for (int nf = 0; nf < 16; nf++) {
            co[nf][0] *= corr0; co[nf][1] *= corr0;
            co[nf][2] *= corr1; co[nf][3] *= corr1;
        }

        // ---- O += P V (single pass, P packed to fp16) ----
#pragma unroll
        for (int ks = 0; ks < 8; ks++) {
            uint32_t ph[4];
            ph[0] = pack2h(cs[ks][0][0], cs[ks][0][1]);
            ph[1] = pack2h(cs[ks][0][2], cs[ks][0][3]);
            ph[2] = pack2h(cs[ks][1][0], cs[ks][1][1]);
            ph[3] = pack2h(cs[ks][1][2], cs[ks][1][3]);
            uint32_t krow = (uint32_t)(ks * 16) * FROW;
#pragma unroll
            for (int db = 0; db < 8; db++) {
                uint32_t doff = krow + (uint32_t)(db * 32) + a_off;
                uint32_t vf[4];
                ldm4t(base + KVTILE + doff, vf[0], vf[1], vf[2], vf[3]);
                mma_f16(co[2 * db], ph, vf);
                mma_f16(co[2 * db + 1], ph, vf + 2);
            }
        }
        __syncthreads();
        kbuf ^= 1;
    }

    // epilogue: normalize, write fp16 for O projection
    float inv0 = 1.f / lsum0;
    float inv1 = 1.f / lsum1;
    int row0 = b * SS + q0 + wid * 16 + (lane >> 2);
    int colb = h * HD + 2 * (lane & 3);
#pragma unroll
    for (int nf = 0; nf < 16; nf++) {
        int col = colb + nf * 8;
        *(uint32_t*)(g_ah + (size_t)row0 * ATTN_DIM + col) =
            pack2h(co[nf][0] * inv0, co[nf][1] * inv0);
        *(uint32_t*)(g_ah + (size_t)(row0 + 8) * ATTN_DIM + col) =
            pack2h(co[nf][2] * inv1, co[nf][3] * inv1);
    }
}

// ------------------------------------------------------------
// launch
// ------------------------------------------------------------
extern "C" void kernel_launch(void* const* d_in, const int* in_sizes, int n_in,
                              void* d_out, int out_size)
{
    const float* hidden    = (const float*)d_in[0];
    const int*   positions = (const int*)d_in[1];
    const float* w_qkv     = (const float*)d_in[2];
    const float* w_o       = (const float*)d_in[3];
    const float* q_norm_w  = (const float*)d_in[4];
    const float* k_norm_w  = (const float*)d_in[5];
    float* out = (float*)d_out;

    float* qkv_buf;
    __half *hh, *wq, *wo, *ah;
    cudaGetSymbolAddress((void**)&qkv_buf, g_qkv);
    cudaGetSymbolAddress((void**)&hh, g_hh);
    cudaGetSymbolAddress((void**)&wq, g_wq);
    cudaGetSymbolAddress((void**)&wo, g_wo);
    cudaGetSymbolAddress((void**)&ah, g_ah);

    cudaFuncSetAttribute(gemm_tc1,
                         cudaFuncAttributeMaxDynamicSharedMemorySize, GEMM1_SMEM);
    cudaFuncSetAttribute(attn_tc,
                         cudaFuncAttributeMaxDynamicSharedMemorySize, FA_SMEM);

    // 0) convert inputs to fp16
    {
        int n4h = BTOK * HIDDEN / 4;
        cvt_f32<<<(n4h + 255) / 256, 256>>>(hidden, hh, n4h);
        int n4q = QKV_DIM * HIDDEN / 4;
        cvt_f32<<<(n4q + 255) / 256, 256>>>(w_qkv, wq, n4q);
        int n4o = HIDDEN * ATTN_DIM / 4;
        cvt_f32<<<(n4o + 255) / 256, 256>>>(w_o, wo, n4o);
    }

    // 1) QKV projection (single-pass fp16) -> fp32 g_qkv
    gemm_tc1<<<dim3(QKV_DIM / 128, BTOK / 64), 128, GEMM1_SMEM>>>(
        hh, wq, qkv_buf, BTOK, QKV_DIM, HIDDEN);

    // 2) RMSNorm + RoPE + fp16 convert
    {
        int total_warps = BTOK * (NH + 2 * NKV);
        norm_rope_split<<<(total_warps + 7) / 8, 256>>>(positions, q_norm_w, k_norm_w);
    }

    // 3) causal GQA flash attention (single-pass fp16)
    attn_tc<<<dim3(SS / FA_BM, NH, BB), 256, FA_SMEM>>>();

    // 4) O projection (single-pass fp16) -> fp32 out
    gemm_tc1<<<dim3(HIDDEN / 128, BTOK / 64), 128, GEMM1_SMEM>>>(
        ah, wo, out, BTOK, HIDDEN, ATTN_DIM);
}